// round 8
// baseline (speedup 1.0000x reference)
#include <cuda_runtime.h>
#include <cuda_bf16.h>
#include <cstdint>
#include <cstddef>
#include <math.h>

#define NB      4
#define SEQ     1024
#define DMODEL  768
#define NH      12
#define DHD     64
#define J3      2304
#define MROWS   4096
#define BHN     48

typedef __nv_bfloat16 bf16;
typedef unsigned int  u32;
typedef unsigned char u8;
typedef unsigned short u16;

// ---------------- scratch ----------------
__device__ __align__(16) u8    g_xq8[MROWS*DMODEL];        // quantized x / out (e4m3)
__device__ __align__(16) u8    g_wq1[J3*DMODEL];           // quantized w_qkv [n][k] e4m3
__device__ __align__(16) u8    g_wq2[DMODEL*DMODEL];       // quantized w_out [n][k] e4m3
__device__ __align__(16) float g_xqkv[MROWS*J3];
__device__ __align__(16) u8    g_qb8[BHN*SEQ*DHD];         // quantized q (e4m3)
__device__ __align__(16) u8    g_kb8[BHN*SEQ*DHD];         // quantized k (e4m3)
__device__ __align__(16) bf16  g_vb[BHN*SEQ*DHD];          // quantized v (bf16)
__device__ __align__(16) float g_outbuf[MROWS*DMODEL];
__device__ float    g_rowsum_x[MROWS];
__device__ float    g_colsum_w1[J3];
__device__ float    g_colsum_w2[DMODEL];
__device__ float    g_xqkvsum[MROWS];
__device__ float    g_rowsumq[BHN*SEQ];
__device__ float    g_colsumk[BHN*SEQ];
__device__ float    g_vcolsum[BHN*DHD];
__device__ float    g_rowm[BHN*SEQ];
__device__ float    g_rowS[BHN*SEQ];
__device__ unsigned g_stat[16];   // slots:0=x 1=w1 2=q 3=k 4=v 5=a 6=out 7=w2

// ---------------- helpers ----------------
__device__ __forceinline__ unsigned fenc(float f){
    unsigned u = __float_as_uint(f);
    return (u & 0x80000000u) ? ~u : (u | 0x80000000u);
}
__device__ __forceinline__ float fdec(unsigned e){
    return (e & 0x80000000u) ? __uint_as_float(e ^ 0x80000000u) : __uint_as_float(~e);
}
__device__ __forceinline__ void get_szi(int slot, float& s, float& z, float& is){
    float mx = fdec(g_stat[2*slot]);
    float mn = fdec(g_stat[2*slot+1]);
    s = __fdiv_rn(mx - mn, 15.0f);
    z = rintf(15.0f - __fdiv_rn(mx, s));
    is = __fdiv_rn(1.0f, s);
}
__device__ __forceinline__ float quantm(float v, float is, float z){
    return rintf(fmaf(v, is, z));
}
__device__ __forceinline__ u32 packbf2(float lo, float hi){
    __nv_bfloat162 t = __floats2bfloat162_rn(lo, hi);
    return *reinterpret_cast<u32*>(&t);
}
// pack 2 floats -> 2 e4m3 bytes (memory order: byte0=lo, byte1=hi)
__device__ __forceinline__ u16 packfp8x2(float lo, float hi){
    u16 r;
    asm("cvt.rn.satfinite.e4m3x2.f32 %0, %1, %2;" : "=h"(r) : "f"(hi), "f"(lo));
    return r;
}
__device__ __forceinline__ u32 packfp8x4(float a, float b, float c, float d){
    u16 lo = packfp8x2(a, b);
    u16 hi = packfp8x2(c, d);
    return (u32)lo | ((u32)hi << 16);
}
__device__ __forceinline__ void ldsm4(u32* r, const void* p){
    u32 a = (u32)__cvta_generic_to_shared(p);
    asm volatile("ldmatrix.sync.aligned.m8n8.x4.shared.b16 {%0,%1,%2,%3},[%4];"
        : "=r"(r[0]),"=r"(r[1]),"=r"(r[2]),"=r"(r[3]) : "r"(a));
}
__device__ __forceinline__ void ldsm2(u32* r, const void* p){
    u32 a = (u32)__cvta_generic_to_shared(p);
    asm volatile("ldmatrix.sync.aligned.m8n8.x2.shared.b16 {%0,%1},[%2];"
        : "=r"(r[0]),"=r"(r[1]) : "r"(a));
}
__device__ __forceinline__ void ldsm2t(u32* r, const void* p){
    u32 a = (u32)__cvta_generic_to_shared(p);
    asm volatile("ldmatrix.sync.aligned.m8n8.x2.trans.shared.b16 {%0,%1},[%2];"
        : "=r"(r[0]),"=r"(r[1]) : "r"(a));
}
__device__ __forceinline__ void mma16816(float* c, const u32* a, const u32* b){
    asm volatile("mma.sync.aligned.m16n8k16.row.col.f32.bf16.bf16.f32 "
        "{%0,%1,%2,%3}, {%4,%5,%6,%7}, {%8,%9}, {%0,%1,%2,%3};"
        : "+f"(c[0]),"+f"(c[1]),"+f"(c[2]),"+f"(c[3])
        : "r"(a[0]),"r"(a[1]),"r"(a[2]),"r"(a[3]), "r"(b[0]),"r"(b[1]));
}
__device__ __forceinline__ void mma8(float* c, const u32* a, const u32* b){
    asm volatile("mma.sync.aligned.m16n8k32.row.col.f32.e4m3.e4m3.f32 "
        "{%0,%1,%2,%3}, {%4,%5,%6,%7}, {%8,%9}, {%0,%1,%2,%3};"
        : "+f"(c[0]),"+f"(c[1]),"+f"(c[2]),"+f"(c[3])
        : "r"(a[0]),"r"(a[1]),"r"(a[2]),"r"(a[3]), "r"(b[0]),"r"(b[1]));
}
__device__ __forceinline__ void cpa(void* s, const void* g){
    u32 a = (u32)__cvta_generic_to_shared(s);
    asm volatile("cp.async.cg.shared.global [%0],[%1],16;" :: "r"(a), "l"(g));
}
#define CP_COMMIT asm volatile("cp.async.commit_group;")
#define CP_WAIT0  asm volatile("cp.async.wait_group 0;")
#define CP_WAIT1  asm volatile("cp.async.wait_group 1;")
#define CP_WAIT2  asm volatile("cp.async.wait_group 2;")

__device__ __forceinline__ float qsum(float v){
    v += __shfl_xor_sync(0xffffffffu, v, 1);
    v += __shfl_xor_sync(0xffffffffu, v, 2);
    return v;
}
__device__ __forceinline__ float qmax(float v){
    v = fmaxf(v, __shfl_xor_sync(0xffffffffu, v, 1));
    v = fmaxf(v, __shfl_xor_sync(0xffffffffu, v, 2));
    return v;
}
__device__ __forceinline__ float qmin(float v){
    v = fminf(v, __shfl_xor_sync(0xffffffffu, v, 1));
    v = fminf(v, __shfl_xor_sync(0xffffffffu, v, 2));
    return v;
}
__device__ __forceinline__ float wsum(float v){
    #pragma unroll
    for (int o = 16; o > 0; o >>= 1) v += __shfl_xor_sync(0xffffffffu, v, o);
    return v;
}

// ---------------- elementwise kernels ----------------
__global__ void k_init(){
    int t = threadIdx.x;
    if (t < 8){ g_stat[2*t] = fenc(-INFINITY); g_stat[2*t+1] = fenc(INFINITY); }
    for (int i = t; i < BHN*DHD; i += blockDim.x) g_vcolsum[i] = 0.f;
    for (int i = t; i < MROWS;   i += blockDim.x) g_xqkvsum[i] = 0.f;
}

__global__ void k_minmax2(const float* __restrict__ pa, int na, int sa_,
                          const float* __restrict__ pb, int nb, int sb_){
    const float* p = blockIdx.y ? pb : pa;
    int n    = blockIdx.y ? nb : na;
    int slot = blockIdx.y ? sb_ : sa_;
    float mx = -INFINITY, mn = INFINITY;
    int n4 = n >> 2;
    const float4* p4 = (const float4*)p;
    for (int i = blockIdx.x*blockDim.x + threadIdx.x; i < n4; i += gridDim.x*blockDim.x){
        float4 v = p4[i];
        mx = fmaxf(mx, fmaxf(fmaxf(v.x,v.y), fmaxf(v.z,v.w)));
        mn = fminf(mn, fminf(fminf(v.x,v.y), fminf(v.z,v.w)));
    }
    __shared__ float smx[256], smn[256];
    int t = threadIdx.x;
    smx[t] = mx; smn[t] = mn; __syncthreads();
    for (int o = 128; o > 0; o >>= 1){
        if (t < o){ smx[t] = fmaxf(smx[t], smx[t+o]); smn[t] = fminf(smn[t], smn[t+o]); }
        __syncthreads();
    }
    if (t == 0){
        atomicMax(&g_stat[2*slot],   fenc(smx[0]));
        atomicMin(&g_stat[2*slot+1], fenc(smn[0]));
    }
}

// warp-per-row quantize -> e4m3, fused row sums (rowlen 768)
__global__ void k_quantrow8(const float* __restrict__ src, u8* __restrict__ dst,
                            float* __restrict__ rowsum, int slot){
    int warp = threadIdx.x >> 5, lane = threadIdx.x & 31;
    int r = blockIdx.x*8 + warp;
    float s, z, is; get_szi(slot, s, z, is);
    const float4* s4 = (const float4*)(src + (long long)r*DMODEL);
    u32* d4 = (u32*)(dst + (long long)r*DMODEL);
    float acc = 0.f;
    #pragma unroll
    for (int i = 0; i < 6; i++){
        float4 v = s4[i*32 + lane];
        float q0 = quantm(v.x, is, z), q1 = quantm(v.y, is, z);
        float q2 = quantm(v.z, is, z), q3 = quantm(v.w, is, z);
        acc += (q0+q1) + (q2+q3);
        d4[i*32 + lane] = packfp8x4(q0, q1, q2, q3);
    }
    acc = wsum(acc);
    if (lane == 0) rowsum[r] = acc;
}

// warp-per-token pack: q,k -> e4m3; v -> bf16; fused token sums + v colsum
__global__ void k_pack_qkv(){
    __shared__ float vsum[64];
    int bh = blockIdx.y;
    int b = bh / NH, h = bh - b*NH;
    int warp = threadIdx.x >> 5, lane = threadIdx.x & 31;
    int n = blockIdx.x*8 + warp;
    if (threadIdx.x < 64) vsum[threadIdx.x] = 0.f;
    __syncthreads();
    float sq, zq, iq, sk, zk, ik, sv, zv, iv;
    get_szi(2, sq, zq, iq); get_szi(3, sk, zk, ik); get_szi(4, sv, zv, iv);
    long long base = (long long)(b*SEQ + n)*J3 + h*DHD + 2*lane;
    float2 qv2 = *(const float2*)&g_xqkv[base];
    float2 kv2 = *(const float2*)&g_xqkv[base + DMODEL];
    float2 vv2 = *(const float2*)&g_xqkv[base + 2*DMODEL];
    float q0 = quantm(qv2.x, iq, zq), q1 = quantm(qv2.y, iq, zq);
    float k0 = quantm(kv2.x, ik, zk), k1 = quantm(kv2.y, ik, zk);
    float v0 = quantm(vv2.x, iv, zv), v1 = quantm(vv2.y, iv, zv);
    long long po16 = ((long long)bh*SEQ + n)*32 + lane;   // u16 index into 64B rows
    ((u16*)g_qb8)[po16] = packfp8x2(q0, q1);
    ((u16*)g_kb8)[po16] = packfp8x2(k0, k1);
    ((u32*)g_vb)[po16]  = packbf2(v0, v1);
    float qs = wsum(q0 + q1);
    float ks = wsum(k0 + k1);
    if (lane == 0){
        g_rowsumq[bh*SEQ + n] = qs;
        g_colsumk[bh*SEQ + n] = ks;
    }
    atomicAdd(&vsum[2*lane],   v0);
    atomicAdd(&vsum[2*lane+1], v1);
    __syncthreads();
    if (threadIdx.x < 64) atomicAdd(&g_vcolsum[bh*DHD + threadIdx.x], vsum[threadIdx.x]);
}

// ---------------- fp8 QK^T fragment loaders ----------------
// A-frag (Q rows): ldsm4, addr = base + (rbase + (lane&15))*80 + kk + (lane>>4)*16
// B-frag (K cols): ldsm2, addr = base + (nbase + (lane&7))*80 + kk + ((lane>>3)&1)*16

// ---------------- fused attention: stats pass ----------------
// dyn smem: Q[128*80] | K[2][128*80] | csk[2][128]
__global__ void __launch_bounds__(256) k_attn_stats(){
    extern __shared__ __align__(16) char smraw[];
    u8* Qs  = (u8*)smraw;                   // 10240
    u8* Ks0 = (u8*)(smraw + 10240);
    u8* Ks1 = (u8*)(smraw + 20480);
    float* csk0 = (float*)(smraw + 30720);
    float* csk1 = (float*)(smraw + 31232);
    __shared__ float redx[256], redn[256];

    int bh = blockIdx.y, qt = blockIdx.x;
    int tid = threadIdx.x, warp = tid >> 5, lane = tid & 31;

    float sq, zq, iq, sk, zk, ik;
    get_szi(2, sq, zq, iq); get_szi(3, sk, zk, ik);
    float s3 = (0.125f * sq) * sk;

    {
        #pragma unroll
        for (int it = 0; it < 2; it++){
            int idx = it*256 + tid;
            int r = idx >> 2, c16 = idx & 3;
            cpa(&Ks0[r*80 + c16*16], &g_kb8[((long long)bh*SEQ + r)*DHD + c16*16]);
        }
        if (tid < 32) cpa(&csk0[tid*4], &g_colsumk[bh*SEQ + tid*4]);
        CP_COMMIT;
        #pragma unroll
        for (int it = 0; it < 2; it++){
            int idx = it*256 + tid;
            int r = idx >> 2, c16 = idx & 3;
            cpa(&Qs[r*80 + c16*16], &g_qb8[((long long)bh*SEQ + qt*128 + r)*DHD + c16*16]);
        }
        CP_COMMIT;
    }

    int r0 = warp*16 + (lane>>2), r1 = r0 + 8;
    float rsq0 = g_rowsumq[bh*SEQ + qt*128 + r0];
    float rsq1 = g_rowsumq[bh*SEQ + qt*128 + r1];

    float m0 = -INFINITY, m1 = -INFINITY;
    float n0 =  INFINITY, n1 =  INFINITY;
    float S0 = 0.f, S1 = 0.f;

    int st = 0;
    for (int kt = 0; kt < 8; kt++){
        u8*    Kc  = st ? Ks1 : Ks0;
        float* ckc = st ? csk1 : csk0;
        if (kt < 7){
            u8*    Kn  = st ? Ks0 : Ks1;
            float* ckn = st ? csk0 : csk1;
            #pragma unroll
            for (int it = 0; it < 2; it++){
                int idx = it*256 + tid;
                int r = idx >> 2, c16 = idx & 3;
                cpa(&Kn[r*80 + c16*16], &g_kb8[((long long)bh*SEQ + (kt+1)*128 + r)*DHD + c16*16]);
            }
            if (tid < 32) cpa(&ckn[tid*4], &g_colsumk[bh*SEQ + (kt+1)*128 + tid*4]);
            CP_COMMIT;
            CP_WAIT1;
        } else {
            CP_WAIT0;
        }
        __syncthreads();

        float acc[16][4];
        #pragma unroll
        for (int nt = 0; nt < 16; nt++){ acc[nt][0]=0.f; acc[nt][1]=0.f; acc[nt][2]=0.f; acc[nt][3]=0.f; }
        #pragma unroll
        for (int kk = 0; kk < 64; kk += 32){
            u32 af[4];
            ldsm4(af, &Qs[(warp*16 + (lane&15))*80 + kk + (lane>>4)*16]);
            #pragma unroll
            for (int nt = 0; nt < 16; nt++){
                u32 bf[2];
                ldsm2(bf, &Kc[(nt*8 + (lane&7))*80 + kk + ((lane>>3)&1)*16]);
                mma8(acc[nt], af, bf);
            }
        }

        int c = (lane&3)*2;
        #pragma unroll
        for (int nt = 0; nt < 16; nt++){
            int cg = nt*8 + c;
            float cz0 = ckc[cg]*zq, cz1 = ckc[cg+1]*zq;
            acc[nt][0] = (acc[nt][0] - cz0 - rsq0*zk)*s3;
            acc[nt][1] = (acc[nt][1] - cz1 - rsq0*zk)*s3;
            acc[nt][2] = (acc[nt][2] - cz0 - rsq1*zk)*s3;
            acc[nt][3] = (acc[nt][3] - cz1 - rsq1*zk)*s3;
        }
        float tx0=-INFINITY, tx1=-INFINITY, tn0=INFINITY, tn1=INFINITY;
        #pragma unroll
        for (int nt = 0; nt < 16; nt++){
            tx0 = fmaxf(tx0, fmaxf(acc[nt][0], acc[nt][1]));
            tx1 = fmaxf(tx1, fmaxf(acc[nt][2], acc[nt][3]));
            tn0 = fminf(tn0, fminf(acc[nt][0], acc[nt][1]));
            tn1 = fminf(tn1, fminf(acc[nt][2], acc[nt][3]));
        }
        tx0 = qmax(tx0); tx1 = qmax(tx1);
        tn0 = qmin(tn0); tn1 = qmin(tn1);
        float nm0 = fmaxf(m0, tx0), nm1 = fmaxf(m1, tx1);
        float se0 = 0.f, se1 = 0.f;
        #pragma unroll
        for (int nt = 0; nt < 16; nt++){
            se0 += __expf(acc[nt][0]-nm0) + __expf(acc[nt][1]-nm0);
            se1 += __expf(acc[nt][2]-nm1) + __expf(acc[nt][3]-nm1);
        }
        se0 = qsum(se0); se1 = qsum(se1);
        S0 = S0*__expf(m0-nm0) + se0;  m0 = nm0;  n0 = fminf(n0, tn0);
        S1 = S1*__expf(m1-nm1) + se1;  m1 = nm1;  n1 = fminf(n1, tn1);

        __syncthreads();
        st ^= 1;
    }

    if ((lane & 3) == 0){
        g_rowm[bh*SEQ + qt*128 + r0] = m0;  g_rowS[bh*SEQ + qt*128 + r0] = S0;
        g_rowm[bh*SEQ + qt*128 + r1] = m1;  g_rowS[bh*SEQ + qt*128 + r1] = S1;
    }
    float i0 = __fdiv_rn(1.0f, S0), i1 = __fdiv_rn(1.0f, S1);
    float ax = fmaxf(i0, i1);
    float an = fminf(__expf(n0 - m0)*i0, __expf(n1 - m1)*i1);
    redx[tid] = ax; redn[tid] = an; __syncthreads();
    for (int o = 128; o > 0; o >>= 1){
        if (tid < o){ redx[tid] = fmaxf(redx[tid], redx[tid+o]); redn[tid] = fminf(redn[tid], redn[tid+o]); }
        __syncthreads();
    }
    if (tid == 0){
        atomicMax(&g_stat[10], fenc(redx[0]));
        atomicMin(&g_stat[11], fenc(redn[0]));
    }
}

// ---------------- fused attention: recompute + quantize + AV ----------------
// dyn smem: Q[10240] | K[2][10240] | V bf16[18432] | csk[2][512] | vcs[256]
__global__ void __launch_bounds__(256) k_attn_av(){
    extern __shared__ __align__(16) char smraw[];
    u8*   Qs  = (u8*)smraw;
    u8*   Ks0 = (u8*)(smraw + 10240);
    u8*   Ks1 = (u8*)(smraw + 20480);
    bf16* Vs  = (bf16*)(smraw + 30720);
    float* csk0 = (float*)(smraw + 49152);
    float* csk1 = (float*)(smraw + 49664);
    float* vcs  = (float*)(smraw + 50176);

    int bh = blockIdx.y, qt = blockIdx.x;
    int b = bh / NH, h = bh - b*NH;
    int tid = threadIdx.x, warp = tid >> 5, lane = tid & 31;
    int l16 = lane & 15;

    float sq, zq, iq, sk, zk, ik, sv, zv, iv, sa, za, ia;
    get_szi(2, sq, zq, iq); get_szi(3, sk, zk, ik);
    get_szi(4, sv, zv, iv); get_szi(5, sa, za, ia);
    float s3 = (0.125f * sq) * sk;

    {
        #pragma unroll
        for (int it = 0; it < 2; it++){
            int idx = it*256 + tid;
            int r = idx >> 2, c16 = idx & 3;
            cpa(&Ks0[r*80 + c16*16], &g_kb8[((long long)bh*SEQ + r)*DHD + c16*16]);
        }
        if (tid < 32) cpa(&csk0[tid*4], &g_colsumk[bh*SEQ + tid*4]);
        CP_COMMIT;
        #pragma unroll
        for (int it = 0; it < 2; it++){
            int idx = it*256 + tid;
            int r = idx >> 2, c16 = idx & 3;
            cpa(&Qs[r*80 + c16*16], &g_qb8[((long long)bh*SEQ + qt*128 + r)*DHD + c16*16]);
        }
        if (tid < 16) cpa(&vcs[tid*4], &g_vcolsum[bh*DHD + tid*4]);
        CP_COMMIT;
    }

    int r0 = warp*16 + (lane>>2), r1 = r0 + 8;
    float rsq0 = g_rowsumq[bh*SEQ + qt*128 + r0];
    float rsq1 = g_rowsumq[bh*SEQ + qt*128 + r1];
    float m0 = g_rowm[bh*SEQ + qt*128 + r0], S0 = g_rowS[bh*SEQ + qt*128 + r0];
    float m1 = g_rowm[bh*SEQ + qt*128 + r1], S1 = g_rowS[bh*SEQ + qt*128 + r1];
    float coef0 = __fdiv_rn(1.0f, S0) * ia;
    float coef1 = __fdiv_rn(1.0f, S1) * ia;

    float oacc[8][4];
    #pragma unroll
    for (int nt = 0; nt < 8; nt++){ oacc[nt][0]=0.f; oacc[nt][1]=0.f; oacc[nt][2]=0.f; oacc[nt][3]=0.f; }
    float aqs0 = 0.f, aqs1 = 0.f;

    int st = 0;
    for (int kt = 0; kt < 8; kt++){
        u8*    Kc  = st ? Ks1 : Ks0;
        float* ckc = st ? csk1 : csk0;
        if (kt < 7){
            u8*    Kn  = st ? Ks0 : Ks1;
            float* ckn = st ? csk0 : csk1;
            #pragma unroll
            for (int it = 0; it < 2; it++){
                int idx = it*256 + tid;
                int r = idx >> 2, c16 = idx & 3;
                cpa(&Kn[r*80 + c16*16], &g_kb8[((long long)bh*SEQ + (kt+1)*128 + r)*DHD + c16*16]);
            }
            if (tid < 32) cpa(&ckn[tid*4], &g_colsumk[bh*SEQ + (kt+1)*128 + tid*4]);
            CP_COMMIT;
        }
        // V(kt) bf16 into single V buffer
        #pragma unroll
        for (int it = 0; it < 4; it++){
            int idx = it*256 + tid;
            int r = idx >> 3, c8 = idx & 7;
            cpa(&Vs[r*72 + c8*8], &g_vb[((long long)bh*SEQ + kt*128 + r)*DHD + c8*8]);
        }
        CP_COMMIT;
        if (kt < 7) { CP_WAIT2; } else { CP_WAIT1; }
        __syncthreads();

        float acc[16][4];
        #pragma unroll
        for (int nt = 0; nt < 16; nt++){ acc[nt][0]=0.f; acc[nt][1]=0.f; acc[nt][2]=0.f; acc[nt][3]=0.f; }
        #pragma unroll
        for (int kk = 0; kk < 64; kk += 32){
            u32 af[4];
            ldsm4(af, &Qs[(warp*16 + (lane&15))*80 + kk + (lane>>4)*16]);
            #pragma unroll
            for (int nt = 0; nt < 16; nt++){
                u32 bf[2];
                ldsm2(bf, &Kc[(nt*8 + (lane&7))*80 + kk + ((lane>>3)&1)*16]);
                mma8(acc[nt], af, bf);
            }
        }

        int c = (lane&3)*2;
        #pragma unroll
        for (int nt = 0; nt < 16; nt++){
            int cg = nt*8 + c;
            float cz0 = ckc[cg]*zq, cz1 = ckc[cg+1]*zq;
            acc[nt][0] = (acc[nt][0] - cz0 - rsq0*zk)*s3;
            acc[nt][1] = (acc[nt][1] - cz1 - rsq0*zk)*s3;
            acc[nt][2] = (acc[nt][2] - cz0 - rsq1*zk)*s3;
            acc[nt][3] = (acc[nt][3] - cz1 - rsq1*zk)*s3;
        }

        if (kt < 7) { CP_WAIT1; } else { CP_WAIT0; }
        __syncthreads();

        #pragma unroll
        for (int j = 0; j < 8; j++){
            float q00 = rintf(fmaf(__expf(acc[2*j][0]   - m0), coef0, za));
            float q01 = rintf(fmaf(__expf(acc[2*j][1]   - m0), coef0, za));
            float q02 = rintf(fmaf(__expf(acc[2*j][2]   - m1), coef1, za));
            float q03 = rintf(fmaf(__expf(acc[2*j][3]   - m1), coef1, za));
            float q10 = rintf(fmaf(__expf(acc[2*j+1][0] - m0), coef0, za));
            float q11 = rintf(fmaf(__expf(acc[2*j+1][1] - m0), coef0, za));
            float q12 = rintf(fmaf(__expf(acc[2*j+1][2] - m1), coef1, za));
            float q13 = rintf(fmaf(__expf(acc[2*j+1][3] - m1), coef1, za));
            aqs0 += q00 + q01 + q10 + q11;
            aqs1 += q02 + q03 + q12 + q13;
            u32 pa[4];
            pa[0] = packbf2(q00, q01);
            pa[1] = packbf2(q02, q03);
            pa[2] = packbf2(q10, q11);
            pa[3] = packbf2(q12, q13);
            #pragma unroll
            for (int nt = 0; nt < 8; nt++){
                u32 vf[2];
                ldsm2t(vf, &Vs[(16*j + l16)*72 + nt*8]);
                mma16816(oacc[nt], pa, vf);
            }
        }
        __syncthreads();
        st ^= 1;
    }

    aqs0 = qsum(aqs0);
    aqs1 = qsum(aqs1);

    float mult  = sa * sv;
    float cterm = (za * zv) * (float)SEQ;
    int c = (lane&3)*2;
    long long ob0 = (long long)(b*SEQ + qt*128 + r0)*DMODEL + h*DHD;
    long long ob1 = (long long)(b*SEQ + qt*128 + r1)*DMODEL + h*DHD;
    #pragma unroll
    for (int nt = 0; nt < 8; nt++){
        int d0 = nt*8 + c;
        float w0 = vcs[d0]*za, w1 = vcs[d0+1]*za;
        g_outbuf[ob0 + d0]     = (oacc[nt][0] - w0 - aqs0*zv + cterm)*mult;
        g_outbuf[ob0 + d0 + 1] = (oacc[nt][1] - w1 - aqs0*zv + cterm)*mult;
        g_outbuf[ob1 + d0]     = (oacc[nt][2] - w0 - aqs1*zv + cterm)*mult;
        g_outbuf[ob1 + d0 + 1] = (oacc[nt][3] - w1 - aqs1*zv + cterm)*mult;
    }
}

// ---------------- fp8 pipelined GEMM with affine epilogue ----------------
// A [M][K] e4m3 k-contig; B [N][K] e4m3 k-contig; C [M][N] f32.
template<int F1>
__global__ void __launch_bounds__(256) k_mma8(
    const u8* __restrict__ A, int lda,
    const u8* __restrict__ Bm, int ldb,
    float* __restrict__ C, int ldc,
    int K,
    const float* __restrict__ colsumB,
    const float* __restrict__ rowsumA,
    int slotA, int slotB, float Kconst,
    const float* __restrict__ bias)
{
    const int BK = 64, PAD = 80;
    __shared__ __align__(16) u8 As[2][128*PAD];
    __shared__ __align__(16) u8 Bs[2][128*PAD];
    __shared__ float redx[256], redn[256];

    int i0 = blockIdx.y * 128, j0 = blockIdx.x * 128;
    int tid = threadIdx.x, warp = tid >> 5, lane = tid & 31;
    int wm = warp >> 2, wn = warp & 3;

    float acc[4][4][4];
    #pragma unroll
    for (int a = 0; a < 4; a++)
        #pragma unroll
        for (int b = 0; b < 4; b++){
            acc[a][b][0]=0.f; acc[a][b][1]=0.f; acc[a][b][2]=0.f; acc[a][b][3]=0.f;
        }

    {
        #pragma unroll
        for (int v = 0; v < 2; v++){
            int idx = v*256 + tid;
            int r = idx >> 2, c16 = idx & 3;
            cpa(&As[0][r*PAD + c16*16], &A[(long long)(i0 + r)*lda + c16*16]);
        }
        #pragma unroll
        for (int v = 0; v < 2; v++){
            int idx = v*256 + tid;
            int r = idx >> 2, c16 = idx & 3;
            cpa(&Bs[0][r*PAD + c16*16], &Bm[(long long)(j0 + r)*ldb + c16*16]);
        }
        CP_COMMIT;
    }

    int st = 0;
    for (int k0 = 0; k0 < K; k0 += BK){
        if (k0 + BK < K){
            int ns = st ^ 1, kn = k0 + BK;
            #pragma unroll
            for (int v = 0; v < 2; v++){
                int idx = v*256 + tid;
                int r = idx >> 2, c16 = idx & 3;
                cpa(&As[ns][r*PAD + c16*16], &A[(long long)(i0 + r)*lda + kn + c16*16]);
            }
            #pragma unroll
            for (int v = 0; v < 2; v++){
                int idx = v*256 + tid;
                int r = idx >> 2, c16 = idx & 3;
                cpa(&Bs[ns][r*PAD + c16*16], &Bm[(long long)(j0 + r)*ldb + kn + c16*16]);
            }
            CP_COMMIT;
            CP_WAIT1;
        } else {
            CP_WAIT0;
        }
        __syncthreads();

        #pragma unroll
        for (int kk = 0; kk < BK; kk += 32){
            u32 af[4][4];
            #pragma unroll
            for (int mt = 0; mt < 4; mt++)
                ldsm4(af[mt], &As[st][(wm*64 + mt*16 + (lane&15))*PAD + kk + (lane>>4)*16]);
            u32 bf[4][2];
            #pragma unroll
            for (int nt = 0; nt < 4; nt++)
                ldsm2(bf[nt], &Bs[st][(wn*32 + nt*8 + (lane&7))*PAD + kk + ((lane>>3)&1)*16]);
            #pragma unroll
            for (int mt = 0; mt < 4; mt++)
                #pragma unroll
                for (int nt = 0; nt < 4; nt++)
                    mma8(acc[mt][nt], af[mt], bf[nt]);
        }
        __syncthreads();
        st ^= 1;
    }

    float sA, zA, iA, sB, zB, iB;
    get_szi(slotA, sA, zA, iA); get_szi(slotB, sB, zB, iB);
    float mult  = sA * sB;
    float cterm = (zA * zB) * Kconst;

    float lmx = -INFINITY, lmn = INFINITY;

    #pragma unroll
    for (int mt = 0; mt < 4; mt++){
        int row0 = i0 + wm*64 + mt*16 + (lane>>2);
        float rs0 = rowsumA[row0], rs1 = rowsumA[row0+8];
        float p0 = 0.f, p8 = 0.f;
        #pragma unroll
        for (int nt = 0; nt < 4; nt++){
            int col0 = j0 + wn*32 + nt*8 + (lane&3)*2;
            float cs0 = colsumB[col0], cs1 = colsumB[col0+1];
            float b0 = bias ? bias[col0]   : 0.f;
            float b1 = bias ? bias[col0+1] : 0.f;
            float v0 = (acc[mt][nt][0] - cs0*zA - rs0*zB + cterm)*mult + b0;
            float v1 = (acc[mt][nt][1] - cs1*zA - rs0*zB + cterm)*mult + b1;
            float v2 = (acc[mt][nt][2] - cs0*zA - rs1*zB + cterm)*mult + b0;
            float v3 = (acc[mt][nt][3] - cs1*zA - rs1*zB + cterm)*mult + b1;
            C[(long long)row0*ldc + col0]       = v0;
            C[(long long)row0*ldc + col0 + 1]   = v1;
            C[(long long)(row0+8)*ldc + col0]   = v2;
            C[(long long)(row0+8)*ldc + col0+1] = v3;
            if (F1){
                p0 += v0 + v1; p8 += v2 + v3;
                lmx = fmaxf(lmx, fmaxf(fmaxf(v0,v1), fmaxf(v2,v3)));
                lmn = fminf(lmn, fminf(fminf(v0,v1), fminf(v2,v3)));
            }
        }
        if (F1){
            p0 = qsum(p0); p8 = qsum(p8);
            if ((lane & 3) == 0){
                atomicAdd(&g_xqkvsum[row0],   p0);
                atomicAdd(&g_xqkvsum[row0+8], p8);
            }
        }
    }

    if (F1){
        redx[tid] = lmx; redn[tid] = lmn; __syncthreads();
        for (int o = 128; o > 0; o >>= 1){
            if (tid < o){ redx[tid] = fmaxf(redx[tid], redx[tid+o]); redn[tid] = fminf(redn[tid], redn[tid+o]); }
            __syncthreads();
        }
        if (tid == 0){
            int region = blockIdx.x / 6;
            atomicMax(&g_stat[2*(2+region)],   fenc(redx[0]));
            atomicMin(&g_stat[2*(2+region)+1], fenc(redn[0]));
        }
    }
}

// ---------------- launcher ----------------
extern "C" void kernel_launch(void* const* d_in, const int* in_sizes, int n_in,
                              void* d_out, int out_size){
    const float *x = 0, *wqkv = 0, *wout = 0, *bout = 0;
    for (int i = 0; i < n_in; i++){
        if      (in_sizes[i] == MROWS*DMODEL)  x    = (const float*)d_in[i];
        else if (in_sizes[i] == J3*DMODEL)     wqkv = (const float*)d_in[i];
        else if (in_sizes[i] == DMODEL*DMODEL) wout = (const float*)d_in[i];
        else if (in_sizes[i] == DMODEL)        bout = (const float*)d_in[i];
    }
    float* out = (float*)d_out;

    u8 *p_xq8, *p_wq1, *p_wq2;
    float *p_xqkv, *p_outbuf;
    float *p_rowsum_x, *p_colsum_w1, *p_colsum_w2, *p_xqkvsum;
    cudaGetSymbolAddress((void**)&p_xq8,       g_xq8);
    cudaGetSymbolAddress((void**)&p_wq1,       g_wq1);
    cudaGetSymbolAddress((void**)&p_wq2,       g_wq2);
    cudaGetSymbolAddress((void**)&p_xqkv,      g_xqkv);
    cudaGetSymbolAddress((void**)&p_outbuf,    g_outbuf);
    cudaGetSymbolAddress((void**)&p_rowsum_x,  g_rowsum_x);
    cudaGetSymbolAddress((void**)&p_colsum_w1, g_colsum_w1);
    cudaGetSymbolAddress((void**)&p_colsum_w2, g_colsum_w2);
    cudaGetSymbolAddress((void**)&p_xqkvsum,   g_xqkvsum);

    static int smem_set = 0;
    if (!smem_set){
        cudaFuncSetAttribute(k_attn_stats, cudaFuncAttributeMaxDynamicSharedMemorySize, 31744);
        cudaFuncSetAttribute(k_attn_av,    cudaFuncAttributeMaxDynamicSharedMemorySize, 50432);
        smem_set = 1;
    }

    k_init<<<1, 256>>>();
    k_minmax2<<<dim3(768, 2), 256>>>(x, MROWS*DMODEL, 0, wqkv, J3*DMODEL, 1);
    k_quantrow8<<<MROWS/8, 256>>>(x, p_xq8, p_rowsum_x, 0);
    k_quantrow8<<<J3/8, 256>>>(wqkv, p_wq1, p_colsum_w1, 1);
    k_mma8<1><<<dim3(J3/128, MROWS/128), 256>>>(
        p_xq8, DMODEL, p_wq1, DMODEL, p_xqkv, J3, DMODEL,
        p_colsum_w1, p_rowsum_x, 0, 1, (float)DMODEL, (const float*)0);
    k_pack_qkv<<<dim3(SEQ/8, BHN), 256>>>();
    k_attn_stats<<<dim3(8, BHN), 256, 31744>>>();
    k_attn_av<<<dim3(8, BHN), 256, 50432>>>();
    k_minmax2<<<dim3(768, 2), 256>>>(p_outbuf, MROWS*DMODEL, 6, wout, DMODEL*DMODEL, 7);
    k_quantrow8<<<MROWS/8, 256>>>(p_outbuf, p_xq8, p_rowsum_x /*dummy*/, 6);
    k_quantrow8<<<DMODEL/8, 256>>>(wout, p_wq2, p_colsum_w2, 7);
    k_mma8<0><<<dim3(DMODEL/128, MROWS/128), 256>>>(
        p_xq8, DMODEL, p_wq2, DMODEL, out, DMODEL, DMODEL,
        p_colsum_w2, p_xqkvsum, 6, 7, (float)J3, bout);
}

// round 9
// speedup vs baseline: 1.5634x; 1.5634x over previous
#include <cuda_runtime.h>
#include <cuda_bf16.h>
#include <cstdint>
#include <cstddef>
#include <math.h>

#define NB      4
#define SEQ     1024
#define DMODEL  768
#define NH      12
#define DHD     64
#define J3      2304
#define MROWS   4096
#define BHN     48

typedef __nv_bfloat16 bf16;
typedef unsigned int  u32;

// ---------------- scratch ----------------
__device__ __align__(16) bf16  g_xq[MROWS*DMODEL];         // quantized x / out (bf16)
__device__ __align__(16) bf16  g_wq1[J3*DMODEL];           // quantized w_qkv [n][k]
__device__ __align__(16) bf16  g_wq2[DMODEL*DMODEL];       // quantized w_out [n][k]
__device__ __align__(16) float g_xqkv[MROWS*J3];
__device__ __align__(16) bf16  g_qb[BHN*SEQ*DHD];
__device__ __align__(16) bf16  g_kb[BHN*SEQ*DHD];
__device__ __align__(16) bf16  g_vb[BHN*SEQ*DHD];
__device__ __align__(16) float g_outbuf[MROWS*DMODEL];
__device__ float    g_rowsum_x[MROWS];
__device__ float    g_colsum_w1[J3];
__device__ float    g_colsum_w2[DMODEL];
__device__ float    g_xqkvsum[MROWS];
__device__ float    g_rowsumq[BHN*SEQ];
__device__ float    g_colsumk[BHN*SEQ];
__device__ float    g_vcolsum[BHN*DHD];
__device__ float    g_rowm[BHN*SEQ];
__device__ float    g_rowS[BHN*SEQ];
__device__ unsigned g_stat[16];   // slots:0=x 1=w1 2=q 3=k 4=v 5=a 6=out 7=w2

// ---------------- helpers ----------------
__device__ __forceinline__ unsigned fenc(float f){
    unsigned u = __float_as_uint(f);
    return (u & 0x80000000u) ? ~u : (u | 0x80000000u);
}
__device__ __forceinline__ float fdec(unsigned e){
    return (e & 0x80000000u) ? __uint_as_float(e ^ 0x80000000u) : __uint_as_float(~e);
}
__device__ __forceinline__ void get_szi(int slot, float& s, float& z, float& is){
    float mx = fdec(g_stat[2*slot]);
    float mn = fdec(g_stat[2*slot+1]);
    s = __fdiv_rn(mx - mn, 15.0f);
    z = rintf(15.0f - __fdiv_rn(mx, s));
    is = __fdiv_rn(1.0f, s);
}
__device__ __forceinline__ float quantm(float v, float is, float z){
    return rintf(fmaf(v, is, z));
}
__device__ __forceinline__ u32 packbf2(float lo, float hi){
    __nv_bfloat162 t = __floats2bfloat162_rn(lo, hi);
    return *reinterpret_cast<u32*>(&t);
}
__device__ __forceinline__ void ldsm4(u32* r, const void* p){
    u32 a = (u32)__cvta_generic_to_shared(p);
    asm volatile("ldmatrix.sync.aligned.m8n8.x4.shared.b16 {%0,%1,%2,%3},[%4];"
        : "=r"(r[0]),"=r"(r[1]),"=r"(r[2]),"=r"(r[3]) : "r"(a));
}
__device__ __forceinline__ void ldsm2(u32* r, const void* p){
    u32 a = (u32)__cvta_generic_to_shared(p);
    asm volatile("ldmatrix.sync.aligned.m8n8.x2.shared.b16 {%0,%1},[%2];"
        : "=r"(r[0]),"=r"(r[1]) : "r"(a));
}
__device__ __forceinline__ void ldsm2t(u32* r, const void* p){
    u32 a = (u32)__cvta_generic_to_shared(p);
    asm volatile("ldmatrix.sync.aligned.m8n8.x2.trans.shared.b16 {%0,%1},[%2];"
        : "=r"(r[0]),"=r"(r[1]) : "r"(a));
}
__device__ __forceinline__ void mma16816(float* c, const u32* a, const u32* b){
    asm volatile("mma.sync.aligned.m16n8k16.row.col.f32.bf16.bf16.f32 "
        "{%0,%1,%2,%3}, {%4,%5,%6,%7}, {%8,%9}, {%0,%1,%2,%3};"
        : "+f"(c[0]),"+f"(c[1]),"+f"(c[2]),"+f"(c[3])
        : "r"(a[0]),"r"(a[1]),"r"(a[2]),"r"(a[3]), "r"(b[0]),"r"(b[1]));
}
__device__ __forceinline__ void cpa(void* s, const void* g){
    u32 a = (u32)__cvta_generic_to_shared(s);
    asm volatile("cp.async.cg.shared.global [%0],[%1],16;" :: "r"(a), "l"(g));
}
#define CP_COMMIT asm volatile("cp.async.commit_group;")
#define CP_WAIT0  asm volatile("cp.async.wait_group 0;")
#define CP_WAIT1  asm volatile("cp.async.wait_group 1;")
#define CP_WAIT2  asm volatile("cp.async.wait_group 2;")

__device__ __forceinline__ float qsum(float v){
    v += __shfl_xor_sync(0xffffffffu, v, 1);
    v += __shfl_xor_sync(0xffffffffu, v, 2);
    return v;
}
__device__ __forceinline__ float qmax(float v){
    v = fmaxf(v, __shfl_xor_sync(0xffffffffu, v, 1));
    v = fmaxf(v, __shfl_xor_sync(0xffffffffu, v, 2));
    return v;
}
__device__ __forceinline__ float qmin(float v){
    v = fminf(v, __shfl_xor_sync(0xffffffffu, v, 1));
    v = fminf(v, __shfl_xor_sync(0xffffffffu, v, 2));
    return v;
}
__device__ __forceinline__ float wsum(float v){
    #pragma unroll
    for (int o = 16; o > 0; o >>= 1) v += __shfl_xor_sync(0xffffffffu, v, o);
    return v;
}

// ---------------- elementwise kernels ----------------
__global__ void k_init(){
    int t = threadIdx.x;
    if (t < 8){ g_stat[2*t] = fenc(-INFINITY); g_stat[2*t+1] = fenc(INFINITY); }
    for (int i = t; i < BHN*DHD; i += blockDim.x) g_vcolsum[i] = 0.f;
    for (int i = t; i < MROWS;   i += blockDim.x) g_xqkvsum[i] = 0.f;
}

__global__ void k_minmax2(const float* __restrict__ pa, int na, int sa_,
                          const float* __restrict__ pb, int nb, int sb_){
    const float* p = blockIdx.y ? pb : pa;
    int n    = blockIdx.y ? nb : na;
    int slot = blockIdx.y ? sb_ : sa_;
    float mx = -INFINITY, mn = INFINITY;
    int n4 = n >> 2;
    const float4* p4 = (const float4*)p;
    for (int i = blockIdx.x*blockDim.x + threadIdx.x; i < n4; i += gridDim.x*blockDim.x){
        float4 v = p4[i];
        mx = fmaxf(mx, fmaxf(fmaxf(v.x,v.y), fmaxf(v.z,v.w)));
        mn = fminf(mn, fminf(fminf(v.x,v.y), fminf(v.z,v.w)));
    }
    __shared__ float smx[256], smn[256];
    int t = threadIdx.x;
    smx[t] = mx; smn[t] = mn; __syncthreads();
    for (int o = 128; o > 0; o >>= 1){
        if (t < o){ smx[t] = fmaxf(smx[t], smx[t+o]); smn[t] = fminf(smn[t], smn[t+o]); }
        __syncthreads();
    }
    if (t == 0){
        atomicMax(&g_stat[2*slot],   fenc(smx[0]));
        atomicMin(&g_stat[2*slot+1], fenc(smn[0]));
    }
}

// warp-per-row quantize -> bf16 (row-major, rowlen 768), fused row sums
__global__ void k_quantrow(const float* __restrict__ src, bf16* __restrict__ dst,
                           float* __restrict__ rowsum, int slot){
    int warp = threadIdx.x >> 5, lane = threadIdx.x & 31;
    int r = blockIdx.x*8 + warp;
    float s, z, is; get_szi(slot, s, z, is);
    const float4* s4 = (const float4*)(src + (long long)r*DMODEL);
    uint2* d2 = (uint2*)(dst + (long long)r*DMODEL);
    float acc = 0.f;
    #pragma unroll
    for (int i = 0; i < 6; i++){
        float4 v = s4[i*32 + lane];
        float q0 = quantm(v.x, is, z), q1 = quantm(v.y, is, z);
        float q2 = quantm(v.z, is, z), q3 = quantm(v.w, is, z);
        acc += (q0+q1) + (q2+q3);
        uint2 o; o.x = packbf2(q0,q1); o.y = packbf2(q2,q3);
        d2[i*32 + lane] = o;
    }
    acc = wsum(acc);
    if (lane == 0) rowsum[r] = acc;
}

// warp-per-token pack of quantized q/k/v; fused token sums + v colsum
__global__ void k_pack_qkv(){
    __shared__ float vsum[64];
    int bh = blockIdx.y;
    int b = bh / NH, h = bh - b*NH;
    int warp = threadIdx.x >> 5, lane = threadIdx.x & 31;
    int n = blockIdx.x*8 + warp;
    if (threadIdx.x < 64) vsum[threadIdx.x] = 0.f;
    __syncthreads();
    float sq, zq, iq, sk, zk, ik, sv, zv, iv;
    get_szi(2, sq, zq, iq); get_szi(3, sk, zk, ik); get_szi(4, sv, zv, iv);
    long long base = (long long)(b*SEQ + n)*J3 + h*DHD + 2*lane;
    float2 qv2 = *(const float2*)&g_xqkv[base];
    float2 kv2 = *(const float2*)&g_xqkv[base + DMODEL];
    float2 vv2 = *(const float2*)&g_xqkv[base + 2*DMODEL];
    float q0 = quantm(qv2.x, iq, zq), q1 = quantm(qv2.y, iq, zq);
    float k0 = quantm(kv2.x, ik, zk), k1 = quantm(kv2.y, ik, zk);
    float v0 = quantm(vv2.x, iv, zv), v1 = quantm(vv2.y, iv, zv);
    long long po = ((long long)bh*SEQ + n)*DHD/2 + lane;
    ((u32*)g_qb)[po] = packbf2(q0, q1);
    ((u32*)g_kb)[po] = packbf2(k0, k1);
    ((u32*)g_vb)[po] = packbf2(v0, v1);
    float qs = wsum(q0 + q1);
    float ks = wsum(k0 + k1);
    if (lane == 0){
        g_rowsumq[bh*SEQ + n] = qs;
        g_colsumk[bh*SEQ + n] = ks;
    }
    atomicAdd(&vsum[2*lane],   v0);
    atomicAdd(&vsum[2*lane+1], v1);
    __syncthreads();
    if (threadIdx.x < 64) atomicAdd(&g_vcolsum[bh*DHD + threadIdx.x], vsum[threadIdx.x]);
}

// ---------------- fused attention: stats pass ----------------
__global__ void __launch_bounds__(256) k_attn_stats(){
    extern __shared__ __align__(16) char smraw[];
    bf16* Qs  = (bf16*)smraw;
    bf16* Ks0 = (bf16*)(smraw + 18432);
    bf16* Ks1 = (bf16*)(smraw + 18432*2);
    float* csk0 = (float*)(smraw + 18432*3);
    float* csk1 = (float*)(smraw + 18432*3 + 512);
    __shared__ float redx[256], redn[256];

    int bh = blockIdx.y, qt = blockIdx.x;
    int tid = threadIdx.x, warp = tid >> 5, lane = tid & 31;
    int l16 = lane & 15;

    float sq, zq, iq, sk, zk, ik;
    get_szi(2, sq, zq, iq); get_szi(3, sk, zk, ik);
    float s3 = (0.125f * sq) * sk;

    {
        #pragma unroll
        for (int it = 0; it < 4; it++){
            int idx = it*256 + tid;
            int r = idx >> 3, c8 = idx & 7;
            cpa(&Ks0[r*72 + c8*8], &g_kb[((long long)bh*SEQ + r)*DHD + c8*8]);
        }
        if (tid < 32) cpa(&csk0[tid*4], &g_colsumk[bh*SEQ + tid*4]);
        CP_COMMIT;
        #pragma unroll
        for (int it = 0; it < 4; it++){
            int idx = it*256 + tid;
            int r = idx >> 3, c8 = idx & 7;
            cpa(&Qs[r*72 + c8*8], &g_qb[((long long)bh*SEQ + qt*128 + r)*DHD + c8*8]);
        }
        CP_COMMIT;
    }

    int r0 = warp*16 + (lane>>2), r1 = r0 + 8;
    float rsq0 = g_rowsumq[bh*SEQ + qt*128 + r0];
    float rsq1 = g_rowsumq[bh*SEQ + qt*128 + r1];

    float m0 = -INFINITY, m1 = -INFINITY;
    float n0 =  INFINITY, n1 =  INFINITY;
    float S0 = 0.f, S1 = 0.f;

    int st = 0;
    for (int kt = 0; kt < 8; kt++){
        bf16*  Kc  = st ? Ks1 : Ks0;
        float* ckc = st ? csk1 : csk0;
        if (kt < 7){
            bf16*  Kn  = st ? Ks0 : Ks1;
            float* ckn = st ? csk0 : csk1;
            #pragma unroll
            for (int it = 0; it < 4; it++){
                int idx = it*256 + tid;
                int r = idx >> 3, c8 = idx & 7;
                cpa(&Kn[r*72 + c8*8], &g_kb[((long long)bh*SEQ + (kt+1)*128 + r)*DHD + c8*8]);
            }
            if (tid < 32) cpa(&ckn[tid*4], &g_colsumk[bh*SEQ + (kt+1)*128 + tid*4]);
            CP_COMMIT;
            CP_WAIT1;
        } else {
            CP_WAIT0;
        }
        __syncthreads();

        float acc[16][4];
        #pragma unroll
        for (int nt = 0; nt < 16; nt++){ acc[nt][0]=0.f; acc[nt][1]=0.f; acc[nt][2]=0.f; acc[nt][3]=0.f; }
        #pragma unroll
        for (int kk = 0; kk < 64; kk += 16){
            u32 af[4];
            ldsm4(af, &Qs[(warp*16 + l16)*72 + kk + (lane>>4)*8]);
            #pragma unroll
            for (int nt = 0; nt < 16; nt++){
                u32 bf[2];
                ldsm2(bf, &Kc[(nt*8 + (l16&7))*72 + kk + ((l16>>3)&1)*8]);
                mma16816(acc[nt], af, bf);
            }
        }

        int c = (lane&3)*2;
        #pragma unroll
        for (int nt = 0; nt < 16; nt++){
            int cg = nt*8 + c;
            float cz0 = ckc[cg]*zq, cz1 = ckc[cg+1]*zq;
            acc[nt][0] = (acc[nt][0] - cz0 - rsq0*zk)*s3;
            acc[nt][1] = (acc[nt][1] - cz1 - rsq0*zk)*s3;
            acc[nt][2] = (acc[nt][2] - cz0 - rsq1*zk)*s3;
            acc[nt][3] = (acc[nt][3] - cz1 - rsq1*zk)*s3;
        }
        float tx0=-INFINITY, tx1=-INFINITY, tn0=INFINITY, tn1=INFINITY;
        #pragma unroll
        for (int nt = 0; nt < 16; nt++){
            tx0 = fmaxf(tx0, fmaxf(acc[nt][0], acc[nt][1]));
            tx1 = fmaxf(tx1, fmaxf(acc[nt][2], acc[nt][3]));
            tn0 = fminf(tn0, fminf(acc[nt][0], acc[nt][1]));
            tn1 = fminf(tn1, fminf(acc[nt][2], acc[nt][3]));
        }
        tx0 = qmax(tx0); tx1 = qmax(tx1);
        tn0 = qmin(tn0); tn1 = qmin(tn1);
        float nm0 = fmaxf(m0, tx0), nm1 = fmaxf(m1, tx1);
        float se0 = 0.f, se1 = 0.f;
        #pragma unroll
        for (int nt = 0; nt < 16; nt++){
            se0 += __expf(acc[nt][0]-nm0) + __expf(acc[nt][1]-nm0);
            se1 += __expf(acc[nt][2]-nm1) + __expf(acc[nt][3]-nm1);
        }
        se0 = qsum(se0); se1 = qsum(se1);
        S0 = S0*__expf(m0-nm0) + se0;  m0 = nm0;  n0 = fminf(n0, tn0);
        S1 = S1*__expf(m1-nm1) + se1;  m1 = nm1;  n1 = fminf(n1, tn1);

        __syncthreads();
        st ^= 1;
    }

    if ((lane & 3) == 0){
        g_rowm[bh*SEQ + qt*128 + r0] = m0;  g_rowS[bh*SEQ + qt*128 + r0] = S0;
        g_rowm[bh*SEQ + qt*128 + r1] = m1;  g_rowS[bh*SEQ + qt*128 + r1] = S1;
    }
    float i0 = __fdiv_rn(1.0f, S0), i1 = __fdiv_rn(1.0f, S1);
    float ax = fmaxf(i0, i1);
    float an = fminf(__expf(n0 - m0)*i0, __expf(n1 - m1)*i1);
    redx[tid] = ax; redn[tid] = an; __syncthreads();
    for (int o = 128; o > 0; o >>= 1){
        if (tid < o){ redx[tid] = fmaxf(redx[tid], redx[tid+o]); redn[tid] = fminf(redn[tid], redn[tid+o]); }
        __syncthreads();
    }
    if (tid == 0){
        atomicMax(&g_stat[10], fenc(redx[0]));
        atomicMin(&g_stat[11], fenc(redn[0]));
    }
}

// ---------------- fused attention: recompute + quantize + AV ----------------
__global__ void __launch_bounds__(256) k_attn_av(){
    extern __shared__ __align__(16) char smraw[];
    bf16* Qs  = (bf16*)smraw;
    bf16* Ks0 = (bf16*)(smraw + 18432);
    bf16* Ks1 = (bf16*)(smraw + 18432*2);
    bf16* Vs  = (bf16*)(smraw + 18432*3);
    float* csk0 = (float*)(smraw + 18432*4);
    float* csk1 = (float*)(smraw + 18432*4 + 512);
    float* vcs  = (float*)(smraw + 18432*4 + 1024);

    int bh = blockIdx.y, qt = blockIdx.x;
    int b = bh / NH, h = bh - b*NH;
    int tid = threadIdx.x, warp = tid >> 5, lane = tid & 31;
    int l16 = lane & 15;

    float sq, zq, iq, sk, zk, ik, sv, zv, iv, sa, za, ia;
    get_szi(2, sq, zq, iq); get_szi(3, sk, zk, ik);
    get_szi(4, sv, zv, iv); get_szi(5, sa, za, ia);
    float s3 = (0.125f * sq) * sk;

    {
        #pragma unroll
        for (int it = 0; it < 4; it++){
            int idx = it*256 + tid;
            int r = idx >> 3, c8 = idx & 7;
            cpa(&Ks0[r*72 + c8*8], &g_kb[((long long)bh*SEQ + r)*DHD + c8*8]);
        }
        if (tid < 32) cpa(&csk0[tid*4], &g_colsumk[bh*SEQ + tid*4]);
        CP_COMMIT;
        #pragma unroll
        for (int it = 0; it < 4; it++){
            int idx = it*256 + tid;
            int r = idx >> 3, c8 = idx & 7;
            cpa(&Qs[r*72 + c8*8], &g_qb[((long long)bh*SEQ + qt*128 + r)*DHD + c8*8]);
        }
        if (tid < 16) cpa(&vcs[tid*4], &g_vcolsum[bh*DHD + tid*4]);
        CP_COMMIT;
    }

    int r0 = warp*16 + (lane>>2), r1 = r0 + 8;
    float rsq0 = g_rowsumq[bh*SEQ + qt*128 + r0];
    float rsq1 = g_rowsumq[bh*SEQ + qt*128 + r1];
    float m0 = g_rowm[bh*SEQ + qt*128 + r0], S0 = g_rowS[bh*SEQ + qt*128 + r0];
    float m1 = g_rowm[bh*SEQ + qt*128 + r1], S1 = g_rowS[bh*SEQ + qt*128 + r1];
    float coef0 = __fdiv_rn(1.0f, S0) * ia;
    float coef1 = __fdiv_rn(1.0f, S1) * ia;

    float oacc[8][4];
    #pragma unroll
    for (int nt = 0; nt < 8; nt++){ oacc[nt][0]=0.f; oacc[nt][1]=0.f; oacc[nt][2]=0.f; oacc[nt][3]=0.f; }
    float aqs0 = 0.f, aqs1 = 0.f;

    int st = 0;
    for (int kt = 0; kt < 8; kt++){
        bf16*  Kc  = st ? Ks1 : Ks0;
        float* ckc = st ? csk1 : csk0;
        if (kt < 7){
            bf16*  Kn  = st ? Ks0 : Ks1;
            float* ckn = st ? csk0 : csk1;
            #pragma unroll
            for (int it = 0; it < 4; it++){
                int idx = it*256 + tid;
                int r = idx >> 3, c8 = idx & 7;
                cpa(&Kn[r*72 + c8*8], &g_kb[((long long)bh*SEQ + (kt+1)*128 + r)*DHD + c8*8]);
            }
            if (tid < 32) cpa(&ckn[tid*4], &g_colsumk[bh*SEQ + (kt+1)*128 + tid*4]);
            CP_COMMIT;
        }
        #pragma unroll
        for (int it = 0; it < 4; it++){
            int idx = it*256 + tid;
            int r = idx >> 3, c8 = idx & 7;
            cpa(&Vs[r*72 + c8*8], &g_vb[((long long)bh*SEQ + kt*128 + r)*DHD + c8*8]);
        }
        CP_COMMIT;
        if (kt < 7) { CP_WAIT2; } else { CP_WAIT1; }
        __syncthreads();

        float acc[16][4];
        #pragma unroll
        for (int nt = 0; nt < 16; nt++){ acc[nt][0]=0.f; acc[nt][1]=0.f; acc[nt][2]=0.f; acc[nt][3]=0.f; }
        #pragma unroll
        for (int kk = 0; kk < 64; kk += 16){
            u32 af[4];
            ldsm4(af, &Qs[(warp*16 + l16)*72 + kk + (lane>>4)*8]);
            #pragma unroll
            for (int nt = 0; nt < 16; nt++){
                u32 bf[2];
                ldsm2(bf, &Kc[(nt*8 + (l16&7))*72 + kk + ((l16>>3)&1)*8]);
                mma16816(acc[nt], af, bf);
            }
        }

        int c = (lane&3)*2;
        #pragma unroll
        for (int nt = 0; nt < 16; nt++){
            int cg = nt*8 + c;
            float cz0 = ckc[cg]*zq, cz1 = ckc[cg+1]*zq;
            acc[nt][0] = (acc[nt][0] - cz0 - rsq0*zk)*s3;
            acc[nt][1] = (acc[nt][1] - cz1 - rsq0*zk)*s3;
            acc[nt][2] = (acc[nt][2] - cz0 - rsq1*zk)*s3;
            acc[nt][3] = (acc[nt][3] - cz1 - rsq1*zk)*s3;
        }

        if (kt < 7) { CP_WAIT1; } else { CP_WAIT0; }
        __syncthreads();

        #pragma unroll
        for (int j = 0; j < 8; j++){
            float q00 = rintf(fmaf(__expf(acc[2*j][0]   - m0), coef0, za));
            float q01 = rintf(fmaf(__expf(acc[2*j][1]   - m0), coef0, za));
            float q02 = rintf(fmaf(__expf(acc[2*j][2]   - m1), coef1, za));
            float q03 = rintf(fmaf(__expf(acc[2*j][3]   - m1), coef1, za));
            float q10 = rintf(fmaf(__expf(acc[2*j+1][0] - m0), coef0, za));
            float q11 = rintf(fmaf(__expf(acc[2*j+1][1] - m0), coef0, za));
            float q12 = rintf(fmaf(__expf(acc[2*j+1][2] - m1), coef1, za));
            float q13 = rintf(fmaf(__expf(acc[2*j+1][3] - m1), coef1, za));
            aqs0 += q00 + q01 + q10 + q11;
            aqs1 += q02 + q03 + q12 + q13;
            u32 pa[4];
            pa[0] = packbf2(q00, q01);
            pa[1] = packbf2(q02, q03);
            pa[2] = packbf2(q10, q11);
            pa[3] = packbf2(q12, q13);
            #pragma unroll
            for (int nt = 0; nt < 8; nt++){
                u32 vf[2];
                ldsm2t(vf, &Vs[(16*j + l16)*72 + nt*8]);
                mma16816(oacc[nt], pa, vf);
            }
        }
        __syncthreads();
        st ^= 1;
    }

    aqs0 = qsum(aqs0);
    aqs1 = qsum(aqs1);

    float mult  = sa * sv;
    float cterm = (za * zv) * (float)SEQ;
    int c = (lane&3)*2;
    long long ob0 = (long long)(b*SEQ + qt*128 + r0)*DMODEL + h*DHD;
    long long ob1 = (long long)(b*SEQ + qt*128 + r1)*DMODEL + h*DHD;
    #pragma unroll
    for (int nt = 0; nt < 8; nt++){
        int d0 = nt*8 + c;
        float w0 = vcs[d0]*za, w1 = vcs[d0+1]*za;
        g_outbuf[ob0 + d0]     = (oacc[nt][0] - w0 - aqs0*zv + cterm)*mult;
        g_outbuf[ob0 + d0 + 1] = (oacc[nt][1] - w1 - aqs0*zv + cterm)*mult;
        g_outbuf[ob1 + d0]     = (oacc[nt][2] - w0 - aqs1*zv + cterm)*mult;
        g_outbuf[ob1 + d0 + 1] = (oacc[nt][3] - w1 - aqs1*zv + cterm)*mult;
    }
}

// ---------------- pipelined tensor-core GEMM (A [M][K], B [N][K], both k-contig) ----------------
template<int F1>
__global__ void __launch_bounds__(256) k_mma(
    const bf16* __restrict__ A, int lda,
    const bf16* __restrict__ Bm, int ldb,
    float* __restrict__ C, int ldc,
    int K,
    const float* __restrict__ colsumB,
    const float* __restrict__ rowsumA,
    int slotA, int slotB, float Kconst,
    const float* __restrict__ bias)
{
    const int BK = 32, PAD = 40;
    __shared__ __align__(16) bf16 As[2][128*PAD];
    __shared__ __align__(16) bf16 Bs[2][128*PAD];
    __shared__ float redx[256], redn[256];

    int i0 = blockIdx.y * 128, j0 = blockIdx.x * 128;
    int tid = threadIdx.x, warp = tid >> 5, lane = tid & 31;
    int wm = warp >> 2, wn = warp & 3;
    int l16 = lane & 15;

    float acc[4][4][4];
    #pragma unroll
    for (int a = 0; a < 4; a++)
        #pragma unroll
        for (int b = 0; b < 4; b++){
            acc[a][b][0]=0.f; acc[a][b][1]=0.f; acc[a][b][2]=0.f; acc[a][b][3]=0.f;
        }

    {
        #pragma unroll
        for (int v = 0; v < 2; v++){
            int idx = v*256 + tid;
            int r = idx >> 2, c8 = idx & 3;
            cpa(&As[0][r*PAD + c8*8], &A[(long long)(i0 + r)*lda + c8*8]);
        }
        #pragma unroll
        for (int v = 0; v < 2; v++){
            int idx = v*256 + tid;
            int r = idx >> 2, c8 = idx & 3;
            cpa(&Bs[0][r*PAD + c8*8], &Bm[(long long)(j0 + r)*ldb + c8*8]);
        }
        CP_COMMIT;
    }

    int st = 0;
    for (int k0 = 0; k0 < K; k0 += BK){
        if (k0 + BK < K){
            int ns = st ^ 1, kn = k0 + BK;
            #pragma unroll
            for (int v = 0; v < 2; v++){
                int idx = v*256 + tid;
                int r = idx >> 2, c8 = idx & 3;
                cpa(&As[ns][r*PAD + c8*8], &A[(long long)(i0 + r)*lda + kn + c8*8]);
            }
            #pragma unroll
            for (int v = 0; v < 2; v++){
                int idx = v*256 + tid;
                int r = idx >> 2, c8 = idx & 3;
                cpa(&Bs[ns][r*PAD + c8*8], &Bm[(long long)(j0 + r)*ldb + kn + c8*8]);
            }
            CP_COMMIT;
            CP_WAIT1;
        } else {
            CP_WAIT0;
        }
        __syncthreads();

        #pragma unroll
        for (int kk = 0; kk < BK; kk += 16){
            u32 af[4][4];
            #pragma unroll
            for (int mt = 0; mt < 4; mt++)
                ldsm4(af[mt], &As[st][(wm*64 + mt*16 + l16)*PAD + kk + (lane>>4)*8]);
            u32 bf[4][2];
            #pragma unroll
            for (int nt = 0; nt < 4; nt++)
                ldsm2(bf[nt], &Bs[st][(wn*32 + nt*8 + (l16&7))*PAD + kk + ((l16>>3)&1)*8]);
            #pragma unroll
            for (int mt = 0; mt < 4; mt++)
                #pragma unroll
                for (int nt = 0; nt < 4; nt++)
                    mma16816(acc[mt][nt], af[mt], bf[nt]);
        }
        __syncthreads();
        st ^= 1;
    }

    float sA, zA, iA, sB, zB, iB;
    get_szi(slotA, sA, zA, iA); get_szi(slotB, sB, zB, iB);
    float mult  = sA * sB;
    float cterm = (zA * zB) * Kconst;

    float lmx = -INFINITY, lmn = INFINITY;

    #pragma unroll
    for (int mt = 0; mt < 4; mt++){
        int row0 = i0 + wm*64 + mt*16 + (lane>>2);
        float rs0 = rowsumA[row0], rs1 = rowsumA[row0+8];
        float p0 = 0.f, p8 = 0.f;
        #pragma unroll
        for (int nt = 0; nt < 4; nt++){
            int col0 = j0 + wn*32 + nt*8 + (lane&3)*2;
            float cs0 = colsumB[col0], cs1 = colsumB[col0+1];
            float b0 = bias ? bias[col0]   : 0.f;
            float b1 = bias ? bias[col0+1] : 0.f;
            float v0 = (acc[mt][nt][0] - cs0*zA - rs0*zB + cterm)*mult + b0;
            float v1 = (acc[mt][nt][1] - cs1*zA - rs0*zB + cterm)*mult + b1;
            float v2 = (acc[mt][nt][2] - cs0*zA - rs1*zB + cterm)*mult + b0;
            float v3 = (acc[mt][nt][3] - cs1*zA - rs1*zB + cterm)*mult + b1;
            C[(long long)row0*ldc + col0]       = v0;
            C[(long long)row0*ldc + col0 + 1]   = v1;
            C[(long long)(row0+8)*ldc + col0]   = v2;
            C[(long long)(row0+8)*ldc + col0+1] = v3;
            if (F1){
                p0 += v0 + v1; p8 += v2 + v3;
                lmx = fmaxf(lmx, fmaxf(fmaxf(v0,v1), fmaxf(v2,v3)));
                lmn = fminf(lmn, fminf(fminf(v0,v1), fminf(v2,v3)));
            }
        }
        if (F1){
            p0 = qsum(p0); p8 = qsum(p8);
            if ((lane & 3) == 0){
                atomicAdd(&g_xqkvsum[row0],   p0);
                atomicAdd(&g_xqkvsum[row0+8], p8);
            }
        }
    }

    if (F1){
        redx[tid] = lmx; redn[tid] = lmn; __syncthreads();
        for (int o = 128; o > 0; o >>= 1){
            if (tid < o){ redx[tid] = fmaxf(redx[tid], redx[tid+o]); redn[tid] = fminf(redn[tid], redn[tid+o]); }
            __syncthreads();
        }
        if (tid == 0){
            int region = blockIdx.x / 6;
            atomicMax(&g_stat[2*(2+region)],   fenc(redx[0]));
            atomicMin(&g_stat[2*(2+region)+1], fenc(redn[0]));
        }
    }
}

// ---------------- launcher ----------------
extern "C" void kernel_launch(void* const* d_in, const int* in_sizes, int n_in,
                              void* d_out, int out_size){
    const float *x = 0, *wqkv = 0, *wout = 0, *bout = 0;
    for (int i = 0; i < n_in; i++){
        if      (in_sizes[i] == MROWS*DMODEL)  x    = (const float*)d_in[i];
        else if (in_sizes[i] == J3*DMODEL)     wqkv = (const float*)d_in[i];
        else if (in_sizes[i] == DMODEL*DMODEL) wout = (const float*)d_in[i];
        else if (in_sizes[i] == DMODEL)        bout = (const float*)d_in[i];
    }
    float* out = (float*)d_out;

    bf16 *p_xq, *p_wq1, *p_wq2;
    float *p_xqkv, *p_outbuf;
    float *p_rowsum_x, *p_colsum_w1, *p_colsum_w2, *p_xqkvsum;
    cudaGetSymbolAddress((void**)&p_xq,        g_xq);
    cudaGetSymbolAddress((void**)&p_wq1,       g_wq1);
    cudaGetSymbolAddress((void**)&p_wq2,       g_wq2);
    cudaGetSymbolAddress((void**)&p_xqkv,      g_xqkv);
    cudaGetSymbolAddress((void**)&p_outbuf,    g_outbuf);
    cudaGetSymbolAddress((void**)&p_rowsum_x,  g_rowsum_x);
    cudaGetSymbolAddress((void**)&p_colsum_w1, g_colsum_w1);
    cudaGetSymbolAddress((void**)&p_colsum_w2, g_colsum_w2);
    cudaGetSymbolAddress((void**)&p_xqkvsum,   g_xqkvsum);

    static int smem_set = 0;
    if (!smem_set){
        cudaFuncSetAttribute(k_attn_stats, cudaFuncAttributeMaxDynamicSharedMemorySize, 18432*3 + 2048);
        cudaFuncSetAttribute(k_attn_av,    cudaFuncAttributeMaxDynamicSharedMemorySize, 18432*4 + 2048);
        smem_set = 1;
    }

    k_init<<<1, 256>>>();
    k_minmax2<<<dim3(768, 2), 256>>>(x, MROWS*DMODEL, 0, wqkv, J3*DMODEL, 1);
    k_quantrow<<<MROWS/8, 256>>>(x, p_xq, p_rowsum_x, 0);
    k_quantrow<<<J3/8, 256>>>(wqkv, p_wq1, p_colsum_w1, 1);
    k_mma<1><<<dim3(J3/128, MROWS/128), 256>>>(
        p_xq, DMODEL, p_wq1, DMODEL, p_xqkv, J3, DMODEL,
        p_colsum_w1, p_rowsum_x, 0, 1, (float)DMODEL, (const float*)0);
    k_pack_qkv<<<dim3(SEQ/8, BHN), 256>>>();
    k_attn_stats<<<dim3(8, BHN), 256, 18432*3 + 2048>>>();
    k_attn_av<<<dim3(8, BHN), 256, 18432*4 + 2048>>>();
    k_minmax2<<<dim3(768, 2), 256>>>(p_outbuf, MROWS*DMODEL, 6, wout, DMODEL*DMODEL, 7);
    k_quantrow<<<MROWS/8, 256>>>(p_outbuf, p_xq, p_rowsum_x /*dummy*/, 6);
    k_quantrow<<<DMODEL/8, 256>>>(wout, p_wq2, p_colsum_w2, 7);
    k_mma<0><<<dim3(DMODEL/128, MROWS/128), 256>>>(
        p_xq, DMODEL, p_wq2, DMODEL, out, DMODEL, DMODEL,
        p_colsum_w2, p_xqkvsum, 6, 7, (float)J3, bout);
}

// round 10
// speedup vs baseline: 1.5694x; 1.0038x over previous
#include <cuda_runtime.h>
#include <cuda_bf16.h>
#include <cstdint>
#include <cstddef>
#include <math.h>

#define NB      4
#define SEQ     1024
#define DMODEL  768
#define NH      12
#define DHD     64
#define J3      2304
#define MROWS   4096
#define BHN     48

typedef __nv_bfloat16 bf16;
typedef unsigned int  u32;

// ---------------- scratch ----------------
__device__ __align__(16) bf16  g_xq[MROWS*DMODEL];         // quantized x / out (bf16)
__device__ __align__(16) bf16  g_wq1[J3*DMODEL];           // quantized w_qkv [n][k]
__device__ __align__(16) bf16  g_wq2[DMODEL*DMODEL];       // quantized w_out [n][k]
__device__ __align__(16) float g_xqkv[MROWS*J3];
__device__ __align__(16) bf16  g_qb[BHN*SEQ*DHD];
__device__ __align__(16) bf16  g_kb[BHN*SEQ*DHD];
__device__ __align__(16) bf16  g_vb[BHN*SEQ*DHD];
__device__ __align__(16) float g_outbuf[MROWS*DMODEL];
__device__ float    g_rowsum_x[MROWS];
__device__ float    g_colsum_w1[J3];
__device__ float    g_colsum_w2[DMODEL];
__device__ float    g_xqkvsum[MROWS];
__device__ float    g_rowsumq[BHN*SEQ];
__device__ float    g_colsumk[BHN*SEQ];
__device__ float    g_vcolsum[BHN*DHD];
__device__ float    g_rowm[BHN*SEQ];
__device__ float    g_rowS[BHN*SEQ];
__device__ unsigned g_stat[16];   // slots:0=x 1=w1 2=q 3=k 4=v 5=a 6=out 7=w2

// ---------------- helpers ----------------
__device__ __forceinline__ unsigned fenc(float f){
    unsigned u = __float_as_uint(f);
    return (u & 0x80000000u) ? ~u : (u | 0x80000000u);
}
__device__ __forceinline__ float fdec(unsigned e){
    return (e & 0x80000000u) ? __uint_as_float(e ^ 0x80000000u) : __uint_as_float(~e);
}
__device__ __forceinline__ void get_szi(int slot, float& s, float& z, float& is){
    float mx = fdec(g_stat[2*slot]);
    float mn = fdec(g_stat[2*slot+1]);
    s = __fdiv_rn(mx - mn, 15.0f);
    z = rintf(15.0f - __fdiv_rn(mx, s));
    is = __fdiv_rn(1.0f, s);
}
__device__ __forceinline__ float quantm(float v, float is, float z){
    return rintf(fmaf(v, is, z));
}
__device__ __forceinline__ u32 packbf2(float lo, float hi){
    __nv_bfloat162 t = __floats2bfloat162_rn(lo, hi);
    return *reinterpret_cast<u32*>(&t);
}
__device__ __forceinline__ void ldsm4(u32* r, const void* p){
    u32 a = (u32)__cvta_generic_to_shared(p);
    asm volatile("ldmatrix.sync.aligned.m8n8.x4.shared.b16 {%0,%1,%2,%3},[%4];"
        : "=r"(r[0]),"=r"(r[1]),"=r"(r[2]),"=r"(r[3]) : "r"(a));
}
__device__ __forceinline__ void ldsm2(u32* r, const void* p){
    u32 a = (u32)__cvta_generic_to_shared(p);
    asm volatile("ldmatrix.sync.aligned.m8n8.x2.shared.b16 {%0,%1},[%2];"
        : "=r"(r[0]),"=r"(r[1]) : "r"(a));
}
__device__ __forceinline__ void ldsm2t(u32* r, const void* p){
    u32 a = (u32)__cvta_generic_to_shared(p);
    asm volatile("ldmatrix.sync.aligned.m8n8.x2.trans.shared.b16 {%0,%1},[%2];"
        : "=r"(r[0]),"=r"(r[1]) : "r"(a));
}
__device__ __forceinline__ void mma16816(float* c, const u32* a, const u32* b){
    asm volatile("mma.sync.aligned.m16n8k16.row.col.f32.bf16.bf16.f32 "
        "{%0,%1,%2,%3}, {%4,%5,%6,%7}, {%8,%9}, {%0,%1,%2,%3};"
        : "+f"(c[0]),"+f"(c[1]),"+f"(c[2]),"+f"(c[3])
        : "r"(a[0]),"r"(a[1]),"r"(a[2]),"r"(a[3]), "r"(b[0]),"r"(b[1]));
}
__device__ __forceinline__ void cpa(void* s, const void* g){
    u32 a = (u32)__cvta_generic_to_shared(s);
    asm volatile("cp.async.cg.shared.global [%0],[%1],16;" :: "r"(a), "l"(g));
}
#define CP_COMMIT asm volatile("cp.async.commit_group;")
#define CP_WAIT0  asm volatile("cp.async.wait_group 0;")
#define CP_WAIT1  asm volatile("cp.async.wait_group 1;")
#define CP_WAIT2  asm volatile("cp.async.wait_group 2;")

__device__ __forceinline__ float qsum(float v){
    v += __shfl_xor_sync(0xffffffffu, v, 1);
    v += __shfl_xor_sync(0xffffffffu, v, 2);
    return v;
}
__device__ __forceinline__ float qmax(float v){
    v = fmaxf(v, __shfl_xor_sync(0xffffffffu, v, 1));
    v = fmaxf(v, __shfl_xor_sync(0xffffffffu, v, 2));
    return v;
}
__device__ __forceinline__ float qmin(float v){
    v = fminf(v, __shfl_xor_sync(0xffffffffu, v, 1));
    v = fminf(v, __shfl_xor_sync(0xffffffffu, v, 2));
    return v;
}
__device__ __forceinline__ float wsum(float v){
    #pragma unroll
    for (int o = 16; o > 0; o >>= 1) v += __shfl_xor_sync(0xffffffffu, v, o);
    return v;
}

// ---------------- elementwise kernels ----------------
__global__ void k_init(){
    int t = threadIdx.x;
    if (t < 8){ g_stat[2*t] = fenc(-INFINITY); g_stat[2*t+1] = fenc(INFINITY); }
    for (int i = t; i < BHN*DHD; i += blockDim.x) g_vcolsum[i] = 0.f;
    for (int i = t; i < MROWS;   i += blockDim.x) g_xqkvsum[i] = 0.f;
}

// triple-tensor minmax: blockIdx.y selects (p,n,slot)
__global__ void k_minmax3(const float* __restrict__ pa, int na, int sa_,
                          const float* __restrict__ pb, int nb, int sb_,
                          const float* __restrict__ pc, int nc, int sc_){
    const float* p; int n, slot;
    if (blockIdx.y == 0){ p = pa; n = na; slot = sa_; }
    else if (blockIdx.y == 1){ p = pb; n = nb; slot = sb_; }
    else { p = pc; n = nc; slot = sc_; }
    float mx = -INFINITY, mn = INFINITY;
    int n4 = n >> 2;
    const float4* p4 = (const float4*)p;
    for (int i = blockIdx.x*blockDim.x + threadIdx.x; i < n4; i += gridDim.x*blockDim.x){
        float4 v = p4[i];
        mx = fmaxf(mx, fmaxf(fmaxf(v.x,v.y), fmaxf(v.z,v.w)));
        mn = fminf(mn, fminf(fminf(v.x,v.y), fminf(v.z,v.w)));
    }
    __shared__ float smx[256], smn[256];
    int t = threadIdx.x;
    smx[t] = mx; smn[t] = mn; __syncthreads();
    for (int o = 128; o > 0; o >>= 1){
        if (t < o){ smx[t] = fmaxf(smx[t], smx[t+o]); smn[t] = fminf(smn[t], smn[t+o]); }
        __syncthreads();
    }
    if (t == 0){
        atomicMax(&g_stat[2*slot],   fenc(smx[0]));
        atomicMin(&g_stat[2*slot+1], fenc(smn[0]));
    }
}

// warp-per-row quantize -> bf16 (row-major, rowlen 768), fused row sums
__global__ void k_quantrow(const float* __restrict__ src, bf16* __restrict__ dst,
                           float* __restrict__ rowsum, int slot){
    int warp = threadIdx.x >> 5, lane = threadIdx.x & 31;
    int r = blockIdx.x*8 + warp;
    float s, z, is; get_szi(slot, s, z, is);
    const float4* s4 = (const float4*)(src + (long long)r*DMODEL);
    uint2* d2 = (uint2*)(dst + (long long)r*DMODEL);
    float acc = 0.f;
    #pragma unroll
    for (int i = 0; i < 6; i++){
        float4 v = s4[i*32 + lane];
        float q0 = quantm(v.x, is, z), q1 = quantm(v.y, is, z);
        float q2 = quantm(v.z, is, z), q3 = quantm(v.w, is, z);
        acc += (q0+q1) + (q2+q3);
        uint2 o; o.x = packbf2(q0,q1); o.y = packbf2(q2,q3);
        d2[i*32 + lane] = o;
    }
    acc = wsum(acc);
    if (lane == 0) rowsum[r] = acc;
}

// warp-per-token pack of quantized q/k/v; fused token sums + v colsum
__global__ void k_pack_qkv(){
    __shared__ float vsum[64];
    int bh = blockIdx.y;
    int b = bh / NH, h = bh - b*NH;
    int warp = threadIdx.x >> 5, lane = threadIdx.x & 31;
    int n = blockIdx.x*8 + warp;
    if (threadIdx.x < 64) vsum[threadIdx.x] = 0.f;
    __syncthreads();
    float sq, zq, iq, sk, zk, ik, sv, zv, iv;
    get_szi(2, sq, zq, iq); get_szi(3, sk, zk, ik); get_szi(4, sv, zv, iv);
    long long base = (long long)(b*SEQ + n)*J3 + h*DHD + 2*lane;
    float2 qv2 = *(const float2*)&g_xqkv[base];
    float2 kv2 = *(const float2*)&g_xqkv[base + DMODEL];
    float2 vv2 = *(const float2*)&g_xqkv[base + 2*DMODEL];
    float q0 = quantm(qv2.x, iq, zq), q1 = quantm(qv2.y, iq, zq);
    float k0 = quantm(kv2.x, ik, zk), k1 = quantm(kv2.y, ik, zk);
    float v0 = quantm(vv2.x, iv, zv), v1 = quantm(vv2.y, iv, zv);
    long long po = ((long long)bh*SEQ + n)*DHD/2 + lane;
    ((u32*)g_qb)[po] = packbf2(q0, q1);
    ((u32*)g_kb)[po] = packbf2(k0, k1);
    ((u32*)g_vb)[po] = packbf2(v0, v1);
    float qs = wsum(q0 + q1);
    float ks = wsum(k0 + k1);
    if (lane == 0){
        g_rowsumq[bh*SEQ + n] = qs;
        g_colsumk[bh*SEQ + n] = ks;
    }
    atomicAdd(&vsum[2*lane],   v0);
    atomicAdd(&vsum[2*lane+1], v1);
    __syncthreads();
    if (threadIdx.x < 64) atomicAdd(&g_vcolsum[bh*DHD + threadIdx.x], vsum[threadIdx.x]);
}

// ---------------- fused attention: stats pass ----------------
__global__ void __launch_bounds__(256) k_attn_stats(){
    extern __shared__ __align__(16) char smraw[];
    bf16* Qs  = (bf16*)smraw;
    bf16* Ks0 = (bf16*)(smraw + 18432);
    bf16* Ks1 = (bf16*)(smraw + 18432*2);
    float* csk0 = (float*)(smraw + 18432*3);
    float* csk1 = (float*)(smraw + 18432*3 + 512);
    __shared__ float redx[256], redn[256];

    int bh = blockIdx.y, qt = blockIdx.x;
    int tid = threadIdx.x, warp = tid >> 5, lane = tid & 31;
    int l16 = lane & 15;

    float sq, zq, iq, sk, zk, ik;
    get_szi(2, sq, zq, iq); get_szi(3, sk, zk, ik);
    float s3 = (0.125f * sq) * sk;

    {
        #pragma unroll
        for (int it = 0; it < 4; it++){
            int idx = it*256 + tid;
            int r = idx >> 3, c8 = idx & 7;
            cpa(&Ks0[r*72 + c8*8], &g_kb[((long long)bh*SEQ + r)*DHD + c8*8]);
        }
        if (tid < 32) cpa(&csk0[tid*4], &g_colsumk[bh*SEQ + tid*4]);
        CP_COMMIT;
        #pragma unroll
        for (int it = 0; it < 4; it++){
            int idx = it*256 + tid;
            int r = idx >> 3, c8 = idx & 7;
            cpa(&Qs[r*72 + c8*8], &g_qb[((long long)bh*SEQ + qt*128 + r)*DHD + c8*8]);
        }
        CP_COMMIT;
    }

    int r0 = warp*16 + (lane>>2), r1 = r0 + 8;
    float rsq0 = g_rowsumq[bh*SEQ + qt*128 + r0];
    float rsq1 = g_rowsumq[bh*SEQ + qt*128 + r1];

    float m0 = -INFINITY, m1 = -INFINITY;
    float n0 =  INFINITY, n1 =  INFINITY;
    float S0 = 0.f, S1 = 0.f;

    int st = 0;
    for (int kt = 0; kt < 8; kt++){
        bf16*  Kc  = st ? Ks1 : Ks0;
        float* ckc = st ? csk1 : csk0;
        if (kt < 7){
            bf16*  Kn  = st ? Ks0 : Ks1;
            float* ckn = st ? csk0 : csk1;
            #pragma unroll
            for (int it = 0; it < 4; it++){
                int idx = it*256 + tid;
                int r = idx >> 3, c8 = idx & 7;
                cpa(&Kn[r*72 + c8*8], &g_kb[((long long)bh*SEQ + (kt+1)*128 + r)*DHD + c8*8]);
            }
            if (tid < 32) cpa(&ckn[tid*4], &g_colsumk[bh*SEQ + (kt+1)*128 + tid*4]);
            CP_COMMIT;
            CP_WAIT1;
        } else {
            CP_WAIT0;
        }
        __syncthreads();

        float acc[16][4];
        #pragma unroll
        for (int nt = 0; nt < 16; nt++){ acc[nt][0]=0.f; acc[nt][1]=0.f; acc[nt][2]=0.f; acc[nt][3]=0.f; }
        #pragma unroll
        for (int kk = 0; kk < 64; kk += 16){
            u32 af[4];
            ldsm4(af, &Qs[(warp*16 + l16)*72 + kk + (lane>>4)*8]);
            #pragma unroll
            for (int nt = 0; nt < 16; nt++){
                u32 bf[2];
                ldsm2(bf, &Kc[(nt*8 + (l16&7))*72 + kk + ((l16>>3)&1)*8]);
                mma16816(acc[nt], af, bf);
            }
        }

        int c = (lane&3)*2;
        #pragma unroll
        for (int nt = 0; nt < 16; nt++){
            int cg = nt*8 + c;
            float cz0 = ckc[cg]*zq, cz1 = ckc[cg+1]*zq;
            acc[nt][0] = (acc[nt][0] - cz0 - rsq0*zk)*s3;
            acc[nt][1] = (acc[nt][1] - cz1 - rsq0*zk)*s3;
            acc[nt][2] = (acc[nt][2] - cz0 - rsq1*zk)*s3;
            acc[nt][3] = (acc[nt][3] - cz1 - rsq1*zk)*s3;
        }
        float tx0=-INFINITY, tx1=-INFINITY, tn0=INFINITY, tn1=INFINITY;
        #pragma unroll
        for (int nt = 0; nt < 16; nt++){
            tx0 = fmaxf(tx0, fmaxf(acc[nt][0], acc[nt][1]));
            tx1 = fmaxf(tx1, fmaxf(acc[nt][2], acc[nt][3]));
            tn0 = fminf(tn0, fminf(acc[nt][0], acc[nt][1]));
            tn1 = fminf(tn1, fminf(acc[nt][2], acc[nt][3]));
        }
        tx0 = qmax(tx0); tx1 = qmax(tx1);
        tn0 = qmin(tn0); tn1 = qmin(tn1);
        float nm0 = fmaxf(m0, tx0), nm1 = fmaxf(m1, tx1);
        float se0 = 0.f, se1 = 0.f;
        #pragma unroll
        for (int nt = 0; nt < 16; nt++){
            se0 += __expf(acc[nt][0]-nm0) + __expf(acc[nt][1]-nm0);
            se1 += __expf(acc[nt][2]-nm1) + __expf(acc[nt][3]-nm1);
        }
        se0 = qsum(se0); se1 = qsum(se1);
        S0 = S0*__expf(m0-nm0) + se0;  m0 = nm0;  n0 = fminf(n0, tn0);
        S1 = S1*__expf(m1-nm1) + se1;  m1 = nm1;  n1 = fminf(n1, tn1);

        __syncthreads();
        st ^= 1;
    }

    if ((lane & 3) == 0){
        g_rowm[bh*SEQ + qt*128 + r0] = m0;  g_rowS[bh*SEQ + qt*128 + r0] = S0;
        g_rowm[bh*SEQ + qt*128 + r1] = m1;  g_rowS[bh*SEQ + qt*128 + r1] = S1;
    }
    float i0 = __fdiv_rn(1.0f, S0), i1 = __fdiv_rn(1.0f, S1);
    float ax = fmaxf(i0, i1);
    float an = fminf(__expf(n0 - m0)*i0, __expf(n1 - m1)*i1);
    redx[tid] = ax; redn[tid] = an; __syncthreads();
    for (int o = 128; o > 0; o >>= 1){
        if (tid < o){ redx[tid] = fmaxf(redx[tid], redx[tid+o]); redn[tid] = fminf(redn[tid], redn[tid+o]); }
        __syncthreads();
    }
    if (tid == 0){
        atomicMax(&g_stat[10], fenc(redx[0]));
        atomicMin(&g_stat[11], fenc(redn[0]));
    }
}

// ---------------- fused attention: recompute + quantize + AV (+out minmax) ----------------
__global__ void __launch_bounds__(256) k_attn_av(){
    extern __shared__ __align__(16) char smraw[];
    bf16* Qs  = (bf16*)smraw;
    bf16* Ks0 = (bf16*)(smraw + 18432);
    bf16* Ks1 = (bf16*)(smraw + 18432*2);
    bf16* Vs  = (bf16*)(smraw + 18432*3);
    float* csk0 = (float*)(smraw + 18432*4);
    float* csk1 = (float*)(smraw + 18432*4 + 512);
    float* vcs  = (float*)(smraw + 18432*4 + 1024);
    __shared__ float redx[256], redn[256];

    int bh = blockIdx.y, qt = blockIdx.x;
    int b = bh / NH, h = bh - b*NH;
    int tid = threadIdx.x, warp = tid >> 5, lane = tid & 31;
    int l16 = lane & 15;

    float sq, zq, iq, sk, zk, ik, sv, zv, iv, sa, za, ia;
    get_szi(2, sq, zq, iq); get_szi(3, sk, zk, ik);
    get_szi(4, sv, zv, iv); get_szi(5, sa, za, ia);
    float s3 = (0.125f * sq) * sk;

    {
        #pragma unroll
        for (int it = 0; it < 4; it++){
            int idx = it*256 + tid;
            int r = idx >> 3, c8 = idx & 7;
            cpa(&Ks0[r*72 + c8*8], &g_kb[((long long)bh*SEQ + r)*DHD + c8*8]);
        }
        if (tid < 32) cpa(&csk0[tid*4], &g_colsumk[bh*SEQ + tid*4]);
        CP_COMMIT;
        #pragma unroll
        for (int it = 0; it < 4; it++){
            int idx = it*256 + tid;
            int r = idx >> 3, c8 = idx & 7;
            cpa(&Qs[r*72 + c8*8], &g_qb[((long long)bh*SEQ + qt*128 + r)*DHD + c8*8]);
        }
        if (tid < 16) cpa(&vcs[tid*4], &g_vcolsum[bh*DHD + tid*4]);
        CP_COMMIT;
    }

    int r0 = warp*16 + (lane>>2), r1 = r0 + 8;
    float rsq0 = g_rowsumq[bh*SEQ + qt*128 + r0];
    float rsq1 = g_rowsumq[bh*SEQ + qt*128 + r1];
    float m0 = g_rowm[bh*SEQ + qt*128 + r0], S0 = g_rowS[bh*SEQ + qt*128 + r0];
    float m1 = g_rowm[bh*SEQ + qt*128 + r1], S1 = g_rowS[bh*SEQ + qt*128 + r1];
    float coef0 = __fdiv_rn(1.0f, S0) * ia;
    float coef1 = __fdiv_rn(1.0f, S1) * ia;

    float oacc[8][4];
    #pragma unroll
    for (int nt = 0; nt < 8; nt++){ oacc[nt][0]=0.f; oacc[nt][1]=0.f; oacc[nt][2]=0.f; oacc[nt][3]=0.f; }
    float aqs0 = 0.f, aqs1 = 0.f;

    int st = 0;
    for (int kt = 0; kt < 8; kt++){
        bf16*  Kc  = st ? Ks1 : Ks0;
        float* ckc = st ? csk1 : csk0;
        if (kt < 7){
            bf16*  Kn  = st ? Ks0 : Ks1;
            float* ckn = st ? csk0 : csk1;
            #pragma unroll
            for (int it = 0; it < 4; it++){
                int idx = it*256 + tid;
                int r = idx >> 3, c8 = idx & 7;
                cpa(&Kn[r*72 + c8*8], &g_kb[((long long)bh*SEQ + (kt+1)*128 + r)*DHD + c8*8]);
            }
            if (tid < 32) cpa(&ckn[tid*4], &g_colsumk[bh*SEQ + (kt+1)*128 + tid*4]);
            CP_COMMIT;
        }
        #pragma unroll
        for (int it = 0; it < 4; it++){
            int idx = it*256 + tid;
            int r = idx >> 3, c8 = idx & 7;
            cpa(&Vs[r*72 + c8*8], &g_vb[((long long)bh*SEQ + kt*128 + r)*DHD + c8*8]);
        }
        CP_COMMIT;
        if (kt < 7) { CP_WAIT2; } else { CP_WAIT1; }
        __syncthreads();

        float acc[16][4];
        #pragma unroll
        for (int nt = 0; nt < 16; nt++){ acc[nt][0]=0.f; acc[nt][1]=0.f; acc[nt][2]=0.f; acc[nt][3]=0.f; }
        #pragma unroll
        for (int kk = 0; kk < 64; kk += 16){
            u32 af[4];
            ldsm4(af, &Qs[(warp*16 + l16)*72 + kk + (lane>>4)*8]);
            #pragma unroll
            for (int nt = 0; nt < 16; nt++){
                u32 bf[2];
                ldsm2(bf, &Kc[(nt*8 + (l16&7))*72 + kk + ((l16>>3)&1)*8]);
                mma16816(acc[nt], af, bf);
            }
        }

        int c = (lane&3)*2;
        #pragma unroll
        for (int nt = 0; nt < 16; nt++){
            int cg = nt*8 + c;
            float cz0 = ckc[cg]*zq, cz1 = ckc[cg+1]*zq;
            acc[nt][0] = (acc[nt][0] - cz0 - rsq0*zk)*s3;
            acc[nt][1] = (acc[nt][1] - cz1 - rsq0*zk)*s3;
            acc[nt][2] = (acc[nt][2] - cz0 - rsq1*zk)*s3;
            acc[nt][3] = (acc[nt][3] - cz1 - rsq1*zk)*s3;
        }

        if (kt < 7) { CP_WAIT1; } else { CP_WAIT0; }
        __syncthreads();

        #pragma unroll
        for (int j = 0; j < 8; j++){
            float q00 = rintf(fmaf(__expf(acc[2*j][0]   - m0), coef0, za));
            float q01 = rintf(fmaf(__expf(acc[2*j][1]   - m0), coef0, za));
            float q02 = rintf(fmaf(__expf(acc[2*j][2]   - m1), coef1, za));
            float q03 = rintf(fmaf(__expf(acc[2*j][3]   - m1), coef1, za));
            float q10 = rintf(fmaf(__expf(acc[2*j+1][0] - m0), coef0, za));
            float q11 = rintf(fmaf(__expf(acc[2*j+1][1] - m0), coef0, za));
            float q12 = rintf(fmaf(__expf(acc[2*j+1][2] - m1), coef1, za));
            float q13 = rintf(fmaf(__expf(acc[2*j+1][3] - m1), coef1, za));
            aqs0 += q00 + q01 + q10 + q11;
            aqs1 += q02 + q03 + q12 + q13;
            u32 pa[4];
            pa[0] = packbf2(q00, q01);
            pa[1] = packbf2(q02, q03);
            pa[2] = packbf2(q10, q11);
            pa[3] = packbf2(q12, q13);
            #pragma unroll
            for (int nt = 0; nt < 8; nt++){
                u32 vf[2];
                ldsm2t(vf, &Vs[(16*j + l16)*72 + nt*8]);
                mma16816(oacc[nt], pa, vf);
            }
        }
        __syncthreads();
        st ^= 1;
    }

    aqs0 = qsum(aqs0);
    aqs1 = qsum(aqs1);

    float mult  = sa * sv;
    float cterm = (za * zv) * (float)SEQ;
    int c = (lane&3)*2;
    long long ob0 = (long long)(b*SEQ + qt*128 + r0)*DMODEL + h*DHD;
    long long ob1 = (long long)(b*SEQ + qt*128 + r1)*DMODEL + h*DHD;
    float lmx = -INFINITY, lmn = INFINITY;
    #pragma unroll
    for (int nt = 0; nt < 8; nt++){
        int d0 = nt*8 + c;
        float w0 = vcs[d0]*za, w1 = vcs[d0+1]*za;
        float o0 = (oacc[nt][0] - w0 - aqs0*zv + cterm)*mult;
        float o1 = (oacc[nt][1] - w1 - aqs0*zv + cterm)*mult;
        float o2 = (oacc[nt][2] - w0 - aqs1*zv + cterm)*mult;
        float o3 = (oacc[nt][3] - w1 - aqs1*zv + cterm)*mult;
        g_outbuf[ob0 + d0]     = o0;
        g_outbuf[ob0 + d0 + 1] = o1;
        g_outbuf[ob1 + d0]     = o2;
        g_outbuf[ob1 + d0 + 1] = o3;
        lmx = fmaxf(lmx, fmaxf(fmaxf(o0,o1), fmaxf(o2,o3)));
        lmn = fminf(lmn, fminf(fminf(o0,o1), fminf(o2,o3)));
    }
    // fused out-tensor (slot 6) minmax
    redx[tid] = lmx; redn[tid] = lmn; __syncthreads();
    for (int o = 128; o > 0; o >>= 1){
        if (tid < o){ redx[tid] = fmaxf(redx[tid], redx[tid+o]); redn[tid] = fminf(redn[tid], redn[tid+o]); }
        __syncthreads();
    }
    if (tid == 0){
        atomicMax(&g_stat[12], fenc(redx[0]));
        atomicMin(&g_stat[13], fenc(redn[0]));
    }
}

// ---------------- pipelined tensor-core GEMM (A [M][K], B [N][K], both k-contig) ----------------
template<int F1>
__global__ void __launch_bounds__(256) k_mma(
    const bf16* __restrict__ A, int lda,
    const bf16* __restrict__ Bm, int ldb,
    float* __restrict__ C, int ldc,
    int K,
    const float* __restrict__ colsumB,
    const float* __restrict__ rowsumA,
    int slotA, int slotB, float Kconst,
    const float* __restrict__ bias)
{
    const int BK = 32, PAD = 40;
    __shared__ __align__(16) bf16 As[2][128*PAD];
    __shared__ __align__(16) bf16 Bs[2][128*PAD];
    __shared__ float redx[256], redn[256];

    int i0 = blockIdx.y * 128, j0 = blockIdx.x * 128;
    int tid = threadIdx.x, warp = tid >> 5, lane = tid & 31;
    int wm = warp >> 2, wn = warp & 3;
    int l16 = lane & 15;

    float acc[4][4][4];
    #pragma unroll
    for (int a = 0; a < 4; a++)
        #pragma unroll
        for (int b = 0; b < 4; b++){
            acc[a][b][0]=0.f; acc[a][b][1]=0.f; acc[a][b][2]=0.f; acc[a][b][3]=0.f;
        }

    {
        #pragma unroll
        for (int v = 0; v < 2; v++){
            int idx = v*256 + tid;
            int r = idx >> 2, c8 = idx & 3;
            cpa(&As[0][r*PAD + c8*8], &A[(long long)(i0 + r)*lda + c8*8]);
        }
        #pragma unroll
        for (int v = 0; v < 2; v++){
            int idx = v*256 + tid;
            int r = idx >> 2, c8 = idx & 3;
            cpa(&Bs[0][r*PAD + c8*8], &Bm[(long long)(j0 + r)*ldb + c8*8]);
        }
        CP_COMMIT;
    }

    int st = 0;
    for (int k0 = 0; k0 < K; k0 += BK){
        if (k0 + BK < K){
            int ns = st ^ 1, kn = k0 + BK;
            #pragma unroll
            for (int v = 0; v < 2; v++){
                int idx = v*256 + tid;
                int r = idx >> 2, c8 = idx & 3;
                cpa(&As[ns][r*PAD + c8*8], &A[(long long)(i0 + r)*lda + kn + c8*8]);
            }
            #pragma unroll
            for (int v = 0; v < 2; v++){
                int idx = v*256 + tid;
                int r = idx >> 2, c8 = idx & 3;
                cpa(&Bs[ns][r*PAD + c8*8], &Bm[(long long)(j0 + r)*ldb + kn + c8*8]);
            }
            CP_COMMIT;
            CP_WAIT1;
        } else {
            CP_WAIT0;
        }
        __syncthreads();

        #pragma unroll
        for (int kk = 0; kk < BK; kk += 16){
            u32 af[4][4];
            #pragma unroll
            for (int mt = 0; mt < 4; mt++)
                ldsm4(af[mt], &As[st][(wm*64 + mt*16 + l16)*PAD + kk + (lane>>4)*8]);
            u32 bf[4][2];
            #pragma unroll
            for (int nt = 0; nt < 4; nt++)
                ldsm2(bf[nt], &Bs[st][(wn*32 + nt*8 + (l16&7))*PAD + kk + ((l16>>3)&1)*8]);
            #pragma unroll
            for (int mt = 0; mt < 4; mt++)
                #pragma unroll
                for (int nt = 0; nt < 4; nt++)
                    mma16816(acc[mt][nt], af[mt], bf[nt]);
        }
        __syncthreads();
        st ^= 1;
    }

    float sA, zA, iA, sB, zB, iB;
    get_szi(slotA, sA, zA, iA); get_szi(slotB, sB, zB, iB);
    float mult  = sA * sB;
    float cterm = (zA * zB) * Kconst;

    float lmx = -INFINITY, lmn = INFINITY;

    #pragma unroll
    for (int mt = 0; mt < 4; mt++){
        int row0 = i0 + wm*64 + mt*16 + (lane>>2);
        float rs0 = rowsumA[row0], rs1 = rowsumA[row0+8];
        float p0 = 0.f, p8 = 0.f;
        #pragma unroll
        for (int nt = 0; nt < 4; nt++){
            int col0 = j0 + wn*32 + nt*8 + (lane&3)*2;
            float cs0 = colsumB[col0], cs1 = colsumB[col0+1];
            float b0 = bias ? bias[col0]   : 0.f;
            float b1 = bias ? bias[col0+1] : 0.f;
            float v0 = (acc[mt][nt][0] - cs0*zA - rs0*zB + cterm)*mult + b0;
            float v1 = (acc[mt][nt][1] - cs1*zA - rs0*zB + cterm)*mult + b1;
            float v2 = (acc[mt][nt][2] - cs0*zA - rs1*zB + cterm)*mult + b0;
            float v3 = (acc[mt][nt][3] - cs1*zA - rs1*zB + cterm)*mult + b1;
            C[(long long)row0*ldc + col0]       = v0;
            C[(long long)row0*ldc + col0 + 1]   = v1;
            C[(long long)(row0+8)*ldc + col0]   = v2;
            C[(long long)(row0+8)*ldc + col0+1] = v3;
            if (F1){
                p0 += v0 + v1; p8 += v2 + v3;
                lmx = fmaxf(lmx, fmaxf(fmaxf(v0,v1), fmaxf(v2,v3)));
                lmn = fminf(lmn, fminf(fminf(v0,v1), fminf(v2,v3)));
            }
        }
        if (F1){
            p0 = qsum(p0); p8 = qsum(p8);
            if ((lane & 3) == 0){
                atomicAdd(&g_xqkvsum[row0],   p0);
                atomicAdd(&g_xqkvsum[row0+8], p8);
            }
        }
    }

    if (F1){
        redx[tid] = lmx; redn[tid] = lmn; __syncthreads();
        for (int o = 128; o > 0; o >>= 1){
            if (tid < o){ redx[tid] = fmaxf(redx[tid], redx[tid+o]); redn[tid] = fminf(redn[tid], redn[tid+o]); }
            __syncthreads();
        }
        if (tid == 0){
            int region = blockIdx.x / 6;
            atomicMax(&g_stat[2*(2+region)],   fenc(redx[0]));
            atomicMin(&g_stat[2*(2+region)+1], fenc(redn[0]));
        }
    }
}

// ---------------- launcher ----------------
extern "C" void kernel_launch(void* const* d_in, const int* in_sizes, int n_in,
                              void* d_out, int out_size){
    const float *x = 0, *wqkv = 0, *wout = 0, *bout = 0;
    for (int i = 0; i < n_in; i++){
        if      (in_sizes[i] == MROWS*DMODEL)  x    = (const float*)d_in[i];
        else if (in_sizes[i] == J3*DMODEL)     wqkv = (const float*)d_in[i];
        else if (in_sizes[i] == DMODEL*DMODEL) wout = (const float*)d_in[i];
        else if (in_sizes[i] == DMODEL)        bout = (const float*)d_in[i];
    }
    float* out = (float*)d_out;

    bf16 *p_xq, *p_wq1, *p_wq2;
    float *p_xqkv, *p_outbuf;
    float *p_rowsum_x, *p_colsum_w1, *p_colsum_w2, *p_xqkvsum;
    cudaGetSymbolAddress((void**)&p_xq,        g_xq);
    cudaGetSymbolAddress((void**)&p_wq1,       g_wq1);
    cudaGetSymbolAddress((void**)&p_wq2,       g_wq2);
    cudaGetSymbolAddress((void**)&p_xqkv,      g_xqkv);
    cudaGetSymbolAddress((void**)&p_outbuf,    g_outbuf);
    cudaGetSymbolAddress((void**)&p_rowsum_x,  g_rowsum_x);
    cudaGetSymbolAddress((void**)&p_colsum_w1, g_colsum_w1);
    cudaGetSymbolAddress((void**)&p_colsum_w2, g_colsum_w2);
    cudaGetSymbolAddress((void**)&p_xqkvsum,   g_xqkvsum);

    static int smem_set = 0;
    if (!smem_set){
        cudaFuncSetAttribute(k_attn_stats, cudaFuncAttributeMaxDynamicSharedMemorySize, 18432*3 + 2048);
        cudaFuncSetAttribute(k_attn_av,    cudaFuncAttributeMaxDynamicSharedMemorySize, 18432*4 + 2048);
        smem_set = 1;
    }

    k_init<<<1, 256>>>();
    // x, w_qkv, w_out min/max all up-front (w_out is input-only: no dependencies)
    k_minmax3<<<dim3(768, 3), 256>>>(x, MROWS*DMODEL, 0,
                                     wqkv, J3*DMODEL, 1,
                                     wout, DMODEL*DMODEL, 7);
    k_quantrow<<<MROWS/8, 256>>>(x, p_xq, p_rowsum_x, 0);
    k_quantrow<<<J3/8, 256>>>(wqkv, p_wq1, p_colsum_w1, 1);
    k_quantrow<<<DMODEL/8, 256>>>(wout, p_wq2, p_colsum_w2, 7);   // early: off critical path tail
    k_mma<1><<<dim3(J3/128, MROWS/128), 256>>>(
        p_xq, DMODEL, p_wq1, DMODEL, p_xqkv, J3, DMODEL,
        p_colsum_w1, p_rowsum_x, 0, 1, (float)DMODEL, (const float*)0);
    k_pack_qkv<<<dim3(SEQ/8, BHN), 256>>>();
    k_attn_stats<<<dim3(8, BHN), 256, 18432*3 + 2048>>>();
    k_attn_av<<<dim3(8, BHN), 256, 18432*4 + 2048>>>();           // also produces slot-6 minmax
    k_quantrow<<<MROWS/8, 256>>>(p_outbuf, p_xq, p_rowsum_x /*dummy*/, 6);
    k_mma<0><<<dim3(DMODEL/128, MROWS/128), 256>>>(
        p_xq, DMODEL, p_wq2, DMODEL, out, DMODEL, DMODEL,
        p_colsum_w2, p_xqkvsum, 6, 7, (float)J3, bout);
}

// round 11
// speedup vs baseline: 1.6100x; 1.0259x over previous
#include <cuda_runtime.h>
#include <cuda_bf16.h>
#include <cstdint>
#include <cstddef>
#include <math.h>

#define NB      4
#define SEQ     1024
#define DMODEL  768
#define NH      12
#define DHD     64
#define J3      2304
#define MROWS   4096
#define BHN     48

typedef __nv_bfloat16 bf16;
typedef unsigned int  u32;

// ---------------- scratch ----------------
__device__ __align__(16) bf16  g_xq[MROWS*DMODEL];
__device__ __align__(16) bf16  g_wq1[J3*DMODEL];
__device__ __align__(16) bf16  g_wq2[DMODEL*DMODEL];
__device__ __align__(16) float g_xqkv[MROWS*J3];
__device__ __align__(16) bf16  g_qb[BHN*SEQ*DHD];
__device__ __align__(16) bf16  g_kb[BHN*SEQ*DHD];
__device__ __align__(16) bf16  g_vb[BHN*SEQ*DHD];
__device__ __align__(16) float g_outbuf[MROWS*DMODEL];
__device__ float    g_rowsum_x[MROWS];
__device__ float    g_colsum_w1[J3];
__device__ float    g_colsum_w2[DMODEL];
__device__ float    g_xqkvsum[MROWS];
__device__ float    g_rowsumq[BHN*SEQ];
__device__ float    g_colsumk[BHN*SEQ];
__device__ float    g_vcolsum[BHN*DHD];
__device__ float    g_rowm[BHN*SEQ];
__device__ float    g_rowS[BHN*SEQ];
__device__ unsigned g_stat[16];   // slots:0=x 1=w1 2=q 3=k 4=v 5=a 6=out 7=w2

// ---------------- helpers ----------------
__device__ __forceinline__ unsigned fenc(float f){
    unsigned u = __float_as_uint(f);
    return (u & 0x80000000u) ? ~u : (u | 0x80000000u);
}
__device__ __forceinline__ float fdec(unsigned e){
    return (e & 0x80000000u) ? __uint_as_float(e ^ 0x80000000u) : __uint_as_float(~e);
}
__device__ __forceinline__ void get_szi(int slot, float& s, float& z, float& is){
    float mx = fdec(g_stat[2*slot]);
    float mn = fdec(g_stat[2*slot+1]);
    s = __fdiv_rn(mx - mn, 15.0f);
    z = rintf(15.0f - __fdiv_rn(mx, s));
    is = __fdiv_rn(1.0f, s);
}
__device__ __forceinline__ float quantm(float v, float is, float z){
    return rintf(fmaf(v, is, z));
}
__device__ __forceinline__ u32 packbf2(float lo, float hi){
    __nv_bfloat162 t = __floats2bfloat162_rn(lo, hi);
    return *reinterpret_cast<u32*>(&t);
}
__device__ __forceinline__ void ldsm4(u32* r, const void* p){
    u32 a = (u32)__cvta_generic_to_shared(p);
    asm volatile("ldmatrix.sync.aligned.m8n8.x4.shared.b16 {%0,%1,%2,%3},[%4];"
        : "=r"(r[0]),"=r"(r[1]),"=r"(r[2]),"=r"(r[3]) : "r"(a));
}
__device__ __forceinline__ void ldsm4t(u32* r, const void* p){
    u32 a = (u32)__cvta_generic_to_shared(p);
    asm volatile("ldmatrix.sync.aligned.m8n8.x4.trans.shared.b16 {%0,%1,%2,%3},[%4];"
        : "=r"(r[0]),"=r"(r[1]),"=r"(r[2]),"=r"(r[3]) : "r"(a));
}
__device__ __forceinline__ void mma16816(float* c, const u32* a, const u32* b){
    asm volatile("mma.sync.aligned.m16n8k16.row.col.f32.bf16.bf16.f32 "
        "{%0,%1,%2,%3}, {%4,%5,%6,%7}, {%8,%9}, {%0,%1,%2,%3};"
        : "+f"(c[0]),"+f"(c[1]),"+f"(c[2]),"+f"(c[3])
        : "r"(a[0]),"r"(a[1]),"r"(a[2]),"r"(a[3]), "r"(b[0]),"r"(b[1]));
}
__device__ __forceinline__ void cpa(void* s, const void* g){
    u32 a = (u32)__cvta_generic_to_shared(s);
    asm volatile("cp.async.cg.shared.global [%0],[%1],16;" :: "r"(a), "l"(g));
}
#define CP_COMMIT asm volatile("cp.async.commit_group;")
#define CP_WAIT0  asm volatile("cp.async.wait_group 0;")
#define CP_WAIT1  asm volatile("cp.async.wait_group 1;")
#define CP_WAIT2  asm volatile("cp.async.wait_group 2;")

__device__ __forceinline__ float qsum(float v){
    v += __shfl_xor_sync(0xffffffffu, v, 1);
    v += __shfl_xor_sync(0xffffffffu, v, 2);
    return v;
}
__device__ __forceinline__ float qmax(float v){
    v = fmaxf(v, __shfl_xor_sync(0xffffffffu, v, 1));
    v = fmaxf(v, __shfl_xor_sync(0xffffffffu, v, 2));
    return v;
}
__device__ __forceinline__ float qmin(float v){
    v = fminf(v, __shfl_xor_sync(0xffffffffu, v, 1));
    v = fminf(v, __shfl_xor_sync(0xffffffffu, v, 2));
    return v;
}
__device__ __forceinline__ float wsum(float v){
    #pragma unroll
    for (int o = 16; o > 0; o >>= 1) v += __shfl_xor_sync(0xffffffffu, v, o);
    return v;
}

// ---------------- elementwise kernels ----------------
__global__ void k_init(){
    int t = threadIdx.x;
    if (t < 8){ g_stat[2*t] = fenc(-INFINITY); g_stat[2*t+1] = fenc(INFINITY); }
    for (int i = t; i < BHN*DHD; i += blockDim.x) g_vcolsum[i] = 0.f;
    for (int i = t; i < MROWS;   i += blockDim.x) g_xqkvsum[i] = 0.f;
}

__global__ void k_minmax3(const float* __restrict__ pa, int na, int sa_,
                          const float* __restrict__ pb, int nb, int sb_,
                          const float* __restrict__ pc, int nc, int sc_){
    const float* p; int n, slot;
    if (blockIdx.y == 0){ p = pa; n = na; slot = sa_; }
    else if (blockIdx.y == 1){ p = pb; n = nb; slot = sb_; }
    else { p = pc; n = nc; slot = sc_; }
    float mx = -INFINITY, mn = INFINITY;
    int n4 = n >> 2;
    const float4* p4 = (const float4*)p;
    for (int i = blockIdx.x*blockDim.x + threadIdx.x; i < n4; i += gridDim.x*blockDim.x){
        float4 v = p4[i];
        mx = fmaxf(mx, fmaxf(fmaxf(v.x,v.y), fmaxf(v.z,v.w)));
        mn = fminf(mn, fminf(fminf(v.x,v.y), fminf(v.z,v.w)));
    }
    __shared__ float smx[256], smn[256];
    int t = threadIdx.x;
    smx[t] = mx; smn[t] = mn; __syncthreads();
    for (int o = 128; o > 0; o >>= 1){
        if (t < o){ smx[t] = fmaxf(smx[t], smx[t+o]); smn[t] = fminf(smn[t], smn[t+o]); }
        __syncthreads();
    }
    if (t == 0){
        atomicMax(&g_stat[2*slot],   fenc(smx[0]));
        atomicMin(&g_stat[2*slot+1], fenc(smn[0]));
    }
}

// warp-per-row quantize -> bf16 (rowlen 768), fused row sums
__global__ void k_quantrow(const float* __restrict__ src, bf16* __restrict__ dst,
                           float* __restrict__ rowsum, int slot){
    int warp = threadIdx.x >> 5, lane = threadIdx.x & 31;
    int r = blockIdx.x*8 + warp;
    float s, z, is; get_szi(slot, s, z, is);
    const float4* s4 = (const float4*)(src + (long long)r*DMODEL);
    uint2* d2 = (uint2*)(dst + (long long)r*DMODEL);
    float acc = 0.f;
    #pragma unroll
    for (int i = 0; i < 6; i++){
        float4 v = s4[i*32 + lane];
        float q0 = quantm(v.x, is, z), q1 = quantm(v.y, is, z);
        float q2 = quantm(v.z, is, z), q3 = quantm(v.w, is, z);
        acc += (q0+q1) + (q2+q3);
        uint2 o; o.x = packbf2(q0,q1); o.y = packbf2(q2,q3);
        d2[i*32 + lane] = o;
    }
    acc = wsum(acc);
    if (lane == 0) rowsum[r] = acc;
}

// warp-per-token pack of quantized q/k/v; fused token sums + v colsum
__global__ void k_pack_qkv(){
    __shared__ float vsum[64];
    int bh = blockIdx.y;
    int b = bh / NH, h = bh - b*NH;
    int warp = threadIdx.x >> 5, lane = threadIdx.x & 31;
    int n = blockIdx.x*8 + warp;
    if (threadIdx.x < 64) vsum[threadIdx.x] = 0.f;
    __syncthreads();
    float sq, zq, iq, sk, zk, ik, sv, zv, iv;
    get_szi(2, sq, zq, iq); get_szi(3, sk, zk, ik); get_szi(4, sv, zv, iv);
    long long base = (long long)(b*SEQ + n)*J3 + h*DHD + 2*lane;
    float2 qv2 = *(const float2*)&g_xqkv[base];
    float2 kv2 = *(const float2*)&g_xqkv[base + DMODEL];
    float2 vv2 = *(const float2*)&g_xqkv[base + 2*DMODEL];
    float q0 = quantm(qv2.x, iq, zq), q1 = quantm(qv2.y, iq, zq);
    float k0 = quantm(kv2.x, ik, zk), k1 = quantm(kv2.y, ik, zk);
    float v0 = quantm(vv2.x, iv, zv), v1 = quantm(vv2.y, iv, zv);
    long long po = ((long long)bh*SEQ + n)*DHD/2 + lane;
    ((u32*)g_qb)[po] = packbf2(q0, q1);
    ((u32*)g_kb)[po] = packbf2(k0, k1);
    ((u32*)g_vb)[po] = packbf2(v0, v1);
    float qs = wsum(q0 + q1);
    float ks = wsum(k0 + k1);
    if (lane == 0){
        g_rowsumq[bh*SEQ + n] = qs;
        g_colsumk[bh*SEQ + n] = ks;
    }
    atomicAdd(&vsum[2*lane],   v0);
    atomicAdd(&vsum[2*lane+1], v1);
    __syncthreads();
    if (threadIdx.x < 64) atomicAdd(&g_vcolsum[bh*DHD + threadIdx.x], vsum[threadIdx.x]);
}

// ---------------- fused attention: stats pass ----------------
__global__ void __launch_bounds__(256) k_attn_stats(){
    extern __shared__ __align__(16) char smraw[];
    bf16* Qs  = (bf16*)smraw;
    bf16* Ks0 = (bf16*)(smraw + 18432);
    bf16* Ks1 = (bf16*)(smraw + 18432*2);
    float* csk0 = (float*)(smraw + 18432*3);
    float* csk1 = (float*)(smraw + 18432*3 + 512);
    __shared__ float redx[256], redn[256];

    int bh = blockIdx.y, qt = blockIdx.x;
    int tid = threadIdx.x, warp = tid >> 5, lane = tid & 31;
    int l16 = lane & 15;
    // x4 B-frag addressing (non-trans): row offset within n16 group, col offset
    int brow = (lane&7) + ((lane>>4)<<3);
    int bcol = ((lane>>3)&1)*8;

    float sq, zq, iq, sk, zk, ik;
    get_szi(2, sq, zq, iq); get_szi(3, sk, zk, ik);
    float s3 = (0.125f * sq) * sk;

    {
        #pragma unroll
        for (int it = 0; it < 4; it++){
            int idx = it*256 + tid;
            int r = idx >> 3, c8 = idx & 7;
            cpa(&Ks0[r*72 + c8*8], &g_kb[((long long)bh*SEQ + r)*DHD + c8*8]);
        }
        if (tid < 32) cpa(&csk0[tid*4], &g_colsumk[bh*SEQ + tid*4]);
        CP_COMMIT;
        #pragma unroll
        for (int it = 0; it < 4; it++){
            int idx = it*256 + tid;
            int r = idx >> 3, c8 = idx & 7;
            cpa(&Qs[r*72 + c8*8], &g_qb[((long long)bh*SEQ + qt*128 + r)*DHD + c8*8]);
        }
        CP_COMMIT;
    }

    int r0 = warp*16 + (lane>>2), r1 = r0 + 8;
    float rsq0 = g_rowsumq[bh*SEQ + qt*128 + r0];
    float rsq1 = g_rowsumq[bh*SEQ + qt*128 + r1];

    float m0 = -INFINITY, m1 = -INFINITY;
    float n0 =  INFINITY, n1 =  INFINITY;
    float S0 = 0.f, S1 = 0.f;

    int st = 0;
    for (int kt = 0; kt < 8; kt++){
        bf16*  Kc  = st ? Ks1 : Ks0;
        float* ckc = st ? csk1 : csk0;
        if (kt < 7){
            bf16*  Kn  = st ? Ks0 : Ks1;
            float* ckn = st ? csk0 : csk1;
            #pragma unroll
            for (int it = 0; it < 4; it++){
                int idx = it*256 + tid;
                int r = idx >> 3, c8 = idx & 7;
                cpa(&Kn[r*72 + c8*8], &g_kb[((long long)bh*SEQ + (kt+1)*128 + r)*DHD + c8*8]);
            }
            if (tid < 32) cpa(&ckn[tid*4], &g_colsumk[bh*SEQ + (kt+1)*128 + tid*4]);
            CP_COMMIT;
            CP_WAIT1;
        } else {
            CP_WAIT0;
        }
        __syncthreads();

        float acc[16][4];
        #pragma unroll
        for (int nt = 0; nt < 16; nt++){ acc[nt][0]=0.f; acc[nt][1]=0.f; acc[nt][2]=0.f; acc[nt][3]=0.f; }
        #pragma unroll
        for (int kk = 0; kk < 64; kk += 16){
            u32 af[4];
            ldsm4(af, &Qs[(warp*16 + l16)*72 + kk + (lane>>4)*8]);
            #pragma unroll
            for (int np = 0; np < 8; np++){
                u32 bq[4];
                ldsm4(bq, &Kc[(np*16 + brow)*72 + kk + bcol]);
                mma16816(acc[2*np],   af, bq);
                mma16816(acc[2*np+1], af, bq+2);
            }
        }

        int c = (lane&3)*2;
        #pragma unroll
        for (int nt = 0; nt < 16; nt++){
            int cg = nt*8 + c;
            float cz0 = ckc[cg]*zq, cz1 = ckc[cg+1]*zq;
            acc[nt][0] = (acc[nt][0] - cz0 - rsq0*zk)*s3;
            acc[nt][1] = (acc[nt][1] - cz1 - rsq0*zk)*s3;
            acc[nt][2] = (acc[nt][2] - cz0 - rsq1*zk)*s3;
            acc[nt][3] = (acc[nt][3] - cz1 - rsq1*zk)*s3;
        }
        float tx0=-INFINITY, tx1=-INFINITY, tn0=INFINITY, tn1=INFINITY;
        #pragma unroll
        for (int nt = 0; nt < 16; nt++){
            tx0 = fmaxf(tx0, fmaxf(acc[nt][0], acc[nt][1]));
            tx1 = fmaxf(tx1, fmaxf(acc[nt][2], acc[nt][3]));
            tn0 = fminf(tn0, fminf(acc[nt][0], acc[nt][1]));
            tn1 = fminf(tn1, fminf(acc[nt][2], acc[nt][3]));
        }
        tx0 = qmax(tx0); tx1 = qmax(tx1);
        tn0 = qmin(tn0); tn1 = qmin(tn1);
        float nm0 = fmaxf(m0, tx0), nm1 = fmaxf(m1, tx1);
        float se0 = 0.f, se1 = 0.f;
        #pragma unroll
        for (int nt = 0; nt < 16; nt++){
            se0 += __expf(acc[nt][0]-nm0) + __expf(acc[nt][1]-nm0);
            se1 += __expf(acc[nt][2]-nm1) + __expf(acc[nt][3]-nm1);
        }
        se0 = qsum(se0); se1 = qsum(se1);
        S0 = S0*__expf(m0-nm0) + se0;  m0 = nm0;  n0 = fminf(n0, tn0);
        S1 = S1*__expf(m1-nm1) + se1;  m1 = nm1;  n1 = fminf(n1, tn1);

        __syncthreads();
        st ^= 1;
    }

    if ((lane & 3) == 0){
        g_rowm[bh*SEQ + qt*128 + r0] = m0;  g_rowS[bh*SEQ + qt*128 + r0] = S0;
        g_rowm[bh*SEQ + qt*128 + r1] = m1;  g_rowS[bh*SEQ + qt*128 + r1] = S1;
    }
    float i0 = __fdiv_rn(1.0f, S0), i1 = __fdiv_rn(1.0f, S1);
    float ax = fmaxf(i0, i1);
    float an = fminf(__expf(n0 - m0)*i0, __expf(n1 - m1)*i1);
    redx[tid] = ax; redn[tid] = an; __syncthreads();
    for (int o = 128; o > 0; o >>= 1){
        if (tid < o){ redx[tid] = fmaxf(redx[tid], redx[tid+o]); redn[tid] = fminf(redn[tid], redn[tid+o]); }
        __syncthreads();
    }
    if (tid == 0){
        atomicMax(&g_stat[10], fenc(redx[0]));
        atomicMin(&g_stat[11], fenc(redn[0]));
    }
}

// ---------------- fused attention: recompute + quantize + AV (+out minmax) ----------------
__global__ void __launch_bounds__(256) k_attn_av(){
    extern __shared__ __align__(16) char smraw[];
    bf16* Qs  = (bf16*)smraw;
    bf16* Ks0 = (bf16*)(smraw + 18432);
    bf16* Ks1 = (bf16*)(smraw + 18432*2);
    bf16* Vs  = (bf16*)(smraw + 18432*3);
    float* csk0 = (float*)(smraw + 18432*4);
    float* csk1 = (float*)(smraw + 18432*4 + 512);
    float* vcs  = (float*)(smraw + 18432*4 + 1024);
    __shared__ float redx[256], redn[256];

    int bh = blockIdx.y, qt = blockIdx.x;
    int b = bh / NH, h = bh - b*NH;
    int tid = threadIdx.x, warp = tid >> 5, lane = tid & 31;
    int l16 = lane & 15;
    int brow = (lane&7) + ((lane>>4)<<3);
    int bcol = ((lane>>3)&1)*8;
    // trans x4 V addressing: row within k16 group, col selects n8 pair member
    int vrow = (lane&7) + (((lane>>3)&1)<<3);
    int vsel = (lane>>4);   // 0 or 1 -> n8 group

    float sq, zq, iq, sk, zk, ik, sv, zv, iv, sa, za, ia;
    get_szi(2, sq, zq, iq); get_szi(3, sk, zk, ik);
    get_szi(4, sv, zv, iv); get_szi(5, sa, za, ia);
    float s3 = (0.125f * sq) * sk;

    {
        #pragma unroll
        for (int it = 0; it < 4; it++){
            int idx = it*256 + tid;
            int r = idx >> 3, c8 = idx & 7;
            cpa(&Ks0[r*72 + c8*8], &g_kb[((long long)bh*SEQ + r)*DHD + c8*8]);
        }
        if (tid < 32) cpa(&csk0[tid*4], &g_colsumk[bh*SEQ + tid*4]);
        CP_COMMIT;
        #pragma unroll
        for (int it = 0; it < 4; it++){
            int idx = it*256 + tid;
            int r = idx >> 3, c8 = idx & 7;
            cpa(&Qs[r*72 + c8*8], &g_qb[((long long)bh*SEQ + qt*128 + r)*DHD + c8*8]);
        }
        if (tid < 16) cpa(&vcs[tid*4], &g_vcolsum[bh*DHD + tid*4]);
        CP_COMMIT;
    }

    int r0 = warp*16 + (lane>>2), r1 = r0 + 8;
    float rsq0 = g_rowsumq[bh*SEQ + qt*128 + r0];
    float rsq1 = g_rowsumq[bh*SEQ + qt*128 + r1];
    float m0 = g_rowm[bh*SEQ + qt*128 + r0], S0 = g_rowS[bh*SEQ + qt*128 + r0];
    float m1 = g_rowm[bh*SEQ + qt*128 + r1], S1 = g_rowS[bh*SEQ + qt*128 + r1];
    float coef0 = __fdiv_rn(1.0f, S0) * ia;
    float coef1 = __fdiv_rn(1.0f, S1) * ia;

    float oacc[8][4];
    #pragma unroll
    for (int nt = 0; nt < 8; nt++){ oacc[nt][0]=0.f; oacc[nt][1]=0.f; oacc[nt][2]=0.f; oacc[nt][3]=0.f; }
    float aqs0 = 0.f, aqs1 = 0.f;

    int st = 0;
    for (int kt = 0; kt < 8; kt++){
        bf16*  Kc  = st ? Ks1 : Ks0;
        float* ckc = st ? csk1 : csk0;
        if (kt < 7){
            bf16*  Kn  = st ? Ks0 : Ks1;
            float* ckn = st ? csk0 : csk1;
            #pragma unroll
            for (int it = 0; it < 4; it++){
                int idx = it*256 + tid;
                int r = idx >> 3, c8 = idx & 7;
                cpa(&Kn[r*72 + c8*8], &g_kb[((long long)bh*SEQ + (kt+1)*128 + r)*DHD + c8*8]);
            }
            if (tid < 32) cpa(&ckn[tid*4], &g_colsumk[bh*SEQ + (kt+1)*128 + tid*4]);
            CP_COMMIT;
        }
        #pragma unroll
        for (int it = 0; it < 4; it++){
            int idx = it*256 + tid;
            int r = idx >> 3, c8 = idx & 7;
            cpa(&Vs[r*72 + c8*8], &g_vb[((long long)bh*SEQ + kt*128 + r)*DHD + c8*8]);
        }
        CP_COMMIT;
        if (kt < 7) { CP_WAIT2; } else { CP_WAIT1; }
        __syncthreads();

        float acc[16][4];
        #pragma unroll
        for (int nt = 0; nt < 16; nt++){ acc[nt][0]=0.f; acc[nt][1]=0.f; acc[nt][2]=0.f; acc[nt][3]=0.f; }
        #pragma unroll
        for (int kk = 0; kk < 64; kk += 16){
            u32 af[4];
            ldsm4(af, &Qs[(warp*16 + l16)*72 + kk + (lane>>4)*8]);
            #pragma unroll
            for (int np = 0; np < 8; np++){
                u32 bq[4];
                ldsm4(bq, &Kc[(np*16 + brow)*72 + kk + bcol]);
                mma16816(acc[2*np],   af, bq);
                mma16816(acc[2*np+1], af, bq+2);
            }
        }

        int c = (lane&3)*2;
        #pragma unroll
        for (int nt = 0; nt < 16; nt++){
            int cg = nt*8 + c;
            float cz0 = ckc[cg]*zq, cz1 = ckc[cg+1]*zq;
            acc[nt][0] = (acc[nt][0] - cz0 - rsq0*zk)*s3;
            acc[nt][1] = (acc[nt][1] - cz1 - rsq0*zk)*s3;
            acc[nt][2] = (acc[nt][2] - cz0 - rsq1*zk)*s3;
            acc[nt][3] = (acc[nt][3] - cz1 - rsq1*zk)*s3;
        }

        if (kt < 7) { CP_WAIT1; } else { CP_WAIT0; }
        __syncthreads();

        #pragma unroll
        for (int j = 0; j < 8; j++){
            float q00 = rintf(fmaf(__expf(acc[2*j][0]   - m0), coef0, za));
            float q01 = rintf(fmaf(__expf(acc[2*j][1]   - m0), coef0, za));
            float q02 = rintf(fmaf(__expf(acc[2*j][2]   - m1), coef1, za));
            float q03 = rintf(fmaf(__expf(acc[2*j][3]   - m1), coef1, za));
            float q10 = rintf(fmaf(__expf(acc[2*j+1][0] - m0), coef0, za));
            float q11 = rintf(fmaf(__expf(acc[2*j+1][1] - m0), coef0, za));
            float q12 = rintf(fmaf(__expf(acc[2*j+1][2] - m1), coef1, za));
            float q13 = rintf(fmaf(__expf(acc[2*j+1][3] - m1), coef1, za));
            aqs0 += q00 + q01 + q10 + q11;
            aqs1 += q02 + q03 + q12 + q13;
            u32 pa[4];
            pa[0] = packbf2(q00, q01);
            pa[1] = packbf2(q02, q03);
            pa[2] = packbf2(q10, q11);
            pa[3] = packbf2(q12, q13);
            #pragma unroll
            for (int np = 0; np < 4; np++){
                u32 vf[4];
                ldsm4t(vf, &Vs[(16*j + vrow)*72 + (2*np + vsel)*8]);
                mma16816(oacc[2*np],   pa, vf);
                mma16816(oacc[2*np+1], pa, vf+2);
            }
        }
        __syncthreads();
        st ^= 1;
    }

    aqs0 = qsum(aqs0);
    aqs1 = qsum(aqs1);

    float mult  = sa * sv;
    float cterm = (za * zv) * (float)SEQ;
    int c = (lane&3)*2;
    long long ob0 = (long long)(b*SEQ + qt*128 + r0)*DMODEL + h*DHD;
    long long ob1 = (long long)(b*SEQ + qt*128 + r1)*DMODEL + h*DHD;
    float lmx = -INFINITY, lmn = INFINITY;
    #pragma unroll
    for (int nt = 0; nt < 8; nt++){
        int d0 = nt*8 + c;
        float w0 = vcs[d0]*za, w1 = vcs[d0+1]*za;
        float o0 = (oacc[nt][0] - w0 - aqs0*zv + cterm)*mult;
        float o1 = (oacc[nt][1] - w1 - aqs0*zv + cterm)*mult;
        float o2 = (oacc[nt][2] - w0 - aqs1*zv + cterm)*mult;
        float o3 = (oacc[nt][3] - w1 - aqs1*zv + cterm)*mult;
        g_outbuf[ob0 + d0]     = o0;
        g_outbuf[ob0 + d0 + 1] = o1;
        g_outbuf[ob1 + d0]     = o2;
        g_outbuf[ob1 + d0 + 1] = o3;
        lmx = fmaxf(lmx, fmaxf(fmaxf(o0,o1), fmaxf(o2,o3)));
        lmn = fminf(lmn, fminf(fminf(o0,o1), fminf(o2,o3)));
    }
    redx[tid] = lmx; redn[tid] = lmn; __syncthreads();
    for (int o = 128; o > 0; o >>= 1){
        if (tid < o){ redx[tid] = fmaxf(redx[tid], redx[tid+o]); redn[tid] = fminf(redn[tid], redn[tid+o]); }
        __syncthreads();
    }
    if (tid == 0){
        atomicMax(&g_stat[12], fenc(redx[0]));
        atomicMin(&g_stat[13], fenc(redn[0]));
    }
}

// ---------------- pipelined tensor-core GEMM (A [M][K], B [N][K], both k-contig) ----------------
template<int F1>
__global__ void __launch_bounds__(256) k_mma(
    const bf16* __restrict__ A, int lda,
    const bf16* __restrict__ Bm, int ldb,
    float* __restrict__ C, int ldc,
    int K,
    const float* __restrict__ colsumB,
    const float* __restrict__ rowsumA,
    int slotA, int slotB, float Kconst,
    const float* __restrict__ bias)
{
    const int BK = 32, PAD = 40;
    __shared__ __align__(16) bf16 As[2][128*PAD];
    __shared__ __align__(16) bf16 Bs[2][128*PAD];
    __shared__ float redx[256], redn[256];

    int i0 = blockIdx.y * 128, j0 = blockIdx.x * 128;
    int tid = threadIdx.x, warp = tid >> 5, lane = tid & 31;
    int wm = warp >> 2, wn = warp & 3;
    int l16 = lane & 15;
    int brow = (lane&7) + ((lane>>4)<<3);
    int bcol = ((lane>>3)&1)*8;

    float acc[4][4][4];
    #pragma unroll
    for (int a = 0; a < 4; a++)
        #pragma unroll
        for (int b = 0; b < 4; b++){
            acc[a][b][0]=0.f; acc[a][b][1]=0.f; acc[a][b][2]=0.f; acc[a][b][3]=0.f;
        }

    {
        #pragma unroll
        for (int v = 0; v < 2; v++){
            int idx = v*256 + tid;
            int r = idx >> 2, c8 = idx & 3;
            cpa(&As[0][r*PAD + c8*8], &A[(long long)(i0 + r)*lda + c8*8]);
        }
        #pragma unroll
        for (int v = 0; v < 2; v++){
            int idx = v*256 + tid;
            int r = idx >> 2, c8 = idx & 3;
            cpa(&Bs[0][r*PAD + c8*8], &Bm[(long long)(j0 + r)*ldb + c8*8]);
        }
        CP_COMMIT;
    }

    int st = 0;
    for (int k0 = 0; k0 < K; k0 += BK){
        if (k0 + BK < K){
            int ns = st ^ 1, kn = k0 + BK;
            #pragma unroll
            for (int v = 0; v < 2; v++){
                int idx = v*256 + tid;
                int r = idx >> 2, c8 = idx & 3;
                cpa(&As[ns][r*PAD + c8*8], &A[(long long)(i0 + r)*lda + kn + c8*8]);
            }
            #pragma unroll
            for (int v = 0; v < 2; v++){
                int idx = v*256 + tid;
                int r = idx >> 2, c8 = idx & 3;
                cpa(&Bs[ns][r*PAD + c8*8], &Bm[(long long)(j0 + r)*ldb + kn + c8*8]);
            }
            CP_COMMIT;
            CP_WAIT1;
        } else {
            CP_WAIT0;
        }
        __syncthreads();

        #pragma unroll
        for (int kk = 0; kk < BK; kk += 16){
            u32 af[4][4];
            #pragma unroll
            for (int mt = 0; mt < 4; mt++)
                ldsm4(af[mt], &As[st][(wm*64 + mt*16 + l16)*PAD + kk + (lane>>4)*8]);
            u32 bq[2][4];
            #pragma unroll
            for (int np = 0; np < 2; np++)
                ldsm4(bq[np], &Bs[st][(wn*32 + np*16 + brow)*PAD + kk + bcol]);
            #pragma unroll
            for (int mt = 0; mt < 4; mt++){
                mma16816(acc[mt][0], af[mt], bq[0]);
                mma16816(acc[mt][1], af[mt], bq[0]+2);
                mma16816(acc[mt][2], af[mt], bq[1]);
                mma16816(acc[mt][3], af[mt], bq[1]+2);
            }
        }
        __syncthreads();
        st ^= 1;
    }

    float sA, zA, iA, sB, zB, iB;
    get_szi(slotA, sA, zA, iA); get_szi(slotB, sB, zB, iB);
    float mult  = sA * sB;
    float cterm = (zA * zB) * Kconst;

    float lmx = -INFINITY, lmn = INFINITY;

    #pragma unroll
    for (int mt = 0; mt < 4; mt++){
        int row0 = i0 + wm*64 + mt*16 + (lane>>2);
        float rs0 = rowsumA[row0], rs1 = rowsumA[row0+8];
        float p0 = 0.f, p8 = 0.f;
        #pragma unroll
        for (int nt = 0; nt < 4; nt++){
            int col0 = j0 + wn*32 + nt*8 + (lane&3)*2;
            float cs0 = colsumB[col0], cs1 = colsumB[col0+1];
            float b0 = bias ? bias[col0]   : 0.f;
            float b1 = bias ? bias[col0+1] : 0.f;
            float v0 = (acc[mt][nt][0] - cs0*zA - rs0*zB + cterm)*mult + b0;
            float v1 = (acc[mt][nt][1] - cs1*zA - rs0*zB + cterm)*mult + b1;
            float v2 = (acc[mt][nt][2] - cs0*zA - rs1*zB + cterm)*mult + b0;
            float v3 = (acc[mt][nt][3] - cs1*zA - rs1*zB + cterm)*mult + b1;
            C[(long long)row0*ldc + col0]       = v0;
            C[(long long)row0*ldc + col0 + 1]   = v1;
            C[(long long)(row0+8)*ldc + col0]   = v2;
            C[(long long)(row0+8)*ldc + col0+1] = v3;
            if (F1){
                p0 += v0 + v1; p8 += v2 + v3;
                lmx = fmaxf(lmx, fmaxf(fmaxf(v0,v1), fmaxf(v2,v3)));
                lmn = fminf(lmn, fminf(fminf(v0,v1), fminf(v2,v3)));
            }
        }
        if (F1){
            p0 = qsum(p0); p8 = qsum(p8);
            if ((lane & 3) == 0){
                atomicAdd(&g_xqkvsum[row0],   p0);
                atomicAdd(&g_xqkvsum[row0+8], p8);
            }
        }
    }

    if (F1){
        redx[tid] = lmx; redn[tid] = lmn; __syncthreads();
        for (int o = 128; o > 0; o >>= 1){
            if (tid < o){ redx[tid] = fmaxf(redx[tid], redx[tid+o]); redn[tid] = fminf(redn[tid], redn[tid+o]); }
            __syncthreads();
        }
        if (tid == 0){
            int region = blockIdx.x / 6;
            atomicMax(&g_stat[2*(2+region)],   fenc(redx[0]));
            atomicMin(&g_stat[2*(2+region)+1], fenc(redn[0]));
        }
    }
}

// ---------------- launcher ----------------
extern "C" void kernel_launch(void* const* d_in, const int* in_sizes, int n_in,
                              void* d_out, int out_size){
    const float *x = 0, *wqkv = 0, *wout = 0, *bout = 0;
    for (int i = 0; i < n_in; i++){
        if      (in_sizes[i] == MROWS*DMODEL)  x    = (const float*)d_in[i];
        else if (in_sizes[i] == J3*DMODEL)     wqkv = (const float*)d_in[i];
        else if (in_sizes[i] == DMODEL*DMODEL) wout = (const float*)d_in[i];
        else if (in_sizes[i] == DMODEL)        bout = (const float*)d_in[i];
    }
    float* out = (float*)d_out;

    bf16 *p_xq, *p_wq1, *p_wq2;
    float *p_xqkv, *p_outbuf;
    float *p_rowsum_x, *p_colsum_w1, *p_colsum_w2, *p_xqkvsum;
    cudaGetSymbolAddress((void**)&p_xq,        g_xq);
    cudaGetSymbolAddress((void**)&p_wq1,       g_wq1);
    cudaGetSymbolAddress((void**)&p_wq2,       g_wq2);
    cudaGetSymbolAddress((void**)&p_xqkv,      g_xqkv);
    cudaGetSymbolAddress((void**)&p_outbuf,    g_outbuf);
    cudaGetSymbolAddress((void**)&p_rowsum_x,  g_rowsum_x);
    cudaGetSymbolAddress((void**)&p_colsum_w1, g_colsum_w1);
    cudaGetSymbolAddress((void**)&p_colsum_w2, g_colsum_w2);
    cudaGetSymbolAddress((void**)&p_xqkvsum,   g_xqkvsum);

    static int smem_set = 0;
    if (!smem_set){
        cudaFuncSetAttribute(k_attn_stats, cudaFuncAttributeMaxDynamicSharedMemorySize, 18432*3 + 2048);
        cudaFuncSetAttribute(k_attn_av,    cudaFuncAttributeMaxDynamicSharedMemorySize, 18432*4 + 2048);
        smem_set = 1;
    }

    k_init<<<1, 256>>>();
    k_minmax3<<<dim3(768, 3), 256>>>(x, MROWS*DMODEL, 0,
                                     wqkv, J3*DMODEL, 1,
                                     wout, DMODEL*DMODEL, 7);
    k_quantrow<<<MROWS/8, 256>>>(x, p_xq, p_rowsum_x, 0);
    k_quantrow<<<J3/8, 256>>>(wqkv, p_wq1, p_colsum_w1, 1);
    k_quantrow<<<DMODEL/8, 256>>>(wout, p_wq2, p_colsum_w2, 7);
    k_mma<1><<<dim3(J3/128, MROWS/128), 256>>>(
        p_xq, DMODEL, p_wq1, DMODEL, p_xqkv, J3, DMODEL,
        p_colsum_w1, p_rowsum_x, 0, 1, (float)DMODEL, (const float*)0);
    k_pack_qkv<<<dim3(SEQ/8, BHN), 256>>>();
    k_attn_stats<<<dim3(8, BHN), 256, 18432*3 + 2048>>>();
    k_attn_av<<<dim3(8, BHN), 256, 18432*4 + 2048>>>();
    k_quantrow<<<MROWS/8, 256>>>(p_outbuf, p_xq, p_rowsum_x /*dummy*/, 6);
    k_mma<0><<<dim3(DMODEL/128, MROWS/128), 256>>>(
        p_xq, DMODEL, p_wq2, DMODEL, out, DMODEL, DMODEL,
        p_colsum_w2, p_xqkvsum, 6, 7, (float)J3, bout);
}

// round 12
// speedup vs baseline: 1.6533x; 1.0269x over previous
#include <cuda_runtime.h>
#include <cuda_bf16.h>
#include <cstdint>
#include <cstddef>
#include <math.h>

#define NB      4
#define SEQ     1024
#define DMODEL  768
#define NH      12
#define DHD     64
#define J3      2304
#define MROWS   4096
#define BHN     48

typedef __nv_bfloat16 bf16;
typedef unsigned int  u32;

// ---------------- scratch ----------------
__device__ __align__(16) bf16  g_xq[MROWS*DMODEL];
__device__ __align__(16) bf16  g_wq1[J3*DMODEL];
__device__ __align__(16) bf16  g_wq2[DMODEL*DMODEL];
__device__ __align__(16) float g_xqkv[MROWS*J3];
__device__ __align__(16) bf16  g_qb[BHN*SEQ*DHD];
__device__ __align__(16) bf16  g_kb[BHN*SEQ*DHD];
__device__ __align__(16) bf16  g_vb[BHN*SEQ*DHD];
__device__ __align__(16) float g_outbuf[MROWS*DMODEL];
__device__ float    g_rowsum_x[MROWS];
__device__ float    g_colsum_w1[J3];
__device__ float    g_colsum_w2[DMODEL];
__device__ float    g_xqkvsum[MROWS];
__device__ float    g_rowsumq[BHN*SEQ];
__device__ float    g_colsumk[BHN*SEQ];
__device__ float    g_vcolsum[BHN*DHD];
__device__ float    g_rowm[BHN*SEQ];
__device__ float    g_rowS[BHN*SEQ];
__device__ unsigned g_stat[16];   // slots:0=x 1=w1 2=q 3=k 4=v 5=a 6=out 7=w2

// ---------------- helpers ----------------
__device__ __forceinline__ unsigned fenc(float f){
    unsigned u = __float_as_uint(f);
    return (u & 0x80000000u) ? ~u : (u | 0x80000000u);
}
__device__ __forceinline__ float fdec(unsigned e){
    return (e & 0x80000000u) ? __uint_as_float(e ^ 0x80000000u) : __uint_as_float(~e);
}
__device__ __forceinline__ void get_szi(int slot, float& s, float& z, float& is){
    float mx = fdec(g_stat[2*slot]);
    float mn = fdec(g_stat[2*slot+1]);
    s = __fdiv_rn(mx - mn, 15.0f);
    z = rintf(15.0f - __fdiv_rn(mx, s));
    is = __fdiv_rn(1.0f, s);
}
__device__ __forceinline__ float quantm(float v, float is, float z){
    return rintf(fmaf(v, is, z));
}
__device__ __forceinline__ u32 packbf2(float lo, float hi){
    __nv_bfloat162 t = __floats2bfloat162_rn(lo, hi);
    return *reinterpret_cast<u32*>(&t);
}
__device__ __forceinline__ void ldsm4(u32* r, const void* p){
    u32 a = (u32)__cvta_generic_to_shared(p);
    asm volatile("ldmatrix.sync.aligned.m8n8.x4.shared.b16 {%0,%1,%2,%3},[%4];"
        : "=r"(r[0]),"=r"(r[1]),"=r"(r[2]),"=r"(r[3]) : "r"(a));
}
__device__ __forceinline__ void ldsm4t(u32* r, const void* p){
    u32 a = (u32)__cvta_generic_to_shared(p);
    asm volatile("ldmatrix.sync.aligned.m8n8.x4.trans.shared.b16 {%0,%1,%2,%3},[%4];"
        : "=r"(r[0]),"=r"(r[1]),"=r"(r[2]),"=r"(r[3]) : "r"(a));
}
__device__ __forceinline__ void mma16816(float* c, const u32* a, const u32* b){
    asm volatile("mma.sync.aligned.m16n8k16.row.col.f32.bf16.bf16.f32 "
        "{%0,%1,%2,%3}, {%4,%5,%6,%7}, {%8,%9}, {%0,%1,%2,%3};"
        : "+f"(c[0]),"+f"(c[1]),"+f"(c[2]),"+f"(c[3])
        : "r"(a[0]),"r"(a[1]),"r"(a[2]),"r"(a[3]), "r"(b[0]),"r"(b[1]));
}
__device__ __forceinline__ void cpa(void* s, const void* g){
    u32 a = (u32)__cvta_generic_to_shared(s);
    asm volatile("cp.async.cg.shared.global [%0],[%1],16;" :: "r"(a), "l"(g));
}
#define CP_COMMIT asm volatile("cp.async.commit_group;")
#define CP_WAIT0  asm volatile("cp.async.wait_group 0;")
#define CP_WAIT1  asm volatile("cp.async.wait_group 1;")
#define CP_WAIT2  asm volatile("cp.async.wait_group 2;")

__device__ __forceinline__ float qsum(float v){
    v += __shfl_xor_sync(0xffffffffu, v, 1);
    v += __shfl_xor_sync(0xffffffffu, v, 2);
    return v;
}
__device__ __forceinline__ float qmax(float v){
    v = fmaxf(v, __shfl_xor_sync(0xffffffffu, v, 1));
    v = fmaxf(v, __shfl_xor_sync(0xffffffffu, v, 2));
    return v;
}
__device__ __forceinline__ float qmin(float v){
    v = fminf(v, __shfl_xor_sync(0xffffffffu, v, 1));
    v = fminf(v, __shfl_xor_sync(0xffffffffu, v, 2));
    return v;
}
__device__ __forceinline__ float wsum(float v){
    #pragma unroll
    for (int o = 16; o > 0; o >>= 1) v += __shfl_xor_sync(0xffffffffu, v, o);
    return v;
}

// ---------------- elementwise kernels ----------------
__global__ void k_init(){
    int t = threadIdx.x;
    if (t < 8){ g_stat[2*t] = fenc(-INFINITY); g_stat[2*t+1] = fenc(INFINITY); }
    for (int i = t; i < BHN*DHD; i += blockDim.x) g_vcolsum[i] = 0.f;
    for (int i = t; i < MROWS;   i += blockDim.x) g_xqkvsum[i] = 0.f;
}

__global__ void k_minmax3(const float* __restrict__ pa, int na, int sa_,
                          const float* __restrict__ pb, int nb, int sb_,
                          const float* __restrict__ pc, int nc, int sc_){
    const float* p; int n, slot;
    if (blockIdx.y == 0){ p = pa; n = na; slot = sa_; }
    else if (blockIdx.y == 1){ p = pb; n = nb; slot = sb_; }
    else { p = pc; n = nc; slot = sc_; }
    float mx = -INFINITY, mn = INFINITY;
    int n4 = n >> 2;
    const float4* p4 = (const float4*)p;
    for (int i = blockIdx.x*blockDim.x + threadIdx.x; i < n4; i += gridDim.x*blockDim.x){
        float4 v = p4[i];
        mx = fmaxf(mx, fmaxf(fmaxf(v.x,v.y), fmaxf(v.z,v.w)));
        mn = fminf(mn, fminf(fminf(v.x,v.y), fminf(v.z,v.w)));
    }
    __shared__ float smx[256], smn[256];
    int t = threadIdx.x;
    smx[t] = mx; smn[t] = mn; __syncthreads();
    for (int o = 128; o > 0; o >>= 1){
        if (t < o){ smx[t] = fmaxf(smx[t], smx[t+o]); smn[t] = fminf(smn[t], smn[t+o]); }
        __syncthreads();
    }
    if (t == 0){
        atomicMax(&g_stat[2*slot],   fenc(smx[0]));
        atomicMin(&g_stat[2*slot+1], fenc(smn[0]));
    }
}

// ONE launch quantizing x, w_qkv, w_out (all rowlen 768). Warp-per-row.
// global row gr in [0,7168): [0,4096)=x, [4096,6400)=w_qkv, [6400,7168)=w_out
__global__ void k_quantrow3(const float* __restrict__ x,
                            const float* __restrict__ w1,
                            const float* __restrict__ w2){
    int warp = threadIdx.x >> 5, lane = threadIdx.x & 31;
    int gr = blockIdx.x*8 + warp;
    const float* src; bf16* dst; float* rsum; int slot; int r;
    if (gr < MROWS){           src = x;  dst = g_xq;  rsum = g_rowsum_x;  slot = 0; r = gr; }
    else if (gr < MROWS+J3){   src = w1; dst = g_wq1; rsum = g_colsum_w1; slot = 1; r = gr - MROWS; }
    else {                     src = w2; dst = g_wq2; rsum = g_colsum_w2; slot = 7; r = gr - MROWS - J3; }
    float s, z, is; get_szi(slot, s, z, is);
    const float4* s4 = (const float4*)(src + (long long)r*DMODEL);
    uint2* d2 = (uint2*)(dst + (long long)r*DMODEL);
    float acc = 0.f;
    #pragma unroll
    for (int i = 0; i < 6; i++){
        float4 v = s4[i*32 + lane];
        float q0 = quantm(v.x, is, z), q1 = quantm(v.y, is, z);
        float q2 = quantm(v.z, is, z), q3 = quantm(v.w, is, z);
        acc += (q0+q1) + (q2+q3);
        uint2 o; o.x = packbf2(q0,q1); o.y = packbf2(q2,q3);
        d2[i*32 + lane] = o;
    }
    acc = wsum(acc);
    if (lane == 0) rsum[r] = acc;
}

// warp-per-token pack of quantized q/k/v; fused token sums + v colsum
__global__ void k_pack_qkv(){
    __shared__ float vsum[64];
    int bh = blockIdx.y;
    int b = bh / NH, h = bh - b*NH;
    int warp = threadIdx.x >> 5, lane = threadIdx.x & 31;
    int n = blockIdx.x*8 + warp;
    if (threadIdx.x < 64) vsum[threadIdx.x] = 0.f;
    __syncthreads();
    float sq, zq, iq, sk, zk, ik, sv, zv, iv;
    get_szi(2, sq, zq, iq); get_szi(3, sk, zk, ik); get_szi(4, sv, zv, iv);
    long long base = (long long)(b*SEQ + n)*J3 + h*DHD + 2*lane;
    float2 qv2 = *(const float2*)&g_xqkv[base];
    float2 kv2 = *(const float2*)&g_xqkv[base + DMODEL];
    float2 vv2 = *(const float2*)&g_xqkv[base + 2*DMODEL];
    float q0 = quantm(qv2.x, iq, zq), q1 = quantm(qv2.y, iq, zq);
    float k0 = quantm(kv2.x, ik, zk), k1 = quantm(kv2.y, ik, zk);
    float v0 = quantm(vv2.x, iv, zv), v1 = quantm(vv2.y, iv, zv);
    long long po = ((long long)bh*SEQ + n)*DHD/2 + lane;
    ((u32*)g_qb)[po] = packbf2(q0, q1);
    ((u32*)g_kb)[po] = packbf2(k0, k1);
    ((u32*)g_vb)[po] = packbf2(v0, v1);
    float qs = wsum(q0 + q1);
    float ks = wsum(k0 + k1);
    if (lane == 0){
        g_rowsumq[bh*SEQ + n] = qs;
        g_colsumk[bh*SEQ + n] = ks;
    }
    atomicAdd(&vsum[2*lane],   v0);
    atomicAdd(&vsum[2*lane+1], v1);
    __syncthreads();
    if (threadIdx.x < 64) atomicAdd(&g_vcolsum[bh*DHD + threadIdx.x], vsum[threadIdx.x]);
}

// ---------------- fused attention: stats pass ----------------
__global__ void __launch_bounds__(256) k_attn_stats(){
    extern __shared__ __align__(16) char smraw[];
    bf16* Qs  = (bf16*)smraw;
    bf16* Ks0 = (bf16*)(smraw + 18432);
    bf16* Ks1 = (bf16*)(smraw + 18432*2);
    float* csk0 = (float*)(smraw + 18432*3);
    float* csk1 = (float*)(smraw + 18432*3 + 512);
    __shared__ float redx[256], redn[256];

    int bh = blockIdx.y, qt = blockIdx.x;
    int tid = threadIdx.x, warp = tid >> 5, lane = tid & 31;
    int l16 = lane & 15;
    int brow = (lane&7) + ((lane>>4)<<3);
    int bcol = ((lane>>3)&1)*8;

    float sq, zq, iq, sk, zk, ik;
    get_szi(2, sq, zq, iq); get_szi(3, sk, zk, ik);
    float s3 = (0.125f * sq) * sk;

    {
        #pragma unroll
        for (int it = 0; it < 4; it++){
            int idx = it*256 + tid;
            int r = idx >> 3, c8 = idx & 7;
            cpa(&Ks0[r*72 + c8*8], &g_kb[((long long)bh*SEQ + r)*DHD + c8*8]);
        }
        if (tid < 32) cpa(&csk0[tid*4], &g_colsumk[bh*SEQ + tid*4]);
        CP_COMMIT;
        #pragma unroll
        for (int it = 0; it < 4; it++){
            int idx = it*256 + tid;
            int r = idx >> 3, c8 = idx & 7;
            cpa(&Qs[r*72 + c8*8], &g_qb[((long long)bh*SEQ + qt*128 + r)*DHD + c8*8]);
        }
        CP_COMMIT;
    }

    int r0 = warp*16 + (lane>>2), r1 = r0 + 8;
    float rsq0 = g_rowsumq[bh*SEQ + qt*128 + r0];
    float rsq1 = g_rowsumq[bh*SEQ + qt*128 + r1];

    float m0 = -INFINITY, m1 = -INFINITY;
    float n0 =  INFINITY, n1 =  INFINITY;
    float S0 = 0.f, S1 = 0.f;

    int st = 0;
    for (int kt = 0; kt < 8; kt++){
        bf16*  Kc  = st ? Ks1 : Ks0;
        float* ckc = st ? csk1 : csk0;
        if (kt < 7){
            bf16*  Kn  = st ? Ks0 : Ks1;
            float* ckn = st ? csk0 : csk1;
            #pragma unroll
            for (int it = 0; it < 4; it++){
                int idx = it*256 + tid;
                int r = idx >> 3, c8 = idx & 7;
                cpa(&Kn[r*72 + c8*8], &g_kb[((long long)bh*SEQ + (kt+1)*128 + r)*DHD + c8*8]);
            }
            if (tid < 32) cpa(&ckn[tid*4], &g_colsumk[bh*SEQ + (kt+1)*128 + tid*4]);
            CP_COMMIT;
            CP_WAIT1;
        } else {
            CP_WAIT0;
        }
        __syncthreads();

        float acc[16][4];
        #pragma unroll
        for (int nt = 0; nt < 16; nt++){ acc[nt][0]=0.f; acc[nt][1]=0.f; acc[nt][2]=0.f; acc[nt][3]=0.f; }
        #pragma unroll
        for (int kk = 0; kk < 64; kk += 16){
            u32 af[4];
            ldsm4(af, &Qs[(warp*16 + l16)*72 + kk + (lane>>4)*8]);
            #pragma unroll
            for (int np = 0; np < 8; np++){
                u32 bq[4];
                ldsm4(bq, &Kc[(np*16 + brow)*72 + kk + bcol]);
                mma16816(acc[2*np],   af, bq);
                mma16816(acc[2*np+1], af, bq+2);
            }
        }

        int c = (lane&3)*2;
        #pragma unroll
        for (int nt = 0; nt < 16; nt++){
            int cg = nt*8 + c;
            float cz0 = ckc[cg]*zq, cz1 = ckc[cg+1]*zq;
            acc[nt][0] = (acc[nt][0] - cz0 - rsq0*zk)*s3;
            acc[nt][1] = (acc[nt][1] - cz1 - rsq0*zk)*s3;
            acc[nt][2] = (acc[nt][2] - cz0 - rsq1*zk)*s3;
            acc[nt][3] = (acc[nt][3] - cz1 - rsq1*zk)*s3;
        }
        float tx0=-INFINITY, tx1=-INFINITY, tn0=INFINITY, tn1=INFINITY;
        #pragma unroll
        for (int nt = 0; nt < 16; nt++){
            tx0 = fmaxf(tx0, fmaxf(acc[nt][0], acc[nt][1]));
            tx1 = fmaxf(tx1, fmaxf(acc[nt][2], acc[nt][3]));
            tn0 = fminf(tn0, fminf(acc[nt][0], acc[nt][1]));
            tn1 = fminf(tn1, fminf(acc[nt][2], acc[nt][3]));
        }
        tx0 = qmax(tx0); tx1 = qmax(tx1);
        tn0 = qmin(tn0); tn1 = qmin(tn1);
        float nm0 = fmaxf(m0, tx0), nm1 = fmaxf(m1, tx1);
        float se0 = 0.f, se1 = 0.f;
        #pragma unroll
        for (int nt = 0; nt < 16; nt++){
            se0 += __expf(acc[nt][0]-nm0) + __expf(acc[nt][1]-nm0);
            se1 += __expf(acc[nt][2]-nm1) + __expf(acc[nt][3]-nm1);
        }
        se0 = qsum(se0); se1 = qsum(se1);
        S0 = S0*__expf(m0-nm0) + se0;  m0 = nm0;  n0 = fminf(n0, tn0);
        S1 = S1*__expf(m1-nm1) + se1;  m1 = nm1;  n1 = fminf(n1, tn1);

        __syncthreads();
        st ^= 1;
    }

    if ((lane & 3) == 0){
        g_rowm[bh*SEQ + qt*128 + r0] = m0;  g_rowS[bh*SEQ + qt*128 + r0] = S0;
        g_rowm[bh*SEQ + qt*128 + r1] = m1;  g_rowS[bh*SEQ + qt*128 + r1] = S1;
    }
    float i0 = __fdiv_rn(1.0f, S0), i1 = __fdiv_rn(1.0f, S1);
    float ax = fmaxf(i0, i1);
    float an = fminf(__expf(n0 - m0)*i0, __expf(n1 - m1)*i1);
    redx[tid] = ax; redn[tid] = an; __syncthreads();
    for (int o = 128; o > 0; o >>= 1){
        if (tid < o){ redx[tid] = fmaxf(redx[tid], redx[tid+o]); redn[tid] = fminf(redn[tid], redn[tid+o]); }
        __syncthreads();
    }
    if (tid == 0){
        atomicMax(&g_stat[10], fenc(redx[0]));
        atomicMin(&g_stat[11], fenc(redn[0]));
    }
}

// ---------------- fused attention: recompute + quantize + AV (+out minmax) ----------------
__global__ void __launch_bounds__(256) k_attn_av(){
    extern __shared__ __align__(16) char smraw[];
    bf16* Qs  = (bf16*)smraw;
    bf16* Ks0 = (bf16*)(smraw + 18432);
    bf16* Ks1 = (bf16*)(smraw + 18432*2);
    bf16* Vs  = (bf16*)(smraw + 18432*3);
    float* csk0 = (float*)(smraw + 18432*4);
    float* csk1 = (float*)(smraw + 18432*4 + 512);
    float* vcs  = (float*)(smraw + 18432*4 + 1024);
    __shared__ float redx[256], redn[256];

    int bh = blockIdx.y, qt = blockIdx.x;
    int b = bh / NH, h = bh - b*NH;
    int tid = threadIdx.x, warp = tid >> 5, lane = tid & 31;
    int l16 = lane & 15;
    int brow = (lane&7) + ((lane>>4)<<3);
    int bcol = ((lane>>3)&1)*8;
    int vrow = (lane&7) + (((lane>>3)&1)<<3);
    int vsel = (lane>>4);

    float sq, zq, iq, sk, zk, ik, sv, zv, iv, sa, za, ia;
    get_szi(2, sq, zq, iq); get_szi(3, sk, zk, ik);
    get_szi(4, sv, zv, iv); get_szi(5, sa, za, ia);
    float s3 = (0.125f * sq) * sk;

    {
        #pragma unroll
        for (int it = 0; it < 4; it++){
            int idx = it*256 + tid;
            int r = idx >> 3, c8 = idx & 7;
            cpa(&Ks0[r*72 + c8*8], &g_kb[((long long)bh*SEQ + r)*DHD + c8*8]);
        }
        if (tid < 32) cpa(&csk0[tid*4], &g_colsumk[bh*SEQ + tid*4]);
        CP_COMMIT;
        #pragma unroll
        for (int it = 0; it < 4; it++){
            int idx = it*256 + tid;
            int r = idx >> 3, c8 = idx & 7;
            cpa(&Qs[r*72 + c8*8], &g_qb[((long long)bh*SEQ + qt*128 + r)*DHD + c8*8]);
        }
        if (tid < 16) cpa(&vcs[tid*4], &g_vcolsum[bh*DHD + tid*4]);
        CP_COMMIT;
    }

    int r0 = warp*16 + (lane>>2), r1 = r0 + 8;
    float rsq0 = g_rowsumq[bh*SEQ + qt*128 + r0];
    float rsq1 = g_rowsumq[bh*SEQ + qt*128 + r1];
    float m0 = g_rowm[bh*SEQ + qt*128 + r0], S0 = g_rowS[bh*SEQ + qt*128 + r0];
    float m1 = g_rowm[bh*SEQ + qt*128 + r1], S1 = g_rowS[bh*SEQ + qt*128 + r1];
    float coef0 = __fdiv_rn(1.0f, S0) * ia;
    float coef1 = __fdiv_rn(1.0f, S1) * ia;

    float oacc[8][4];
    #pragma unroll
    for (int nt = 0; nt < 8; nt++){ oacc[nt][0]=0.f; oacc[nt][1]=0.f; oacc[nt][2]=0.f; oacc[nt][3]=0.f; }
    float aqs0 = 0.f, aqs1 = 0.f;

    int st = 0;
    for (int kt = 0; kt < 8; kt++){
        bf16*  Kc  = st ? Ks1 : Ks0;
        float* ckc = st ? csk1 : csk0;
        if (kt < 7){
            bf16*  Kn  = st ? Ks0 : Ks1;
            float* ckn = st ? csk0 : csk1;
            #pragma unroll
            for (int it = 0; it < 4; it++){
                int idx = it*256 + tid;
                int r = idx >> 3, c8 = idx & 7;
                cpa(&Kn[r*72 + c8*8], &g_kb[((long long)bh*SEQ + (kt+1)*128 + r)*DHD + c8*8]);
            }
            if (tid < 32) cpa(&ckn[tid*4], &g_colsumk[bh*SEQ + (kt+1)*128 + tid*4]);
            CP_COMMIT;
        }
        #pragma unroll
        for (int it = 0; it < 4; it++){
            int idx = it*256 + tid;
            int r = idx >> 3, c8 = idx & 7;
            cpa(&Vs[r*72 + c8*8], &g_vb[((long long)bh*SEQ + kt*128 + r)*DHD + c8*8]);
        }
        CP_COMMIT;
        if (kt < 7) { CP_WAIT2; } else { CP_WAIT1; }
        __syncthreads();

        float acc[16][4];
        #pragma unroll
        for (int nt = 0; nt < 16; nt++){ acc[nt][0]=0.f; acc[nt][1]=0.f; acc[nt][2]=0.f; acc[nt][3]=0.f; }
        #pragma unroll
        for (int kk = 0; kk < 64; kk += 16){
            u32 af[4];
            ldsm4(af, &Qs[(warp*16 + l16)*72 + kk + (lane>>4)*8]);
            #pragma unroll
            for (int np = 0; np < 8; np++){
                u32 bq[4];
                ldsm4(bq, &Kc[(np*16 + brow)*72 + kk + bcol]);
                mma16816(acc[2*np],   af, bq);
                mma16816(acc[2*np+1], af, bq+2);
            }
        }

        int c = (lane&3)*2;
        #pragma unroll
        for (int nt = 0; nt < 16; nt++){
            int cg = nt*8 + c;
            float cz0 = ckc[cg]*zq, cz1 = ckc[cg+1]*zq;
            acc[nt][0] = (acc[nt][0] - cz0 - rsq0*zk)*s3;
            acc[nt][1] = (acc[nt][1] - cz1 - rsq0*zk)*s3;
            acc[nt][2] = (acc[nt][2] - cz0 - rsq1*zk)*s3;
            acc[nt][3] = (acc[nt][3] - cz1 - rsq1*zk)*s3;
        }

        if (kt < 7) { CP_WAIT1; } else { CP_WAIT0; }
        __syncthreads();

        #pragma unroll
        for (int j = 0; j < 8; j++){
            float q00 = rintf(fmaf(__expf(acc[2*j][0]   - m0), coef0, za));
            float q01 = rintf(fmaf(__expf(acc[2*j][1]   - m0), coef0, za));
            float q02 = rintf(fmaf(__expf(acc[2*j][2]   - m1), coef1, za));
            float q03 = rintf(fmaf(__expf(acc[2*j][3]   - m1), coef1, za));
            float q10 = rintf(fmaf(__expf(acc[2*j+1][0] - m0), coef0, za));
            float q11 = rintf(fmaf(__expf(acc[2*j+1][1] - m0), coef0, za));
            float q12 = rintf(fmaf(__expf(acc[2*j+1][2] - m1), coef1, za));
            float q13 = rintf(fmaf(__expf(acc[2*j+1][3] - m1), coef1, za));
            aqs0 += q00 + q01 + q10 + q11;
            aqs1 += q02 + q03 + q12 + q13;
            u32 pa[4];
            pa[0] = packbf2(q00, q01);
            pa[1] = packbf2(q02, q03);
            pa[2] = packbf2(q10, q11);
            pa[3] = packbf2(q12, q13);
            #pragma unroll
            for (int np = 0; np < 4; np++){
                u32 vf[4];
                ldsm4t(vf, &Vs[(16*j + vrow)*72 + (2*np + vsel)*8]);
                mma16816(oacc[2*np],   pa, vf);
                mma16816(oacc[2*np+1], pa, vf+2);
            }
        }
        __syncthreads();
        st ^= 1;
    }

    aqs0 = qsum(aqs0);
    aqs1 = qsum(aqs1);

    float mult  = sa * sv;
    float cterm = (za * zv) * (float)SEQ;
    int c = (lane&3)*2;
    long long ob0 = (long long)(b*SEQ + qt*128 + r0)*DMODEL + h*DHD;
    long long ob1 = (long long)(b*SEQ + qt*128 + r1)*DMODEL + h*DHD;
    float lmx = -INFINITY, lmn = INFINITY;
    #pragma unroll
    for (int nt = 0; nt < 8; nt++){
        int d0 = nt*8 + c;
        float w0 = vcs[d0]*za, w1 = vcs[d0+1]*za;
        float o0 = (oacc[nt][0] - w0 - aqs0*zv + cterm)*mult;
        float o1 = (oacc[nt][1] - w1 - aqs0*zv + cterm)*mult;
        float o2 = (oacc[nt][2] - w0 - aqs1*zv + cterm)*mult;
        float o3 = (oacc[nt][3] - w1 - aqs1*zv + cterm)*mult;
        g_outbuf[ob0 + d0]     = o0;
        g_outbuf[ob0 + d0 + 1] = o1;
        g_outbuf[ob1 + d0]     = o2;
        g_outbuf[ob1 + d0 + 1] = o3;
        lmx = fmaxf(lmx, fmaxf(fmaxf(o0,o1), fmaxf(o2,o3)));
        lmn = fminf(lmn, fminf(fminf(o0,o1), fminf(o2,o3)));
    }
    redx[tid] = lmx; redn[tid] = lmn; __syncthreads();
    for (int o = 128; o > 0; o >>= 1){
        if (tid < o){ redx[tid] = fmaxf(redx[tid], redx[tid+o]); redn[tid] = fminf(redn[tid], redn[tid+o]); }
        __syncthreads();
    }
    if (tid == 0){
        atomicMax(&g_stat[12], fenc(redx[0]));
        atomicMin(&g_stat[13], fenc(redn[0]));
    }
}

// ---------------- pipelined tensor-core GEMM ----------------
// A: QA=0 -> bf16 [M][K] via cp.async; QA=1 -> f32 Af quantized on the fly (slot 6)
// B [N][K] bf16 k-contig via cp.async.
template<int F1, int QA>
__global__ void __launch_bounds__(256) k_mma(
    const bf16* __restrict__ A, const float* __restrict__ Af, int lda,
    const bf16* __restrict__ Bm, int ldb,
    float* __restrict__ C, int ldc,
    int K,
    const float* __restrict__ colsumB,
    const float* __restrict__ rowsumA,
    int slotA, int slotB, float Kconst,
    const float* __restrict__ bias)
{
    const int BK = 32, PAD = 40;
    __shared__ __align__(16) bf16 As[2][128*PAD];
    __shared__ __align__(16) bf16 Bs[2][128*PAD];
    __shared__ float redx[256], redn[256];

    int i0 = blockIdx.y * 128, j0 = blockIdx.x * 128;
    int tid = threadIdx.x, warp = tid >> 5, lane = tid & 31;
    int wm = warp >> 2, wn = warp & 3;
    int l16 = lane & 15;
    int brow = (lane&7) + ((lane>>4)<<3);
    int bcol = ((lane>>3)&1)*8;

    float sA, zA, iA, sB, zB, iB;
    get_szi(slotA, sA, zA, iA); get_szi(slotB, sB, zB, iB);

    float acc[4][4][4];
    #pragma unroll
    for (int a = 0; a < 4; a++)
        #pragma unroll
        for (int b = 0; b < 4; b++){
            acc[a][b][0]=0.f; acc[a][b][1]=0.f; acc[a][b][2]=0.f; acc[a][b][3]=0.f;
        }

    float4 areg[4];
    {
        if (QA){
            #pragma unroll
            for (int v = 0; v < 4; v++){
                int idx = v*256 + tid;
                int r = idx >> 3, c4 = idx & 7;
                areg[v] = *(const float4*)&Af[(long long)(i0 + r)*lda + c4*4];
            }
        } else {
            #pragma unroll
            for (int v = 0; v < 2; v++){
                int idx = v*256 + tid;
                int r = idx >> 2, c8 = idx & 3;
                cpa(&As[0][r*PAD + c8*8], &A[(long long)(i0 + r)*lda + c8*8]);
            }
        }
        #pragma unroll
        for (int v = 0; v < 2; v++){
            int idx = v*256 + tid;
            int r = idx >> 2, c8 = idx & 3;
            cpa(&Bs[0][r*PAD + c8*8], &Bm[(long long)(j0 + r)*ldb + c8*8]);
        }
        CP_COMMIT;
    }

    int st = 0;
    for (int k0 = 0; k0 < K; k0 += BK){
        if (k0 + BK < K){
            int ns = st ^ 1, kn = k0 + BK;
            if (!QA){
                #pragma unroll
                for (int v = 0; v < 2; v++){
                    int idx = v*256 + tid;
                    int r = idx >> 2, c8 = idx & 3;
                    cpa(&As[ns][r*PAD + c8*8], &A[(long long)(i0 + r)*lda + kn + c8*8]);
                }
            }
            #pragma unroll
            for (int v = 0; v < 2; v++){
                int idx = v*256 + tid;
                int r = idx >> 2, c8 = idx & 3;
                cpa(&Bs[ns][r*PAD + c8*8], &Bm[(long long)(j0 + r)*ldb + kn + c8*8]);
            }
            CP_COMMIT;
        }
        if (QA){
            // quantize current A regs -> As[st]
            #pragma unroll
            for (int v = 0; v < 4; v++){
                int idx = v*256 + tid;
                int r = idx >> 3, c4 = idx & 7;
                float q0 = quantm(areg[v].x, iA, zA), q1 = quantm(areg[v].y, iA, zA);
                float q2 = quantm(areg[v].z, iA, zA), q3 = quantm(areg[v].w, iA, zA);
                uint2 o; o.x = packbf2(q0,q1); o.y = packbf2(q2,q3);
                *(uint2*)&As[st][r*PAD + c4*4] = o;
            }
            // prefetch next-stage A f32
            if (k0 + BK < K){
                int kn = k0 + BK;
                #pragma unroll
                for (int v = 0; v < 4; v++){
                    int idx = v*256 + tid;
                    int r = idx >> 3, c4 = idx & 7;
                    areg[v] = *(const float4*)&Af[(long long)(i0 + r)*lda + kn + c4*4];
                }
            }
        }
        if (k0 + BK < K) { CP_WAIT1; } else { CP_WAIT0; }
        __syncthreads();

        #pragma unroll
        for (int kk = 0; kk < BK; kk += 16){
            u32 af[4][4];
            #pragma unroll
            for (int mt = 0; mt < 4; mt++)
                ldsm4(af[mt], &As[st][(wm*64 + mt*16 + l16)*PAD + kk + (lane>>4)*8]);
            u32 bq[2][4];
            #pragma unroll
            for (int np = 0; np < 2; np++)
                ldsm4(bq[np], &Bs[st][(wn*32 + np*16 + brow)*PAD + kk + bcol]);
            #pragma unroll
            for (int mt = 0; mt < 4; mt++){
                mma16816(acc[mt][0], af[mt], bq[0]);
                mma16816(acc[mt][1], af[mt], bq[0]+2);
                mma16816(acc[mt][2], af[mt], bq[1]);
                mma16816(acc[mt][3], af[mt], bq[1]+2);
            }
        }
        __syncthreads();
        st ^= 1;
    }

    float mult  = sA * sB;
    float cterm = (zA * zB) * Kconst;

    float lmx = -INFINITY, lmn = INFINITY;

    #pragma unroll
    for (int mt = 0; mt < 4; mt++){
        int row0 = i0 + wm*64 + mt*16 + (lane>>2);
        float rs0 = rowsumA[row0], rs1 = rowsumA[row0+8];
        float p0 = 0.f, p8 = 0.f;
        #pragma unroll
        for (int nt = 0; nt < 4; nt++){
            int col0 = j0 + wn*32 + nt*8 + (lane&3)*2;
            float cs0 = colsumB[col0], cs1 = colsumB[col0+1];
            float b0 = bias ? bias[col0]   : 0.f;
            float b1 = bias ? bias[col0+1] : 0.f;
            float v0 = (acc[mt][nt][0] - cs0*zA - rs0*zB + cterm)*mult + b0;
            float v1 = (acc[mt][nt][1] - cs1*zA - rs0*zB + cterm)*mult + b1;
            float v2 = (acc[mt][nt][2] - cs0*zA - rs1*zB + cterm)*mult + b0;
            float v3 = (acc[mt][nt][3] - cs1*zA - rs1*zB + cterm)*mult + b1;
            C[(long long)row0*ldc + col0]       = v0;
            C[(long long)row0*ldc + col0 + 1]   = v1;
            C[(long long)(row0+8)*ldc + col0]   = v2;
            C[(long long)(row0+8)*ldc + col0+1] = v3;
            if (F1){
                p0 += v0 + v1; p8 += v2 + v3;
                lmx = fmaxf(lmx, fmaxf(fmaxf(v0,v1), fmaxf(v2,v3)));
                lmn = fminf(lmn, fminf(fminf(v0,v1), fminf(v2,v3)));
            }
        }
        if (F1){
            p0 = qsum(p0); p8 = qsum(p8);
            if ((lane & 3) == 0){
                atomicAdd(&g_xqkvsum[row0],   p0);
                atomicAdd(&g_xqkvsum[row0+8], p8);
            }
        }
    }

    if (F1){
        redx[tid] = lmx; redn[tid] = lmn; __syncthreads();
        for (int o = 128; o > 0; o >>= 1){
            if (tid < o){ redx[tid] = fmaxf(redx[tid], redx[tid+o]); redn[tid] = fminf(redn[tid], redn[tid+o]); }
            __syncthreads();
        }
        if (tid == 0){
            int region = blockIdx.x / 6;
            atomicMax(&g_stat[2*(2+region)],   fenc(redx[0]));
            atomicMin(&g_stat[2*(2+region)+1], fenc(redn[0]));
        }
    }
}

// ---------------- launcher ----------------
extern "C" void kernel_launch(void* const* d_in, const int* in_sizes, int n_in,
                              void* d_out, int out_size){
    const float *x = 0, *wqkv = 0, *wout = 0, *bout = 0;
    for (int i = 0; i < n_in; i++){
        if      (in_sizes[i] == MROWS*DMODEL)  x    = (const float*)d_in[i];
        else if (in_sizes[i] == J3*DMODEL)     wqkv = (const float*)d_in[i];
        else if (in_sizes[i] == DMODEL*DMODEL) wout = (const float*)d_in[i];
        else if (in_sizes[i] == DMODEL)        bout = (const float*)d_in[i];
    }
    float* out = (float*)d_out;

    bf16 *p_xq, *p_wq1, *p_wq2;
    float *p_xqkv, *p_outbuf;
    float *p_rowsum_x, *p_colsum_w1, *p_colsum_w2, *p_xqkvsum;
    cudaGetSymbolAddress((void**)&p_xq,        g_xq);
    cudaGetSymbolAddress((void**)&p_wq1,       g_wq1);
    cudaGetSymbolAddress((void**)&p_wq2,       g_wq2);
    cudaGetSymbolAddress((void**)&p_xqkv,      g_xqkv);
    cudaGetSymbolAddress((void**)&p_outbuf,    g_outbuf);
    cudaGetSymbolAddress((void**)&p_rowsum_x,  g_rowsum_x);
    cudaGetSymbolAddress((void**)&p_colsum_w1, g_colsum_w1);
    cudaGetSymbolAddress((void**)&p_colsum_w2, g_colsum_w2);
    cudaGetSymbolAddress((void**)&p_xqkvsum,   g_xqkvsum);

    static int smem_set = 0;
    if (!smem_set){
        cudaFuncSetAttribute(k_attn_stats, cudaFuncAttributeMaxDynamicSharedMemorySize, 18432*3 + 2048);
        cudaFuncSetAttribute(k_attn_av,    cudaFuncAttributeMaxDynamicSharedMemorySize, 18432*4 + 2048);
        smem_set = 1;
    }

    k_init<<<1, 256>>>();
    k_minmax3<<<dim3(768, 3), 256>>>(x, MROWS*DMODEL, 0,
                                     wqkv, J3*DMODEL, 1,
                                     wout, DMODEL*DMODEL, 7);
    k_quantrow3<<<(MROWS+J3+DMODEL)/8, 256>>>(x, wqkv, wout);
    k_mma<1,0><<<dim3(J3/128, MROWS/128), 256>>>(
        p_xq, (const float*)0, DMODEL, p_wq1, DMODEL, p_xqkv, J3, DMODEL,
        p_colsum_w1, p_rowsum_x, 0, 1, (float)DMODEL, (const float*)0);
    k_pack_qkv<<<dim3(SEQ/8, BHN), 256>>>();
    k_attn_stats<<<dim3(8, BHN), 256, 18432*3 + 2048>>>();
    k_attn_av<<<dim3(8, BHN), 256, 18432*4 + 2048>>>();
    // gemm2: A = outbuf f32 quantized on the fly (slot 6); rowsum = xqkvsum (faithful bug)
    k_mma<0,1><<<dim3(DMODEL/128, MROWS/128), 256>>>(
        (const bf16*)0, p_outbuf, DMODEL, p_wq2, DMODEL, out, DMODEL, DMODEL,
        p_colsum_w2, p_xqkvsum, 6, 7, (float)J3, bout);
}

// round 13
// speedup vs baseline: 1.6562x; 1.0017x over previous
#include <cuda_runtime.h>
#include <cuda_bf16.h>
#include <cstdint>
#include <cstddef>
#include <math.h>

#define NB      4
#define SEQ     1024
#define DMODEL  768
#define NH      12
#define DHD     64
#define J3      2304
#define MROWS   4096
#define BHN     48

typedef __nv_bfloat16 bf16;
typedef unsigned int  u32;

// ---------------- scratch ----------------
__device__ __align__(16) bf16  g_xq[MROWS*DMODEL];
__device__ __align__(16) bf16  g_wq1[J3*DMODEL];
__device__ __align__(16) bf16  g_wq2[DMODEL*DMODEL];
__device__ __align__(16) float g_xqkv[MROWS*J3];
__device__ __align__(16) bf16  g_qb[BHN*SEQ*DHD];
__device__ __align__(16) bf16  g_kb[BHN*SEQ*DHD];
__device__ __align__(16) bf16  g_vb[BHN*SEQ*DHD];
__device__ __align__(16) float g_outbuf[MROWS*DMODEL];
__device__ float    g_rowsum_x[MROWS];
__device__ float    g_colsum_w1[J3];
__device__ float    g_colsum_w2[DMODEL];
__device__ float    g_xqkvsum[MROWS];
__device__ float    g_rowsumq[BHN*SEQ];
__device__ float    g_colsumk[BHN*SEQ];
__device__ float    g_vcolsum[BHN*DHD];
__device__ float    g_rowm[BHN*SEQ];
__device__ float    g_rowS[BHN*SEQ];
__device__ unsigned g_stat[16];   // slots:0=x 1=w1 2=q 3=k 4=v 5=a 6=out 7=w2

// ---------------- helpers ----------------
__device__ __forceinline__ unsigned fenc(float f){
    unsigned u = __float_as_uint(f);
    return (u & 0x80000000u) ? ~u : (u | 0x80000000u);
}
__device__ __forceinline__ float fdec(unsigned e){
    return (e & 0x80000000u) ? __uint_as_float(e ^ 0x80000000u) : __uint_as_float(~e);
}
__device__ __forceinline__ void get_szi(int slot, float& s, float& z, float& is){
    float mx = fdec(g_stat[2*slot]);
    float mn = fdec(g_stat[2*slot+1]);
    s = __fdiv_rn(mx - mn, 15.0f);
    z = rintf(15.0f - __fdiv_rn(mx, s));
    is = __fdiv_rn(1.0f, s);
}
__device__ __forceinline__ float quantm(float v, float is, float z){
    return rintf(fmaf(v, is, z));
}
__device__ __forceinline__ u32 packbf2(float lo, float hi){
    __nv_bfloat162 t = __floats2bfloat162_rn(lo, hi);
    return *reinterpret_cast<u32*>(&t);
}
__device__ __forceinline__ void ldsm4(u32* r, const void* p){
    u32 a = (u32)__cvta_generic_to_shared(p);
    asm volatile("ldmatrix.sync.aligned.m8n8.x4.shared.b16 {%0,%1,%2,%3},[%4];"
        : "=r"(r[0]),"=r"(r[1]),"=r"(r[2]),"=r"(r[3]) : "r"(a));
}
__device__ __forceinline__ void ldsm4t(u32* r, const void* p){
    u32 a = (u32)__cvta_generic_to_shared(p);
    asm volatile("ldmatrix.sync.aligned.m8n8.x4.trans.shared.b16 {%0,%1,%2,%3},[%4];"
        : "=r"(r[0]),"=r"(r[1]),"=r"(r[2]),"=r"(r[3]) : "r"(a));
}
__device__ __forceinline__ void mma16816(float* c, const u32* a, const u32* b){
    asm volatile("mma.sync.aligned.m16n8k16.row.col.f32.bf16.bf16.f32 "
        "{%0,%1,%2,%3}, {%4,%5,%6,%7}, {%8,%9}, {%0,%1,%2,%3};"
        : "+f"(c[0]),"+f"(c[1]),"+f"(c[2]),"+f"(c[3])
        : "r"(a[0]),"r"(a[1]),"r"(a[2]),"r"(a[3]), "r"(b[0]),"r"(b[1]));
}
__device__ __forceinline__ void cpa(void* s, const void* g){
    u32 a = (u32)__cvta_generic_to_shared(s);
    asm volatile("cp.async.cg.shared.global [%0],[%1],16;" :: "r"(a), "l"(g));
}
#define CP_COMMIT asm volatile("cp.async.commit_group;")
#define CP_WAIT0  asm volatile("cp.async.wait_group 0;")
#define CP_WAIT1  asm volatile("cp.async.wait_group 1;")
#define CP_WAIT2  asm volatile("cp.async.wait_group 2;")

__device__ __forceinline__ float qsum(float v){
    v += __shfl_xor_sync(0xffffffffu, v, 1);
    v += __shfl_xor_sync(0xffffffffu, v, 2);
    return v;
}
__device__ __forceinline__ float qmax(float v){
    v = fmaxf(v, __shfl_xor_sync(0xffffffffu, v, 1));
    v = fmaxf(v, __shfl_xor_sync(0xffffffffu, v, 2));
    return v;
}
__device__ __forceinline__ float qmin(float v){
    v = fminf(v, __shfl_xor_sync(0xffffffffu, v, 1));
    v = fminf(v, __shfl_xor_sync(0xffffffffu, v, 2));
    return v;
}
__device__ __forceinline__ float wsum(float v){
    #pragma unroll
    for (int o = 16; o > 0; o >>= 1) v += __shfl_xor_sync(0xffffffffu, v, o);
    return v;
}

// ---------------- elementwise kernels ----------------
__global__ void k_init(){
    int t = threadIdx.x;
    if (t < 8){ g_stat[2*t] = fenc(-INFINITY); g_stat[2*t+1] = fenc(INFINITY); }
    for (int i = t; i < BHN*DHD; i += blockDim.x) g_vcolsum[i] = 0.f;
    for (int i = t; i < MROWS;   i += blockDim.x) g_xqkvsum[i] = 0.f;
}

__global__ void k_minmax3(const float* __restrict__ pa, int na, int sa_,
                          const float* __restrict__ pb, int nb, int sb_,
                          const float* __restrict__ pc, int nc, int sc_){
    const float* p; int n, slot;
    if (blockIdx.y == 0){ p = pa; n = na; slot = sa_; }
    else if (blockIdx.y == 1){ p = pb; n = nb; slot = sb_; }
    else { p = pc; n = nc; slot = sc_; }
    float mx = -INFINITY, mn = INFINITY;
    int n4 = n >> 2;
    const float4* p4 = (const float4*)p;
    for (int i = blockIdx.x*blockDim.x + threadIdx.x; i < n4; i += gridDim.x*blockDim.x){
        float4 v = p4[i];
        mx = fmaxf(mx, fmaxf(fmaxf(v.x,v.y), fmaxf(v.z,v.w)));
        mn = fminf(mn, fminf(fminf(v.x,v.y), fminf(v.z,v.w)));
    }
    __shared__ float smx[256], smn[256];
    int t = threadIdx.x;
    smx[t] = mx; smn[t] = mn; __syncthreads();
    for (int o = 128; o > 0; o >>= 1){
        if (t < o){ smx[t] = fmaxf(smx[t], smx[t+o]); smn[t] = fminf(smn[t], smn[t+o]); }
        __syncthreads();
    }
    if (t == 0){
        atomicMax(&g_stat[2*slot],   fenc(smx[0]));
        atomicMin(&g_stat[2*slot+1], fenc(smn[0]));
    }
}

// ONE launch quantizing x, w_qkv, w_out (all rowlen 768). Warp-per-row.
__global__ void k_quantrow3(const float* __restrict__ x,
                            const float* __restrict__ w1,
                            const float* __restrict__ w2){
    int warp = threadIdx.x >> 5, lane = threadIdx.x & 31;
    int gr = blockIdx.x*8 + warp;
    const float* src; bf16* dst; float* rsum; int slot; int r;
    if (gr < MROWS){           src = x;  dst = g_xq;  rsum = g_rowsum_x;  slot = 0; r = gr; }
    else if (gr < MROWS+J3){   src = w1; dst = g_wq1; rsum = g_colsum_w1; slot = 1; r = gr - MROWS; }
    else {                     src = w2; dst = g_wq2; rsum = g_colsum_w2; slot = 7; r = gr - MROWS - J3; }
    float s, z, is; get_szi(slot, s, z, is);
    const float4* s4 = (const float4*)(src + (long long)r*DMODEL);
    uint2* d2 = (uint2*)(dst + (long long)r*DMODEL);
    float acc = 0.f;
    #pragma unroll
    for (int i = 0; i < 6; i++){
        float4 v = s4[i*32 + lane];
        float q0 = quantm(v.x, is, z), q1 = quantm(v.y, is, z);
        float q2 = quantm(v.z, is, z), q3 = quantm(v.w, is, z);
        acc += (q0+q1) + (q2+q3);
        uint2 o; o.x = packbf2(q0,q1); o.y = packbf2(q2,q3);
        d2[i*32 + lane] = o;
    }
    acc = wsum(acc);
    if (lane == 0) rsum[r] = acc;
}

// warp-per-token pack of quantized q/k/v; fused token sums + v colsum
__global__ void k_pack_qkv(){
    __shared__ float vsum[64];
    int bh = blockIdx.y;
    int b = bh / NH, h = bh - b*NH;
    int warp = threadIdx.x >> 5, lane = threadIdx.x & 31;
    int n = blockIdx.x*8 + warp;
    if (threadIdx.x < 64) vsum[threadIdx.x] = 0.f;
    __syncthreads();
    float sq, zq, iq, sk, zk, ik, sv, zv, iv;
    get_szi(2, sq, zq, iq); get_szi(3, sk, zk, ik); get_szi(4, sv, zv, iv);
    long long base = (long long)(b*SEQ + n)*J3 + h*DHD + 2*lane;
    float2 qv2 = *(const float2*)&g_xqkv[base];
    float2 kv2 = *(const float2*)&g_xqkv[base + DMODEL];
    float2 vv2 = *(const float2*)&g_xqkv[base + 2*DMODEL];
    float q0 = quantm(qv2.x, iq, zq), q1 = quantm(qv2.y, iq, zq);
    float k0 = quantm(kv2.x, ik, zk), k1 = quantm(kv2.y, ik, zk);
    float v0 = quantm(vv2.x, iv, zv), v1 = quantm(vv2.y, iv, zv);
    long long po = ((long long)bh*SEQ + n)*DHD/2 + lane;
    ((u32*)g_qb)[po] = packbf2(q0, q1);
    ((u32*)g_kb)[po] = packbf2(k0, k1);
    ((u32*)g_vb)[po] = packbf2(v0, v1);
    float qs = wsum(q0 + q1);
    float ks = wsum(k0 + k1);
    if (lane == 0){
        g_rowsumq[bh*SEQ + n] = qs;
        g_colsumk[bh*SEQ + n] = ks;
    }
    atomicAdd(&vsum[2*lane],   v0);
    atomicAdd(&vsum[2*lane+1], v1);
    __syncthreads();
    if (threadIdx.x < 64) atomicAdd(&g_vcolsum[bh*DHD + threadIdx.x], vsum[threadIdx.x]);
}

// ---------------- fused attention: stats pass ----------------
__global__ void __launch_bounds__(256) k_attn_stats(){
    extern __shared__ __align__(16) char smraw[];
    bf16* Qs  = (bf16*)smraw;
    bf16* Ks0 = (bf16*)(smraw + 18432);
    bf16* Ks1 = (bf16*)(smraw + 18432*2);
    float* csk0 = (float*)(smraw + 18432*3);
    float* csk1 = (float*)(smraw + 18432*3 + 512);
    __shared__ float redx[256], redn[256];

    int bh = blockIdx.y, qt = blockIdx.x;
    int tid = threadIdx.x, warp = tid >> 5, lane = tid & 31;
    int l16 = lane & 15;
    int brow = (lane&7) + ((lane>>4)<<3);
    int bcol = ((lane>>3)&1)*8;

    float sq, zq, iq, sk, zk, ik;
    get_szi(2, sq, zq, iq); get_szi(3, sk, zk, ik);
    float s3 = (0.125f * sq) * sk;

    {
        #pragma unroll
        for (int it = 0; it < 4; it++){
            int idx = it*256 + tid;
            int r = idx >> 3, c8 = idx & 7;
            cpa(&Ks0[r*72 + c8*8], &g_kb[((long long)bh*SEQ + r)*DHD + c8*8]);
        }
        if (tid < 32) cpa(&csk0[tid*4], &g_colsumk[bh*SEQ + tid*4]);
        CP_COMMIT;
        #pragma unroll
        for (int it = 0; it < 4; it++){
            int idx = it*256 + tid;
            int r = idx >> 3, c8 = idx & 7;
            cpa(&Qs[r*72 + c8*8], &g_qb[((long long)bh*SEQ + qt*128 + r)*DHD + c8*8]);
        }
        CP_COMMIT;
    }

    int r0 = warp*16 + (lane>>2), r1 = r0 + 8;
    float rsq0 = g_rowsumq[bh*SEQ + qt*128 + r0];
    float rsq1 = g_rowsumq[bh*SEQ + qt*128 + r1];

    float m0 = -INFINITY, m1 = -INFINITY;
    float n0 =  INFINITY, n1 =  INFINITY;
    float S0 = 0.f, S1 = 0.f;

    int st = 0;
    for (int kt = 0; kt < 8; kt++){
        bf16*  Kc  = st ? Ks1 : Ks0;
        float* ckc = st ? csk1 : csk0;
        if (kt < 7){
            bf16*  Kn  = st ? Ks0 : Ks1;
            float* ckn = st ? csk0 : csk1;
            #pragma unroll
            for (int it = 0; it < 4; it++){
                int idx = it*256 + tid;
                int r = idx >> 3, c8 = idx & 7;
                cpa(&Kn[r*72 + c8*8], &g_kb[((long long)bh*SEQ + (kt+1)*128 + r)*DHD + c8*8]);
            }
            if (tid < 32) cpa(&ckn[tid*4], &g_colsumk[bh*SEQ + (kt+1)*128 + tid*4]);
            CP_COMMIT;
            CP_WAIT1;
        } else {
            CP_WAIT0;
        }
        __syncthreads();

        float acc[16][4];
        #pragma unroll
        for (int nt = 0; nt < 16; nt++){ acc[nt][0]=0.f; acc[nt][1]=0.f; acc[nt][2]=0.f; acc[nt][3]=0.f; }
        #pragma unroll
        for (int kk = 0; kk < 64; kk += 16){
            u32 af[4];
            ldsm4(af, &Qs[(warp*16 + l16)*72 + kk + (lane>>4)*8]);
            #pragma unroll
            for (int np = 0; np < 8; np++){
                u32 bq[4];
                ldsm4(bq, &Kc[(np*16 + brow)*72 + kk + bcol]);
                mma16816(acc[2*np],   af, bq);
                mma16816(acc[2*np+1], af, bq+2);
            }
        }

        int c = (lane&3)*2;
        #pragma unroll
        for (int nt = 0; nt < 16; nt++){
            int cg = nt*8 + c;
            float cz0 = ckc[cg]*zq, cz1 = ckc[cg+1]*zq;
            acc[nt][0] = (acc[nt][0] - cz0 - rsq0*zk)*s3;
            acc[nt][1] = (acc[nt][1] - cz1 - rsq0*zk)*s3;
            acc[nt][2] = (acc[nt][2] - cz0 - rsq1*zk)*s3;
            acc[nt][3] = (acc[nt][3] - cz1 - rsq1*zk)*s3;
        }
        float tx0=-INFINITY, tx1=-INFINITY, tn0=INFINITY, tn1=INFINITY;
        #pragma unroll
        for (int nt = 0; nt < 16; nt++){
            tx0 = fmaxf(tx0, fmaxf(acc[nt][0], acc[nt][1]));
            tx1 = fmaxf(tx1, fmaxf(acc[nt][2], acc[nt][3]));
            tn0 = fminf(tn0, fminf(acc[nt][0], acc[nt][1]));
            tn1 = fminf(tn1, fminf(acc[nt][2], acc[nt][3]));
        }
        tx0 = qmax(tx0); tx1 = qmax(tx1);
        tn0 = qmin(tn0); tn1 = qmin(tn1);
        float nm0 = fmaxf(m0, tx0), nm1 = fmaxf(m1, tx1);
        float se0 = 0.f, se1 = 0.f;
        #pragma unroll
        for (int nt = 0; nt < 16; nt++){
            se0 += __expf(acc[nt][0]-nm0) + __expf(acc[nt][1]-nm0);
            se1 += __expf(acc[nt][2]-nm1) + __expf(acc[nt][3]-nm1);
        }
        se0 = qsum(se0); se1 = qsum(se1);
        S0 = S0*__expf(m0-nm0) + se0;  m0 = nm0;  n0 = fminf(n0, tn0);
        S1 = S1*__expf(m1-nm1) + se1;  m1 = nm1;  n1 = fminf(n1, tn1);

        __syncthreads();
        st ^= 1;
    }

    if ((lane & 3) == 0){
        g_rowm[bh*SEQ + qt*128 + r0] = m0;  g_rowS[bh*SEQ + qt*128 + r0] = S0;
        g_rowm[bh*SEQ + qt*128 + r1] = m1;  g_rowS[bh*SEQ + qt*128 + r1] = S1;
    }
    float i0 = __fdiv_rn(1.0f, S0), i1 = __fdiv_rn(1.0f, S1);
    float ax = fmaxf(i0, i1);
    float an = fminf(__expf(n0 - m0)*i0, __expf(n1 - m1)*i1);
    redx[tid] = ax; redn[tid] = an; __syncthreads();
    for (int o = 128; o > 0; o >>= 1){
        if (tid < o){ redx[tid] = fmaxf(redx[tid], redx[tid+o]); redn[tid] = fminf(redn[tid], redn[tid+o]); }
        __syncthreads();
    }
    if (tid == 0){
        atomicMax(&g_stat[10], fenc(redx[0]));
        atomicMin(&g_stat[11], fenc(redn[0]));
    }
}

// ---------------- fused attention: recompute + quantize + AV (+out minmax) ----------------
__global__ void __launch_bounds__(256) k_attn_av(){
    extern __shared__ __align__(16) char smraw[];
    bf16* Qs  = (bf16*)smraw;
    bf16* Ks0 = (bf16*)(smraw + 18432);
    bf16* Ks1 = (bf16*)(smraw + 18432*2);
    bf16* Vs  = (bf16*)(smraw + 18432*3);
    float* csk0 = (float*)(smraw + 18432*4);
    float* csk1 = (float*)(smraw + 18432*4 + 512);
    float* vcs  = (float*)(smraw + 18432*4 + 1024);
    __shared__ float redx[256], redn[256];

    int bh = blockIdx.y, qt = blockIdx.x;
    int b = bh / NH, h = bh - b*NH;
    int tid = threadIdx.x, warp = tid >> 5, lane = tid & 31;
    int l16 = lane & 15;
    int brow = (lane&7) + ((lane>>4)<<3);
    int bcol = ((lane>>3)&1)*8;
    int vrow = (lane&7) + (((lane>>3)&1)<<3);
    int vsel = (lane>>4);

    float sq, zq, iq, sk, zk, ik, sv, zv, iv, sa, za, ia;
    get_szi(2, sq, zq, iq); get_szi(3, sk, zk, ik);
    get_szi(4, sv, zv, iv); get_szi(5, sa, za, ia);
    float s3 = (0.125f * sq) * sk;

    {
        #pragma unroll
        for (int it = 0; it < 4; it++){
            int idx = it*256 + tid;
            int r = idx >> 3, c8 = idx & 7;
            cpa(&Ks0[r*72 + c8*8], &g_kb[((long long)bh*SEQ + r)*DHD + c8*8]);
        }
        if (tid < 32) cpa(&csk0[tid*4], &g_colsumk[bh*SEQ + tid*4]);
        CP_COMMIT;
        #pragma unroll
        for (int it = 0; it < 4; it++){
            int idx = it*256 + tid;
            int r = idx >> 3, c8 = idx & 7;
            cpa(&Qs[r*72 + c8*8], &g_qb[((long long)bh*SEQ + qt*128 + r)*DHD + c8*8]);
        }
        if (tid < 16) cpa(&vcs[tid*4], &g_vcolsum[bh*DHD + tid*4]);
        CP_COMMIT;
    }

    int r0 = warp*16 + (lane>>2), r1 = r0 + 8;
    float rsq0 = g_rowsumq[bh*SEQ + qt*128 + r0];
    float rsq1 = g_rowsumq[bh*SEQ + qt*128 + r1];
    float m0 = g_rowm[bh*SEQ + qt*128 + r0], S0 = g_rowS[bh*SEQ + qt*128 + r0];
    float m1 = g_rowm[bh*SEQ + qt*128 + r1], S1 = g_rowS[bh*SEQ + qt*128 + r1];
    float coef0 = __fdiv_rn(1.0f, S0) * ia;
    float coef1 = __fdiv_rn(1.0f, S1) * ia;

    float oacc[8][4];
    #pragma unroll
    for (int nt = 0; nt < 8; nt++){ oacc[nt][0]=0.f; oacc[nt][1]=0.f; oacc[nt][2]=0.f; oacc[nt][3]=0.f; }
    float aqs0 = 0.f, aqs1 = 0.f;

    int st = 0;
    for (int kt = 0; kt < 8; kt++){
        bf16*  Kc  = st ? Ks1 : Ks0;
        float* ckc = st ? csk1 : csk0;
        if (kt < 7){
            bf16*  Kn  = st ? Ks0 : Ks1;
            float* ckn = st ? csk0 : csk1;
            #pragma unroll
            for (int it = 0; it < 4; it++){
                int idx = it*256 + tid;
                int r = idx >> 3, c8 = idx & 7;
                cpa(&Kn[r*72 + c8*8], &g_kb[((long long)bh*SEQ + (kt+1)*128 + r)*DHD + c8*8]);
            }
            if (tid < 32) cpa(&ckn[tid*4], &g_colsumk[bh*SEQ + (kt+1)*128 + tid*4]);
            CP_COMMIT;
        }
        #pragma unroll
        for (int it = 0; it < 4; it++){
            int idx = it*256 + tid;
            int r = idx >> 3, c8 = idx & 7;
            cpa(&Vs[r*72 + c8*8], &g_vb[((long long)bh*SEQ + kt*128 + r)*DHD + c8*8]);
        }
        CP_COMMIT;
        if (kt < 7) { CP_WAIT2; } else { CP_WAIT1; }
        __syncthreads();

        float acc[16][4];
        #pragma unroll
        for (int nt = 0; nt < 16; nt++){ acc[nt][0]=0.f; acc[nt][1]=0.f; acc[nt][2]=0.f; acc[nt][3]=0.f; }
        #pragma unroll
        for (int kk = 0; kk < 64; kk += 16){
            u32 af[4];
            ldsm4(af, &Qs[(warp*16 + l16)*72 + kk + (lane>>4)*8]);
            #pragma unroll
            for (int np = 0; np < 8; np++){
                u32 bq[4];
                ldsm4(bq, &Kc[(np*16 + brow)*72 + kk + bcol]);
                mma16816(acc[2*np],   af, bq);
                mma16816(acc[2*np+1], af, bq+2);
            }
        }

        int c = (lane&3)*2;
        #pragma unroll
        for (int nt = 0; nt < 16; nt++){
            int cg = nt*8 + c;
            float cz0 = ckc[cg]*zq, cz1 = ckc[cg+1]*zq;
            acc[nt][0] = (acc[nt][0] - cz0 - rsq0*zk)*s3;
            acc[nt][1] = (acc[nt][1] - cz1 - rsq0*zk)*s3;
            acc[nt][2] = (acc[nt][2] - cz0 - rsq1*zk)*s3;
            acc[nt][3] = (acc[nt][3] - cz1 - rsq1*zk)*s3;
        }

        if (kt < 7) { CP_WAIT1; } else { CP_WAIT0; }
        __syncthreads();

        #pragma unroll
        for (int j = 0; j < 8; j++){
            float q00 = rintf(fmaf(__expf(acc[2*j][0]   - m0), coef0, za));
            float q01 = rintf(fmaf(__expf(acc[2*j][1]   - m0), coef0, za));
            float q02 = rintf(fmaf(__expf(acc[2*j][2]   - m1), coef1, za));
            float q03 = rintf(fmaf(__expf(acc[2*j][3]   - m1), coef1, za));
            float q10 = rintf(fmaf(__expf(acc[2*j+1][0] - m0), coef0, za));
            float q11 = rintf(fmaf(__expf(acc[2*j+1][1] - m0), coef0, za));
            float q12 = rintf(fmaf(__expf(acc[2*j+1][2] - m1), coef1, za));
            float q13 = rintf(fmaf(__expf(acc[2*j+1][3] - m1), coef1, za));
            aqs0 += q00 + q01 + q10 + q11;
            aqs1 += q02 + q03 + q12 + q13;
            u32 pa[4];
            pa[0] = packbf2(q00, q01);
            pa[1] = packbf2(q02, q03);
            pa[2] = packbf2(q10, q11);
            pa[3] = packbf2(q12, q13);
            #pragma unroll
            for (int np = 0; np < 4; np++){
                u32 vf[4];
                ldsm4t(vf, &Vs[(16*j + vrow)*72 + (2*np + vsel)*8]);
                mma16816(oacc[2*np],   pa, vf);
                mma16816(oacc[2*np+1], pa, vf+2);
            }
        }
        __syncthreads();
        st ^= 1;
    }

    aqs0 = qsum(aqs0);
    aqs1 = qsum(aqs1);

    float mult  = sa * sv;
    float cterm = (za * zv) * (float)SEQ;
    int c = (lane&3)*2;
    long long ob0 = (long long)(b*SEQ + qt*128 + r0)*DMODEL + h*DHD;
    long long ob1 = (long long)(b*SEQ + qt*128 + r1)*DMODEL + h*DHD;
    float lmx = -INFINITY, lmn = INFINITY;
    #pragma unroll
    for (int nt = 0; nt < 8; nt++){
        int d0 = nt*8 + c;
        float w0 = vcs[d0]*za, w1 = vcs[d0+1]*za;
        float o0 = (oacc[nt][0] - w0 - aqs0*zv + cterm)*mult;
        float o1 = (oacc[nt][1] - w1 - aqs0*zv + cterm)*mult;
        float o2 = (oacc[nt][2] - w0 - aqs1*zv + cterm)*mult;
        float o3 = (oacc[nt][3] - w1 - aqs1*zv + cterm)*mult;
        g_outbuf[ob0 + d0]     = o0;
        g_outbuf[ob0 + d0 + 1] = o1;
        g_outbuf[ob1 + d0]     = o2;
        g_outbuf[ob1 + d0 + 1] = o3;
        lmx = fmaxf(lmx, fmaxf(fmaxf(o0,o1), fmaxf(o2,o3)));
        lmn = fminf(lmn, fminf(fminf(o0,o1), fminf(o2,o3)));
    }
    redx[tid] = lmx; redn[tid] = lmn; __syncthreads();
    for (int o = 128; o > 0; o >>= 1){
        if (tid < o){ redx[tid] = fmaxf(redx[tid], redx[tid+o]); redn[tid] = fminf(redn[tid], redn[tid+o]); }
        __syncthreads();
    }
    if (tid == 0){
        atomicMax(&g_stat[12], fenc(redx[0]));
        atomicMin(&g_stat[13], fenc(redn[0]));
    }
}

// ---------------- pipelined tensor-core GEMM, BK=64, dynamic smem ----------------
// A: QA=0 -> bf16 [M][K] via cp.async; QA=1 -> f32 Af quantized on the fly (slot 6)
// B [N][K] bf16 k-contig. smem layout: As[2][128*PAD] | Bs[2][128*PAD], PAD=72.
template<int F1, int QA>
__global__ void __launch_bounds__(256) k_mma(
    const bf16* __restrict__ A, const float* __restrict__ Af, int lda,
    const bf16* __restrict__ Bm, int ldb,
    float* __restrict__ C, int ldc,
    int K,
    const float* __restrict__ colsumB,
    const float* __restrict__ rowsumA,
    int slotA, int slotB, float Kconst,
    const float* __restrict__ bias)
{
    const int BK = 64, PAD = 72;
    extern __shared__ __align__(16) char gsm[];
    bf16* As0 = (bf16*)gsm;
    bf16* As1 = (bf16*)(gsm + 128*PAD*2);
    bf16* Bs0 = (bf16*)(gsm + 128*PAD*4);
    bf16* Bs1 = (bf16*)(gsm + 128*PAD*6);
    float* redx = (float*)(gsm + 128*PAD*8);
    float* redn = redx + 256;

    int i0 = blockIdx.y * 128, j0 = blockIdx.x * 128;
    int tid = threadIdx.x, warp = tid >> 5, lane = tid & 31;
    int wm = warp >> 2, wn = warp & 3;
    int l16 = lane & 15;
    int brow = (lane&7) + ((lane>>4)<<3);
    int bcol = ((lane>>3)&1)*8;

    float sA, zA, iA, sB, zB, iB;
    get_szi(slotA, sA, zA, iA); get_szi(slotB, sB, zB, iB);

    float acc[4][4][4];
    #pragma unroll
    for (int a = 0; a < 4; a++)
        #pragma unroll
        for (int b = 0; b < 4; b++){
            acc[a][b][0]=0.f; acc[a][b][1]=0.f; acc[a][b][2]=0.f; acc[a][b][3]=0.f;
        }

    float4 areg[8];
    {
        if (QA){
            #pragma unroll
            for (int v = 0; v < 8; v++){
                int idx = v*256 + tid;
                int r = idx >> 4, c4 = idx & 15;
                areg[v] = *(const float4*)&Af[(long long)(i0 + r)*lda + c4*4];
            }
        } else {
            #pragma unroll
            for (int v = 0; v < 4; v++){
                int idx = v*256 + tid;
                int r = idx >> 3, c8 = idx & 7;
                cpa(&As0[r*PAD + c8*8], &A[(long long)(i0 + r)*lda + c8*8]);
            }
        }
        #pragma unroll
        for (int v = 0; v < 4; v++){
            int idx = v*256 + tid;
            int r = idx >> 3, c8 = idx & 7;
            cpa(&Bs0[r*PAD + c8*8], &Bm[(long long)(j0 + r)*ldb + c8*8]);
        }
        CP_COMMIT;
    }

    int st = 0;
    for (int k0 = 0; k0 < K; k0 += BK){
        bf16* Asc = st ? As1 : As0;
        bf16* Bsc = st ? Bs1 : Bs0;
        if (k0 + BK < K){
            bf16* Asn = st ? As0 : As1;
            bf16* Bsn = st ? Bs0 : Bs1;
            int kn = k0 + BK;
            if (!QA){
                #pragma unroll
                for (int v = 0; v < 4; v++){
                    int idx = v*256 + tid;
                    int r = idx >> 3, c8 = idx & 7;
                    cpa(&Asn[r*PAD + c8*8], &A[(long long)(i0 + r)*lda + kn + c8*8]);
                }
            }
            #pragma unroll
            for (int v = 0; v < 4; v++){
                int idx = v*256 + tid;
                int r = idx >> 3, c8 = idx & 7;
                cpa(&Bsn[r*PAD + c8*8], &Bm[(long long)(j0 + r)*ldb + kn + c8*8]);
            }
            CP_COMMIT;
        }
        if (QA){
            #pragma unroll
            for (int v = 0; v < 8; v++){
                int idx = v*256 + tid;
                int r = idx >> 4, c4 = idx & 15;
                float q0 = quantm(areg[v].x, iA, zA), q1 = quantm(areg[v].y, iA, zA);
                float q2 = quantm(areg[v].z, iA, zA), q3 = quantm(areg[v].w, iA, zA);
                uint2 o; o.x = packbf2(q0,q1); o.y = packbf2(q2,q3);
                *(uint2*)&Asc[r*PAD + c4*4] = o;
            }
            if (k0 + BK < K){
                int kn = k0 + BK;
                #pragma unroll
                for (int v = 0; v < 8; v++){
                    int idx = v*256 + tid;
                    int r = idx >> 4, c4 = idx & 15;
                    areg[v] = *(const float4*)&Af[(long long)(i0 + r)*lda + kn + c4*4];
                }
            }
        }
        if (k0 + BK < K) { CP_WAIT1; } else { CP_WAIT0; }
        __syncthreads();

        #pragma unroll
        for (int kk = 0; kk < BK; kk += 16){
            u32 af[4][4];
            #pragma unroll
            for (int mt = 0; mt < 4; mt++)
                ldsm4(af[mt], &Asc[(wm*64 + mt*16 + l16)*PAD + kk + (lane>>4)*8]);
            u32 bq[2][4];
            #pragma unroll
            for (int np = 0; np < 2; np++)
                ldsm4(bq[np], &Bsc[(wn*32 + np*16 + brow)*PAD + kk + bcol]);
            #pragma unroll
            for (int mt = 0; mt < 4; mt++){
                mma16816(acc[mt][0], af[mt], bq[0]);
                mma16816(acc[mt][1], af[mt], bq[0]+2);
                mma16816(acc[mt][2], af[mt], bq[1]);
                mma16816(acc[mt][3], af[mt], bq[1]+2);
            }
        }
        __syncthreads();
        st ^= 1;
    }

    float mult  = sA * sB;
    float cterm = (zA * zB) * Kconst;

    float lmx = -INFINITY, lmn = INFINITY;

    #pragma unroll
    for (int mt = 0; mt < 4; mt++){
        int row0 = i0 + wm*64 + mt*16 + (lane>>2);
        float rs0 = rowsumA[row0], rs1 = rowsumA[row0+8];
        float p0 = 0.f, p8 = 0.f;
        #pragma unroll
        for (int nt = 0; nt < 4; nt++){
            int col0 = j0 + wn*32 + nt*8 + (lane&3)*2;
            float cs0 = colsumB[col0], cs1 = colsumB[col0+1];
            float b0 = bias ? bias[col0]   : 0.f;
            float b1 = bias ? bias[col0+1] : 0.f;
            float v0 = (acc[mt][nt][0] - cs0*zA - rs0*zB + cterm)*mult + b0;
            float v1 = (acc[mt][nt][1] - cs1*zA - rs0*zB + cterm)*mult + b1;
            float v2 = (acc[mt][nt][2] - cs0*zA - rs1*zB + cterm)*mult + b0;
            float v3 = (acc[mt][nt][3] - cs1*zA - rs1*zB + cterm)*mult + b1;
            C[(long long)row0*ldc + col0]       = v0;
            C[(long long)row0*ldc + col0 + 1]   = v1;
            C[(long long)(row0+8)*ldc + col0]   = v2;
            C[(long long)(row0+8)*ldc + col0+1] = v3;
            if (F1){
                p0 += v0 + v1; p8 += v2 + v3;
                lmx = fmaxf(lmx, fmaxf(fmaxf(v0,v1), fmaxf(v2,v3)));
                lmn = fminf(lmn, fminf(fminf(v0,v1), fminf(v2,v3)));
            }
        }
        if (F1){
            p0 = qsum(p0); p8 = qsum(p8);
            if ((lane & 3) == 0){
                atomicAdd(&g_xqkvsum[row0],   p0);
                atomicAdd(&g_xqkvsum[row0+8], p8);
            }
        }
    }

    if (F1){
        redx[tid] = lmx; redn[tid] = lmn; __syncthreads();
        for (int o = 128; o > 0; o >>= 1){
            if (tid < o){ redx[tid] = fmaxf(redx[tid], redx[tid+o]); redn[tid] = fminf(redn[tid], redn[tid+o]); }
            __syncthreads();
        }
        if (tid == 0){
            int region = blockIdx.x / 6;
            atomicMax(&g_stat[2*(2+region)],   fenc(redx[0]));
            atomicMin(&g_stat[2*(2+region)+1], fenc(redn[0]));
        }
    }
}

// ---------------- launcher ----------------
#define GEMM_SMEM (128*72*2*4 + 2048)

extern "C" void kernel_launch(void* const* d_in, const int* in_sizes, int n_in,
                              void* d_out, int out_size){
    const float *x = 0, *wqkv = 0, *wout = 0, *bout = 0;
    for (int i = 0; i < n_in; i++){
        if      (in_sizes[i] == MROWS*DMODEL)  x    = (const float*)d_in[i];
        else if (in_sizes[i] == J3*DMODEL)     wqkv = (const float*)d_in[i];
        else if (in_sizes[i] == DMODEL*DMODEL) wout = (const float*)d_in[i];
        else if (in_sizes[i] == DMODEL)        bout = (const float*)d_in[i];
    }
    float* out = (float*)d_out;

    bf16 *p_xq, *p_wq1, *p_wq2;
    float *p_xqkv, *p_outbuf;
    float *p_rowsum_x, *p_colsum_w1, *p_colsum_w2, *p_xqkvsum;
    cudaGetSymbolAddress((void**)&p_xq,        g_xq);
    cudaGetSymbolAddress((void**)&p_wq1,       g_wq1);
    cudaGetSymbolAddress((void**)&p_wq2,       g_wq2);
    cudaGetSymbolAddress((void**)&p_xqkv,      g_xqkv);
    cudaGetSymbolAddress((void**)&p_outbuf,    g_outbuf);
    cudaGetSymbolAddress((void**)&p_rowsum_x,  g_rowsum_x);
    cudaGetSymbolAddress((void**)&p_colsum_w1, g_colsum_w1);
    cudaGetSymbolAddress((void**)&p_colsum_w2, g_colsum_w2);
    cudaGetSymbolAddress((void**)&p_xqkvsum,   g_xqkvsum);

    static int smem_set = 0;
    if (!smem_set){
        cudaFuncSetAttribute(k_attn_stats, cudaFuncAttributeMaxDynamicSharedMemorySize, 18432*3 + 2048);
        cudaFuncSetAttribute(k_attn_av,    cudaFuncAttributeMaxDynamicSharedMemorySize, 18432*4 + 2048);
        cudaFuncSetAttribute(k_mma<1,0>,   cudaFuncAttributeMaxDynamicSharedMemorySize, GEMM_SMEM);
        cudaFuncSetAttribute(k_mma<0,1>,   cudaFuncAttributeMaxDynamicSharedMemorySize, GEMM_SMEM);
        smem_set = 1;
    }

    k_init<<<1, 256>>>();
    k_minmax3<<<dim3(768, 3), 256>>>(x, MROWS*DMODEL, 0,
                                     wqkv, J3*DMODEL, 1,
                                     wout, DMODEL*DMODEL, 7);
    k_quantrow3<<<(MROWS+J3+DMODEL)/8, 256>>>(x, wqkv, wout);
    k_mma<1,0><<<dim3(J3/128, MROWS/128), 256, GEMM_SMEM>>>(
        p_xq, (const float*)0, DMODEL, p_wq1, DMODEL, p_xqkv, J3, DMODEL,
        p_colsum_w1, p_rowsum_x, 0, 1, (float)DMODEL, (const float*)0);
    k_pack_qkv<<<dim3(SEQ/8, BHN), 256>>>();
    k_attn_stats<<<dim3(8, BHN), 256, 18432*3 + 2048>>>();
    k_attn_av<<<dim3(8, BHN), 256, 18432*4 + 2048>>>();
    k_mma<0,1><<<dim3(DMODEL/128, MROWS/128), 256, GEMM_SMEM>>>(
        (const bf16*)0, p_outbuf, DMODEL, p_wq2, DMODEL, out, DMODEL, DMODEL,
        p_colsum_w2, p_xqkvsum, 6, 7, (float)J3, bout);
}

// round 16
// speedup vs baseline: 1.6687x; 1.0076x over previous
#include <cuda_runtime.h>
#include <cuda_bf16.h>
#include <cstdint>
#include <cstddef>
#include <math.h>

#define NB      4
#define SEQ     1024
#define DMODEL  768
#define NH      12
#define DHD     64
#define J3      2304
#define MROWS   4096
#define BHN     48

typedef __nv_bfloat16 bf16;
typedef unsigned int  u32;

// ---------------- scratch ----------------
__device__ __align__(16) bf16  g_xq[MROWS*DMODEL];
__device__ __align__(16) bf16  g_wq1[J3*DMODEL];
__device__ __align__(16) bf16  g_wq2[DMODEL*DMODEL];
__device__ __align__(16) float g_xqkv[MROWS*J3];
__device__ __align__(16) bf16  g_qb[BHN*SEQ*DHD];
__device__ __align__(16) bf16  g_kb[BHN*SEQ*DHD];
__device__ __align__(16) bf16  g_vb[BHN*SEQ*DHD];
__device__ __align__(16) float g_outbuf[MROWS*DMODEL];
__device__ float    g_rowsum_x[MROWS];
__device__ float    g_colsum_w1[J3];
__device__ float    g_colsum_w2[DMODEL];
__device__ float    g_xqkvsum[MROWS];
__device__ float    g_rowsumq[BHN*SEQ];
__device__ float    g_colsumk[BHN*SEQ];
__device__ float    g_vcolsum[BHN*DHD];
__device__ float    g_rowm[BHN*SEQ];
__device__ float    g_rowS[BHN*SEQ];
__device__ unsigned g_stat[16];   // slots:0=x 1=w1 2=q 3=k 4=v 5=a 6=out 7=w2

// ---------------- helpers ----------------
__device__ __forceinline__ unsigned fenc(float f){
    unsigned u = __float_as_uint(f);
    return (u & 0x80000000u) ? ~u : (u | 0x80000000u);
}
__device__ __forceinline__ float fdec(unsigned e){
    return (e & 0x80000000u) ? __uint_as_float(e ^ 0x80000000u) : __uint_as_float(~e);
}
__device__ __forceinline__ void get_szi(int slot, float& s, float& z, float& is){
    float mx = fdec(g_stat[2*slot]);
    float mn = fdec(g_stat[2*slot+1]);
    s = __fdiv_rn(mx - mn, 15.0f);
    z = rintf(15.0f - __fdiv_rn(mx, s));
    is = __fdiv_rn(1.0f, s);
}
__device__ __forceinline__ float quantm(float v, float is, float z){
    return rintf(fmaf(v, is, z));
}
__device__ __forceinline__ u32 packbf2(float lo, float hi){
    __nv_bfloat162 t = __floats2bfloat162_rn(lo, hi);
    return *reinterpret_cast<u32*>(&t);
}
__device__ __forceinline__ void ldsm4(u32* r, const void* p){
    u32 a = (u32)__cvta_generic_to_shared(p);
    asm volatile("ldmatrix.sync.aligned.m8n8.x4.shared.b16 {%0,%1,%2,%3},[%4];"
        : "=r"(r[0]),"=r"(r[1]),"=r"(r[2]),"=r"(r[3]) : "r"(a));
}
__device__ __forceinline__ void ldsm4t(u32* r, const void* p){
    u32 a = (u32)__cvta_generic_to_shared(p);
    asm volatile("ldmatrix.sync.aligned.m8n8.x4.trans.shared.b16 {%0,%1,%2,%3},[%4];"
        : "=r"(r[0]),"=r"(r[1]),"=r"(r[2]),"=r"(r[3]) : "r"(a));
}
__device__ __forceinline__ void mma16816(float* c, const u32* a, const u32* b){
    asm volatile("mma.sync.aligned.m16n8k16.row.col.f32.bf16.bf16.f32 "
        "{%0,%1,%2,%3}, {%4,%5,%6,%7}, {%8,%9}, {%0,%1,%2,%3};"
        : "+f"(c[0]),"+f"(c[1]),"+f"(c[2]),"+f"(c[3])
        : "r"(a[0]),"r"(a[1]),"r"(a[2]),"r"(a[3]), "r"(b[0]),"r"(b[1]));
}
__device__ __forceinline__ void cpa(void* s, const void* g){
    u32 a = (u32)__cvta_generic_to_shared(s);
    asm volatile("cp.async.cg.shared.global [%0],[%1],16;" :: "r"(a), "l"(g));
}
#define CP_COMMIT asm volatile("cp.async.commit_group;")
#define CP_WAIT0  asm volatile("cp.async.wait_group 0;")
#define CP_WAIT1  asm volatile("cp.async.wait_group 1;")
#define CP_WAIT2  asm volatile("cp.async.wait_group 2;")

__device__ __forceinline__ float qsum(float v){
    v += __shfl_xor_sync(0xffffffffu, v, 1);
    v += __shfl_xor_sync(0xffffffffu, v, 2);
    return v;
}
__device__ __forceinline__ float qmax(float v){
    v = fmaxf(v, __shfl_xor_sync(0xffffffffu, v, 1));
    v = fmaxf(v, __shfl_xor_sync(0xffffffffu, v, 2));
    return v;
}
__device__ __forceinline__ float qmin(float v){
    v = fminf(v, __shfl_xor_sync(0xffffffffu, v, 1));
    v = fminf(v, __shfl_xor_sync(0xffffffffu, v, 2));
    return v;
}
__device__ __forceinline__ float wsum(float v){
    #pragma unroll
    for (int o = 16; o > 0; o >>= 1) v += __shfl_xor_sync(0xffffffffu, v, o);
    return v;
}

// ---------------- elementwise kernels ----------------
__global__ void k_init(){
    int t = threadIdx.x;
    if (t < 8){ g_stat[2*t] = fenc(-INFINITY); g_stat[2*t+1] = fenc(INFINITY); }
    for (int i = t; i < BHN*DHD; i += blockDim.x) g_vcolsum[i] = 0.f;
    for (int i = t; i < MROWS;   i += blockDim.x) g_xqkvsum[i] = 0.f;
}

__global__ void k_minmax3(const float* __restrict__ pa, int na, int sa_,
                          const float* __restrict__ pb, int nb, int sb_,
                          const float* __restrict__ pc, int nc, int sc_){
    const float* p; int n, slot;
    if (blockIdx.y == 0){ p = pa; n = na; slot = sa_; }
    else if (blockIdx.y == 1){ p = pb; n = nb; slot = sb_; }
    else { p = pc; n = nc; slot = sc_; }
    float mx = -INFINITY, mn = INFINITY;
    int n4 = n >> 2;
    const float4* p4 = (const float4*)p;
    for (int i = blockIdx.x*blockDim.x + threadIdx.x; i < n4; i += gridDim.x*blockDim.x){
        float4 v = p4[i];
        mx = fmaxf(mx, fmaxf(fmaxf(v.x,v.y), fmaxf(v.z,v.w)));
        mn = fminf(mn, fminf(fminf(v.x,v.y), fminf(v.z,v.w)));
    }
    __shared__ float smx[256], smn[256];
    int t = threadIdx.x;
    smx[t] = mx; smn[t] = mn; __syncthreads();
    for (int o = 128; o > 0; o >>= 1){
        if (t < o){ smx[t] = fmaxf(smx[t], smx[t+o]); smn[t] = fminf(smn[t], smn[t+o]); }
        __syncthreads();
    }
    if (t == 0){
        atomicMax(&g_stat[2*slot],   fenc(smx[0]));
        atomicMin(&g_stat[2*slot+1], fenc(smn[0]));
    }
}

// ONE launch quantizing x, w_qkv, w_out (all rowlen 768). Warp-per-row.
__global__ void k_quantrow3(const float* __restrict__ x,
                            const float* __restrict__ w1,
                            const float* __restrict__ w2){
    int warp = threadIdx.x >> 5, lane = threadIdx.x & 31;
    int gr = blockIdx.x*8 + warp;
    const float* src; bf16* dst; float* rsum; int slot; int r;
    if (gr < MROWS){           src = x;  dst = g_xq;  rsum = g_rowsum_x;  slot = 0; r = gr; }
    else if (gr < MROWS+J3){   src = w1; dst = g_wq1; rsum = g_colsum_w1; slot = 1; r = gr - MROWS; }
    else {                     src = w2; dst = g_wq2; rsum = g_colsum_w2; slot = 7; r = gr - MROWS - J3; }
    float s, z, is; get_szi(slot, s, z, is);
    const float4* s4 = (const float4*)(src + (long long)r*DMODEL);
    uint2* d2 = (uint2*)(dst + (long long)r*DMODEL);
    float acc = 0.f;
    #pragma unroll
    for (int i = 0; i < 6; i++){
        float4 v = s4[i*32 + lane];
        float q0 = quantm(v.x, is, z), q1 = quantm(v.y, is, z);
        float q2 = quantm(v.z, is, z), q3 = quantm(v.w, is, z);
        acc += (q0+q1) + (q2+q3);
        uint2 o; o.x = packbf2(q0,q1); o.y = packbf2(q2,q3);
        d2[i*32 + lane] = o;
    }
    acc = wsum(acc);
    if (lane == 0) rsum[r] = acc;
}

// warp-per-token pack of quantized q/k/v; fused token sums + v colsum
__global__ void k_pack_qkv(){
    __shared__ float vsum[64];
    int bh = blockIdx.y;
    int b = bh / NH, h = bh - b*NH;
    int warp = threadIdx.x >> 5, lane = threadIdx.x & 31;
    int n = blockIdx.x*8 + warp;
    if (threadIdx.x < 64) vsum[threadIdx.x] = 0.f;
    __syncthreads();
    float sq, zq, iq, sk, zk, ik, sv, zv, iv;
    get_szi(2, sq, zq, iq); get_szi(3, sk, zk, ik); get_szi(4, sv, zv, iv);
    long long base = (long long)(b*SEQ + n)*J3 + h*DHD + 2*lane;
    float2 qv2 = *(const float2*)&g_xqkv[base];
    float2 kv2 = *(const float2*)&g_xqkv[base + DMODEL];
    float2 vv2 = *(const float2*)&g_xqkv[base + 2*DMODEL];
    float q0 = quantm(qv2.x, iq, zq), q1 = quantm(qv2.y, iq, zq);
    float k0 = quantm(kv2.x, ik, zk), k1 = quantm(kv2.y, ik, zk);
    float v0 = quantm(vv2.x, iv, zv), v1 = quantm(vv2.y, iv, zv);
    long long po = ((long long)bh*SEQ + n)*DHD/2 + lane;
    ((u32*)g_qb)[po] = packbf2(q0, q1);
    ((u32*)g_kb)[po] = packbf2(k0, k1);
    ((u32*)g_vb)[po] = packbf2(v0, v1);
    float qs = wsum(q0 + q1);
    float ks = wsum(k0 + k1);
    if (lane == 0){
        g_rowsumq[bh*SEQ + n] = qs;
        g_colsumk[bh*SEQ + n] = ks;
    }
    atomicAdd(&vsum[2*lane],   v0);
    atomicAdd(&vsum[2*lane+1], v1);
    __syncthreads();
    if (threadIdx.x < 64) atomicAdd(&g_vcolsum[bh*DHD + threadIdx.x], vsum[threadIdx.x]);
}

// ---------------- fused attention: stats pass ----------------
__global__ void __launch_bounds__(256) k_attn_stats(){
    extern __shared__ __align__(16) char smraw[];
    bf16* Qs  = (bf16*)smraw;
    bf16* Ks0 = (bf16*)(smraw + 18432);
    bf16* Ks1 = (bf16*)(smraw + 18432*2);
    float* csk0 = (float*)(smraw + 18432*3);
    float* csk1 = (float*)(smraw + 18432*3 + 512);
    __shared__ float redx[256], redn[256];

    int bh = blockIdx.y, qt = blockIdx.x;
    int tid = threadIdx.x, warp = tid >> 5, lane = tid & 31;
    int l16 = lane & 15;
    int brow = (lane&7) + ((lane>>4)<<3);
    int bcol = ((lane>>3)&1)*8;

    float sq, zq, iq, sk, zk, ik;
    get_szi(2, sq, zq, iq); get_szi(3, sk, zk, ik);
    float s3 = (0.125f * sq) * sk;

    {
        #pragma unroll
        for (int it = 0; it < 4; it++){
            int idx = it*256 + tid;
            int r = idx >> 3, c8 = idx & 7;
            cpa(&Ks0[r*72 + c8*8], &g_kb[((long long)bh*SEQ + r)*DHD + c8*8]);
        }
        if (tid < 32) cpa(&csk0[tid*4], &g_colsumk[bh*SEQ + tid*4]);
        CP_COMMIT;
        #pragma unroll
        for (int it = 0; it < 4; it++){
            int idx = it*256 + tid;
            int r = idx >> 3, c8 = idx & 7;
            cpa(&Qs[r*72 + c8*8], &g_qb[((long long)bh*SEQ + qt*128 + r)*DHD + c8*8]);
        }
        CP_COMMIT;
    }

    int r0 = warp*16 + (lane>>2), r1 = r0 + 8;
    float rsq0 = g_rowsumq[bh*SEQ + qt*128 + r0];
    float rsq1 = g_rowsumq[bh*SEQ + qt*128 + r1];

    float m0 = -INFINITY, m1 = -INFINITY;
    float n0 =  INFINITY, n1 =  INFINITY;
    float S0 = 0.f, S1 = 0.f;

    int st = 0;
    for (int kt = 0; kt < 8; kt++){
        bf16*  Kc  = st ? Ks1 : Ks0;
        float* ckc = st ? csk1 : csk0;
        if (kt < 7){
            bf16*  Kn  = st ? Ks0 : Ks1;
            float* ckn = st ? csk0 : csk1;
            #pragma unroll
            for (int it = 0; it < 4; it++){
                int idx = it*256 + tid;
                int r = idx >> 3, c8 = idx & 7;
                cpa(&Kn[r*72 + c8*8], &g_kb[((long long)bh*SEQ + (kt+1)*128 + r)*DHD + c8*8]);
            }
            if (tid < 32) cpa(&ckn[tid*4], &g_colsumk[bh*SEQ + (kt+1)*128 + tid*4]);
            CP_COMMIT;
            CP_WAIT1;
        } else {
            CP_WAIT0;
        }
        __syncthreads();

        float acc[16][4];
        #pragma unroll
        for (int nt = 0; nt < 16; nt++){ acc[nt][0]=0.f; acc[nt][1]=0.f; acc[nt][2]=0.f; acc[nt][3]=0.f; }
        #pragma unroll
        for (int kk = 0; kk < 64; kk += 16){
            u32 af[4];
            ldsm4(af, &Qs[(warp*16 + l16)*72 + kk + (lane>>4)*8]);
            #pragma unroll
            for (int np = 0; np < 8; np++){
                u32 bq[4];
                ldsm4(bq, &Kc[(np*16 + brow)*72 + kk + bcol]);
                mma16816(acc[2*np],   af, bq);
                mma16816(acc[2*np+1], af, bq+2);
            }
        }

        int c = (lane&3)*2;
        #pragma unroll
        for (int nt = 0; nt < 16; nt++){
            int cg = nt*8 + c;
            float cz0 = ckc[cg]*zq, cz1 = ckc[cg+1]*zq;
            acc[nt][0] = (acc[nt][0] - cz0 - rsq0*zk)*s3;
            acc[nt][1] = (acc[nt][1] - cz1 - rsq0*zk)*s3;
            acc[nt][2] = (acc[nt][2] - cz0 - rsq1*zk)*s3;
            acc[nt][3] = (acc[nt][3] - cz1 - rsq1*zk)*s3;
        }
        float tx0=-INFINITY, tx1=-INFINITY, tn0=INFINITY, tn1=INFINITY;
        #pragma unroll
        for (int nt = 0; nt < 16; nt++){
            tx0 = fmaxf(tx0, fmaxf(acc[nt][0], acc[nt][1]));
            tx1 = fmaxf(tx1, fmaxf(acc[nt][2], acc[nt][3]));
            tn0 = fminf(tn0, fminf(acc[nt][0], acc[nt][1]));
            tn1 = fminf(tn1, fminf(acc[nt][2], acc[nt][3]));
        }
        tx0 = qmax(tx0); tx1 = qmax(tx1);
        tn0 = qmin(tn0); tn1 = qmin(tn1);
        float nm0 = fmaxf(m0, tx0), nm1 = fmaxf(m1, tx1);
        float se0 = 0.f, se1 = 0.f;
        #pragma unroll
        for (int nt = 0; nt < 16; nt++){
            se0 += __expf(acc[nt][0]-nm0) + __expf(acc[nt][1]-nm0);
            se1 += __expf(acc[nt][2]-nm1) + __expf(acc[nt][3]-nm1);
        }
        se0 = qsum(se0); se1 = qsum(se1);
        S0 = S0*__expf(m0-nm0) + se0;  m0 = nm0;  n0 = fminf(n0, tn0);
        S1 = S1*__expf(m1-nm1) + se1;  m1 = nm1;  n1 = fminf(n1, tn1);

        __syncthreads();
        st ^= 1;
    }

    if ((lane & 3) == 0){
        g_rowm[bh*SEQ + qt*128 + r0] = m0;  g_rowS[bh*SEQ + qt*128 + r0] = S0;
        g_rowm[bh*SEQ + qt*128 + r1] = m1;  g_rowS[bh*SEQ + qt*128 + r1] = S1;
    }
    float i0 = __fdiv_rn(1.0f, S0), i1 = __fdiv_rn(1.0f, S1);
    float ax = fmaxf(i0, i1);
    float an = fminf(__expf(n0 - m0)*i0, __expf(n1 - m1)*i1);
    redx[tid] = ax; redn[tid] = an; __syncthreads();
    for (int o = 128; o > 0; o >>= 1){
        if (tid < o){ redx[tid] = fmaxf(redx[tid], redx[tid+o]); redn[tid] = fminf(redn[tid], redn[tid+o]); }
        __syncthreads();
    }
    if (tid == 0){
        atomicMax(&g_stat[10], fenc(redx[0]));
        atomicMin(&g_stat[11], fenc(redn[0]));
    }
}

// ---------------- fused attention: recompute + quantize + AV (+out minmax) ----------------
__global__ void __launch_bounds__(256) k_attn_av(){
    extern __shared__ __align__(16) char smraw[];
    bf16* Qs  = (bf16*)smraw;
    bf16* Ks0 = (bf16*)(smraw + 18432);
    bf16* Ks1 = (bf16*)(smraw + 18432*2);
    bf16* Vs  = (bf16*)(smraw + 18432*3);
    float* csk0 = (float*)(smraw + 18432*4);
    float* csk1 = (float*)(smraw + 18432*4 + 512);
    float* vcs  = (float*)(smraw + 18432*4 + 1024);
    __shared__ float redx[256], redn[256];

    int bh = blockIdx.y, qt = blockIdx.x;
    int b = bh / NH, h = bh - b*NH;
    int tid = threadIdx.x, warp = tid >> 5, lane = tid & 31;
    int l16 = lane & 15;
    int brow = (lane&7) + ((lane>>4)<<3);
    int bcol = ((lane>>3)&1)*8;
    int vrow = (lane&7) + (((lane>>3)&1)<<3);
    int vsel = (lane>>4);

    float sq, zq, iq, sk, zk, ik, sv, zv, iv, sa, za, ia;
    get_szi(2, sq, zq, iq); get_szi(3, sk, zk, ik);
    get_szi(4, sv, zv, iv); get_szi(5, sa, za, ia);
    float s3 = (0.125f * sq) * sk;

    {
        #pragma unroll
        for (int it = 0; it < 4; it++){
            int idx = it*256 + tid;
            int r = idx >> 3, c8 = idx & 7;
            cpa(&Ks0[r*72 + c8*8], &g_kb[((long long)bh*SEQ + r)*DHD + c8*8]);
        }
        if (tid < 32) cpa(&csk0[tid*4], &g_colsumk[bh*SEQ + tid*4]);
        CP_COMMIT;
        #pragma unroll
        for (int it = 0; it < 4; it++){
            int idx = it*256 + tid;
            int r = idx >> 3, c8 = idx & 7;
            cpa(&Qs[r*72 + c8*8], &g_qb[((long long)bh*SEQ + qt*128 + r)*DHD + c8*8]);
        }
        if (tid < 16) cpa(&vcs[tid*4], &g_vcolsum[bh*DHD + tid*4]);
        CP_COMMIT;
    }

    int r0 = warp*16 + (lane>>2), r1 = r0 + 8;
    float rsq0 = g_rowsumq[bh*SEQ + qt*128 + r0];
    float rsq1 = g_rowsumq[bh*SEQ + qt*128 + r1];
    float m0 = g_rowm[bh*SEQ + qt*128 + r0], S0 = g_rowS[bh*SEQ + qt*128 + r0];
    float m1 = g_rowm[bh*SEQ + qt*128 + r1], S1 = g_rowS[bh*SEQ + qt*128 + r1];
    float coef0 = __fdiv_rn(1.0f, S0) * ia;
    float coef1 = __fdiv_rn(1.0f, S1) * ia;

    float oacc[8][4];
    #pragma unroll
    for (int nt = 0; nt < 8; nt++){ oacc[nt][0]=0.f; oacc[nt][1]=0.f; oacc[nt][2]=0.f; oacc[nt][3]=0.f; }
    float aqs0 = 0.f, aqs1 = 0.f;

    int st = 0;
    for (int kt = 0; kt < 8; kt++){
        bf16*  Kc  = st ? Ks1 : Ks0;
        float* ckc = st ? csk1 : csk0;
        if (kt < 7){
            bf16*  Kn  = st ? Ks0 : Ks1;
            float* ckn = st ? csk0 : csk1;
            #pragma unroll
            for (int it = 0; it < 4; it++){
                int idx = it*256 + tid;
                int r = idx >> 3, c8 = idx & 7;
                cpa(&Kn[r*72 + c8*8], &g_kb[((long long)bh*SEQ + (kt+1)*128 + r)*DHD + c8*8]);
            }
            if (tid < 32) cpa(&ckn[tid*4], &g_colsumk[bh*SEQ + (kt+1)*128 + tid*4]);
            CP_COMMIT;
        }
        #pragma unroll
        for (int it = 0; it < 4; it++){
            int idx = it*256 + tid;
            int r = idx >> 3, c8 = idx & 7;
            cpa(&Vs[r*72 + c8*8], &g_vb[((long long)bh*SEQ + kt*128 + r)*DHD + c8*8]);
        }
        CP_COMMIT;
        if (kt < 7) { CP_WAIT2; } else { CP_WAIT1; }
        __syncthreads();

        float acc[16][4];
        #pragma unroll
        for (int nt = 0; nt < 16; nt++){ acc[nt][0]=0.f; acc[nt][1]=0.f; acc[nt][2]=0.f; acc[nt][3]=0.f; }
        #pragma unroll
        for (int kk = 0; kk < 64; kk += 16){
            u32 af[4];
            ldsm4(af, &Qs[(warp*16 + l16)*72 + kk + (lane>>4)*8]);
            #pragma unroll
            for (int np = 0; np < 8; np++){
                u32 bq[4];
                ldsm4(bq, &Kc[(np*16 + brow)*72 + kk + bcol]);
                mma16816(acc[2*np],   af, bq);
                mma16816(acc[2*np+1], af, bq+2);
            }
        }

        int c = (lane&3)*2;
        #pragma unroll
        for (int nt = 0; nt < 16; nt++){
            int cg = nt*8 + c;
            float cz0 = ckc[cg]*zq, cz1 = ckc[cg+1]*zq;
            acc[nt][0] = (acc[nt][0] - cz0 - rsq0*zk)*s3;
            acc[nt][1] = (acc[nt][1] - cz1 - rsq0*zk)*s3;
            acc[nt][2] = (acc[nt][2] - cz0 - rsq1*zk)*s3;
            acc[nt][3] = (acc[nt][3] - cz1 - rsq1*zk)*s3;
        }

        if (kt < 7) { CP_WAIT1; } else { CP_WAIT0; }
        __syncthreads();

        #pragma unroll
        for (int j = 0; j < 8; j++){
            float q00 = rintf(fmaf(__expf(acc[2*j][0]   - m0), coef0, za));
            float q01 = rintf(fmaf(__expf(acc[2*j][1]   - m0), coef0, za));
            float q02 = rintf(fmaf(__expf(acc[2*j][2]   - m1), coef1, za));
            float q03 = rintf(fmaf(__expf(acc[2*j][3]   - m1), coef1, za));
            float q10 = rintf(fmaf(__expf(acc[2*j+1][0] - m0), coef0, za));
            float q11 = rintf(fmaf(__expf(acc[2*j+1][1] - m0), coef0, za));
            float q12 = rintf(fmaf(__expf(acc[2*j+1][2] - m1), coef1, za));
            float q13 = rintf(fmaf(__expf(acc[2*j+1][3] - m1), coef1, za));
            aqs0 += q00 + q01 + q10 + q11;
            aqs1 += q02 + q03 + q12 + q13;
            u32 pa[4];
            pa[0] = packbf2(q00, q01);
            pa[1] = packbf2(q02, q03);
            pa[2] = packbf2(q10, q11);
            pa[3] = packbf2(q12, q13);
            #pragma unroll
            for (int np = 0; np < 4; np++){
                u32 vf[4];
                ldsm4t(vf, &Vs[(16*j + vrow)*72 + (2*np + vsel)*8]);
                mma16816(oacc[2*np],   pa, vf);
                mma16816(oacc[2*np+1], pa, vf+2);
            }
        }
        __syncthreads();
        st ^= 1;
    }

    aqs0 = qsum(aqs0);
    aqs1 = qsum(aqs1);

    float mult  = sa * sv;
    float cterm = (za * zv) * (float)SEQ;
    int c = (lane&3)*2;
    long long ob0 = (long long)(b*SEQ + qt*128 + r0)*DMODEL + h*DHD;
    long long ob1 = (long long)(b*SEQ + qt*128 + r1)*DMODEL + h*DHD;
    float lmx = -INFINITY, lmn = INFINITY;
    #pragma unroll
    for (int nt = 0; nt < 8; nt++){
        int d0 = nt*8 + c;
        float w0 = vcs[d0]*za, w1 = vcs[d0+1]*za;
        float o0 = (oacc[nt][0] - w0 - aqs0*zv + cterm)*mult;
        float o1 = (oacc[nt][1] - w1 - aqs0*zv + cterm)*mult;
        float o2 = (oacc[nt][2] - w0 - aqs1*zv + cterm)*mult;
        float o3 = (oacc[nt][3] - w1 - aqs1*zv + cterm)*mult;
        g_outbuf[ob0 + d0]     = o0;
        g_outbuf[ob0 + d0 + 1] = o1;
        g_outbuf[ob1 + d0]     = o2;
        g_outbuf[ob1 + d0 + 1] = o3;
        lmx = fmaxf(lmx, fmaxf(fmaxf(o0,o1), fmaxf(o2,o3)));
        lmn = fminf(lmn, fminf(fminf(o0,o1), fminf(o2,o3)));
    }
    redx[tid] = lmx; redn[tid] = lmn; __syncthreads();
    for (int o = 128; o > 0; o >>= 1){
        if (tid < o){ redx[tid] = fmaxf(redx[tid], redx[tid+o]); redn[tid] = fminf(redn[tid], redn[tid+o]); }
        __syncthreads();
    }
    if (tid == 0){
        atomicMax(&g_stat[12], fenc(redx[0]));
        atomicMin(&g_stat[13], fenc(redn[0]));
    }
}

// ---------------- GEMM, BK=64, single barrier per chunk ----------------
// A: QA=0 -> bf16 [M][K] cp.async; QA=1 -> f32 Af quantized on the fly (slot 6)
// Loop invariant: at iter c, buffer st holds chunk c (awaited); prefetch of
// chunk c+1 into st^1 is issued AFTER the barrier (all reads of st^1 done).
template<int F1, int QA>
__global__ void __launch_bounds__(256) k_mma(
    const bf16* __restrict__ A, const float* __restrict__ Af, int lda,
    const bf16* __restrict__ Bm, int ldb,
    float* __restrict__ C, int ldc,
    int K,
    const float* __restrict__ colsumB,
    const float* __restrict__ rowsumA,
    int slotA, int slotB, float Kconst,
    const float* __restrict__ bias)
{
    const int BK = 64, PAD = 72;
    extern __shared__ __align__(16) char gsm[];
    bf16* As0 = (bf16*)gsm;
    bf16* As1 = (bf16*)(gsm + 128*PAD*2);
    bf16* Bs0 = (bf16*)(gsm + 128*PAD*4);
    bf16* Bs1 = (bf16*)(gsm + 128*PAD*6);
    float* redx = (float*)(gsm + 128*PAD*8);
    float* redn = redx + 256;

    int i0 = blockIdx.y * 128, j0 = blockIdx.x * 128;
    int tid = threadIdx.x, warp = tid >> 5, lane = tid & 31;
    int wm = warp >> 2, wn = warp & 3;
    int l16 = lane & 15;
    int brow = (lane&7) + ((lane>>4)<<3);
    int bcol = ((lane>>3)&1)*8;

    float sA, zA, iA, sB, zB, iB;
    get_szi(slotA, sA, zA, iA); get_szi(slotB, sB, zB, iB);

    float acc[4][4][4];
    #pragma unroll
    for (int a = 0; a < 4; a++)
        #pragma unroll
        for (int b = 0; b < 4; b++){
            acc[a][b][0]=0.f; acc[a][b][1]=0.f; acc[a][b][2]=0.f; acc[a][b][3]=0.f;
        }

    float4 areg[8];
    // prologue: chunk 0 into buffer 0
    {
        if (QA){
            #pragma unroll
            for (int v = 0; v < 8; v++){
                int idx = v*256 + tid;
                int r = idx >> 4, c4 = idx & 15;
                areg[v] = *(const float4*)&Af[(long long)(i0 + r)*lda + c4*4];
            }
        } else {
            #pragma unroll
            for (int v = 0; v < 4; v++){
                int idx = v*256 + tid;
                int r = idx >> 3, c8 = idx & 7;
                cpa(&As0[r*PAD + c8*8], &A[(long long)(i0 + r)*lda + c8*8]);
            }
        }
        #pragma unroll
        for (int v = 0; v < 4; v++){
            int idx = v*256 + tid;
            int r = idx >> 3, c8 = idx & 7;
            cpa(&Bs0[r*PAD + c8*8], &Bm[(long long)(j0 + r)*ldb + c8*8]);
        }
        CP_COMMIT;
    }

    int st = 0;
    for (int k0 = 0; k0 < K; k0 += BK){
        bf16* Asc = st ? As1 : As0;
        bf16* Bsc = st ? Bs1 : Bs0;
        if (QA){
            // stage chunk c A (quantized) into Asc; readers of Asc finished at prev barrier
            #pragma unroll
            for (int v = 0; v < 8; v++){
                int idx = v*256 + tid;
                int r = idx >> 4, c4 = idx & 15;
                float q0 = quantm(areg[v].x, iA, zA), q1 = quantm(areg[v].y, iA, zA);
                float q2 = quantm(areg[v].z, iA, zA), q3 = quantm(areg[v].w, iA, zA);
                uint2 o; o.x = packbf2(q0,q1); o.y = packbf2(q2,q3);
                *(uint2*)&Asc[r*PAD + c4*4] = o;
            }
        }
        CP_WAIT0;            // chunk c B (and A if !QA) arrived
        __syncthreads();     // also: all reads of buffer st^1 (chunk c-1) done
        if (k0 + BK < K){
            bf16* Asn = st ? As0 : As1;
            bf16* Bsn = st ? Bs0 : Bs1;
            int kn = k0 + BK;
            if (QA){
                #pragma unroll
                for (int v = 0; v < 8; v++){
                    int idx = v*256 + tid;
                    int r = idx >> 4, c4 = idx & 15;
                    areg[v] = *(const float4*)&Af[(long long)(i0 + r)*lda + kn + c4*4];
                }
            } else {
                #pragma unroll
                for (int v = 0; v < 4; v++){
                    int idx = v*256 + tid;
                    int r = idx >> 3, c8 = idx & 7;
                    cpa(&Asn[r*PAD + c8*8], &A[(long long)(i0 + r)*lda + kn + c8*8]);
                }
            }
            #pragma unroll
            for (int v = 0; v < 4; v++){
                int idx = v*256 + tid;
                int r = idx >> 3, c8 = idx & 7;
                cpa(&Bsn[r*PAD + c8*8], &Bm[(long long)(j0 + r)*ldb + kn + c8*8]);
            }
            CP_COMMIT;
        }

        #pragma unroll
        for (int kk = 0; kk < BK; kk += 16){
            u32 af[4][4];
            #pragma unroll
            for (int mt = 0; mt < 4; mt++)
                ldsm4(af[mt], &Asc[(wm*64 + mt*16 + l16)*PAD + kk + (lane>>4)*8]);
            u32 bq[2][4];
            #pragma unroll
            for (int np = 0; np < 2; np++)
                ldsm4(bq[np], &Bsc[(wn*32 + np*16 + brow)*PAD + kk + bcol]);
            #pragma unroll
            for (int mt = 0; mt < 4; mt++){
                mma16816(acc[mt][0], af[mt], bq[0]);
                mma16816(acc[mt][1], af[mt], bq[0]+2);
                mma16816(acc[mt][2], af[mt], bq[1]);
                mma16816(acc[mt][3], af[mt], bq[1]+2);
            }
        }
        st ^= 1;
    }

    float mult  = sA * sB;
    float cterm = (zA * zB) * Kconst;

    float lmx = -INFINITY, lmn = INFINITY;

    #pragma unroll
    for (int mt = 0; mt < 4; mt++){
        int row0 = i0 + wm*64 + mt*16 + (lane>>2);
        float rs0 = rowsumA[row0], rs1 = rowsumA[row0+8];
        float p0 = 0.f, p8 = 0.f;
        #pragma unroll
        for (int nt = 0; nt < 4; nt++){
            int col0 = j0 + wn*32 + nt*8 + (lane&3)*2;
            float cs0 = colsumB[col0], cs1 = colsumB[col0+1];
            float b0 = bias ? bias[col0]   : 0.f;
            float b1 = bias ? bias[col0+1] : 0.f;
            float v0 = (acc[mt][nt][0] - cs0*zA - rs0*zB + cterm)*mult + b0;
            float v1 = (acc[mt][nt][1] - cs1*zA - rs0*zB + cterm)*mult + b1;
            float v2 = (acc[mt][nt][2] - cs0*zA - rs1*zB + cterm)*mult + b0;
            float v3 = (acc[mt][nt][3] - cs1*zA - rs1*zB + cterm)*mult + b1;
            C[(long long)row0*ldc + col0]       = v0;
            C[(long long)row0*ldc + col0 + 1]   = v1;
            C[(long long)(row0+8)*ldc + col0]   = v2;
            C[(long long)(row0+8)*ldc + col0+1] = v3;
            if (F1){
                p0 += v0 + v1; p8 += v2 + v3;
                lmx = fmaxf(lmx, fmaxf(fmaxf(v0,v1), fmaxf(v2,v3)));
                lmn = fminf(lmn, fminf(fminf(v0,v1), fminf(v2,v3)));
            }
        }
        if (F1){
            p0 = qsum(p0); p8 = qsum(p8);
            if ((lane & 3) == 0){
                atomicAdd(&g_xqkvsum[row0],   p0);
                atomicAdd(&g_xqkvsum[row0+8], p8);
            }
        }
    }

    if (F1){
        __syncthreads();   // retire mainloop reads before reusing smem for reduction
        redx[tid] = lmx; redn[tid] = lmn; __syncthreads();
        for (int o = 128; o > 0; o >>= 1){
            if (tid < o){ redx[tid] = fmaxf(redx[tid], redx[tid+o]); redn[tid] = fminf(redn[tid], redn[tid+o]); }
            __syncthreads();
        }
        if (tid == 0){
            int region = blockIdx.x / 6;
            atomicMax(&g_stat[2*(2+region)],   fenc(redx[0]));
            atomicMin(&g_stat[2*(2+region)+1], fenc(redn[0]));
        }
    }
}

// ---------------- launcher ----------------
#define GEMM_SMEM (128*72*2*4 + 2048)

extern "C" void kernel_launch(void* const* d_in, const int* in_sizes, int n_in,
                              void* d_out, int out_size){
    const float *x = 0, *wqkv = 0, *wout = 0, *bout = 0;
    for (int i = 0; i < n_in; i++){
        if      (in_sizes[i] == MROWS*DMODEL)  x    = (const float*)d_in[i];
        else if (in_sizes[i] == J3*DMODEL)     wqkv = (const float*)d_in[i];
        else if (in_sizes[i] == DMODEL*DMODEL) wout = (const float*)d_in[i];
        else if (in_sizes[i] == DMODEL)        bout = (const float*)d_in[i];
    }
    float* out = (float*)d_out;

    bf16 *p_xq, *p_wq1, *p_wq2;
    float *p_xqkv, *p_outbuf;
    float *p_rowsum_x, *p_colsum_w1, *p_colsum_w2, *p_xqkvsum;
    cudaGetSymbolAddress((void**)&p_xq,        g_xq);
    cudaGetSymbolAddress((void**)&p_wq1,       g_wq1);
    cudaGetSymbolAddress((void**)&p_wq2,       g_wq2);
    cudaGetSymbolAddress((void**)&p_xqkv,      g_xqkv);
    cudaGetSymbolAddress((void**)&p_outbuf,    g_outbuf);
    cudaGetSymbolAddress((void**)&p_rowsum_x,  g_rowsum_x);
    cudaGetSymbolAddress((void**)&p_colsum_w1, g_colsum_w1);
    cudaGetSymbolAddress((void**)&p_colsum_w2, g_colsum_w2);
    cudaGetSymbolAddress((void**)&p_xqkvsum,   g_xqkvsum);

    static int smem_set = 0;
    if (!smem_set){
        cudaFuncSetAttribute(k_attn_stats, cudaFuncAttributeMaxDynamicSharedMemorySize, 18432*3 + 2048);
        cudaFuncSetAttribute(k_attn_av,    cudaFuncAttributeMaxDynamicSharedMemorySize, 18432*4 + 2048);
        cudaFuncSetAttribute(k_mma<1,0>,   cudaFuncAttributeMaxDynamicSharedMemorySize, GEMM_SMEM);
        cudaFuncSetAttribute(k_mma<0,1>,   cudaFuncAttributeMaxDynamicSharedMemorySize, GEMM_SMEM);
        smem_set = 1;
    }

    k_init<<<1, 256>>>();
    k_minmax3<<<dim3(768, 3), 256>>>(x, MROWS*DMODEL, 0,
                                     wqkv, J3*DMODEL, 1,
                                     wout, DMODEL*DMODEL, 7);
    k_quantrow3<<<(MROWS+J3+DMODEL)/8, 256>>>(x, wqkv, wout);
    k_mma<1,0><<<dim3(J3/128, MROWS/128), 256, GEMM_SMEM>>>(
        p_xq, (const float*)0, DMODEL, p_wq1, DMODEL, p_xqkv, J3, DMODEL,
        p_colsum_w1, p_rowsum_x, 0, 1, (float)DMODEL, (const float*)0);
    k_pack_qkv<<<dim3(SEQ/8, BHN), 256>>>();
    k_attn_stats<<<dim3(8, BHN), 256, 18432*3 + 2048>>>();
    k_attn_av<<<dim3(8, BHN), 256, 18432*4 + 2048>>>();
    k_mma<0,1><<<dim3(DMODEL/128, MROWS/128), 256, GEMM_SMEM>>>(
        (const bf16*)0, p_outbuf, DMODEL, p_wq2, DMODEL, out, DMODEL, DMODEL,
        p_colsum_w2, p_xqkvsum, 6, 7, (float)J3, bout);
}

// round 17
// speedup vs baseline: 1.6692x; 1.0003x over previous
#include <cuda_runtime.h>
#include <cuda_bf16.h>
#include <cstdint>
#include <cstddef>
#include <math.h>

#define NB      4
#define SEQ     1024
#define DMODEL  768
#define NH      12
#define DHD     64
#define J3      2304
#define MROWS   4096
#define BHN     48

typedef __nv_bfloat16 bf16;
typedef unsigned int  u32;

// ---------------- scratch ----------------
__device__ __align__(16) bf16  g_xq[MROWS*DMODEL];
__device__ __align__(16) bf16  g_wq1[J3*DMODEL];
__device__ __align__(16) bf16  g_wq2[DMODEL*DMODEL];
__device__ __align__(16) float g_xqkv[MROWS*J3];
__device__ __align__(16) bf16  g_qb[BHN*SEQ*DHD];
__device__ __align__(16) bf16  g_kb[BHN*SEQ*DHD];
__device__ __align__(16) bf16  g_vb[BHN*SEQ*DHD];
__device__ __align__(16) float g_outbuf[MROWS*DMODEL];
__device__ float    g_rowsum_x[MROWS];
__device__ float    g_colsum_w1[J3];
__device__ float    g_colsum_w2[DMODEL];
__device__ float    g_xqkvsum[MROWS];
__device__ float    g_rowsumq[BHN*SEQ];
__device__ float    g_colsumk[BHN*SEQ];
__device__ float    g_vcolsum[BHN*DHD];
__device__ float    g_rowm[BHN*SEQ];
__device__ float    g_rowS[BHN*SEQ];
__device__ float    g_pm[2*BHN*SEQ];    // per-z partial row max
__device__ float    g_pS[2*BHN*SEQ];    // per-z partial row sumexp
__device__ float    g_pn[2*BHN*SEQ];    // per-z partial row min
__device__ unsigned g_stat[16];   // slots:0=x 1=w1 2=q 3=k 4=v 5=a 6=out 7=w2

// ---------------- helpers ----------------
__device__ __forceinline__ unsigned fenc(float f){
    unsigned u = __float_as_uint(f);
    return (u & 0x80000000u) ? ~u : (u | 0x80000000u);
}
__device__ __forceinline__ float fdec(unsigned e){
    return (e & 0x80000000u) ? __uint_as_float(e ^ 0x80000000u) : __uint_as_float(~e);
}
__device__ __forceinline__ void get_szi(int slot, float& s, float& z, float& is){
    float mx = fdec(g_stat[2*slot]);
    float mn = fdec(g_stat[2*slot+1]);
    s = __fdiv_rn(mx - mn, 15.0f);
    z = rintf(15.0f - __fdiv_rn(mx, s));
    is = __fdiv_rn(1.0f, s);
}
__device__ __forceinline__ float quantm(float v, float is, float z){
    return rintf(fmaf(v, is, z));
}
__device__ __forceinline__ u32 packbf2(float lo, float hi){
    __nv_bfloat162 t = __floats2bfloat162_rn(lo, hi);
    return *reinterpret_cast<u32*>(&t);
}
__device__ __forceinline__ void ldsm4(u32* r, const void* p){
    u32 a = (u32)__cvta_generic_to_shared(p);
    asm volatile("ldmatrix.sync.aligned.m8n8.x4.shared.b16 {%0,%1,%2,%3},[%4];"
        : "=r"(r[0]),"=r"(r[1]),"=r"(r[2]),"=r"(r[3]) : "r"(a));
}
__device__ __forceinline__ void ldsm4t(u32* r, const void* p){
    u32 a = (u32)__cvta_generic_to_shared(p);
    asm volatile("ldmatrix.sync.aligned.m8n8.x4.trans.shared.b16 {%0,%1,%2,%3},[%4];"
        : "=r"(r[0]),"=r"(r[1]),"=r"(r[2]),"=r"(r[3]) : "r"(a));
}
__device__ __forceinline__ void mma16816(float* c, const u32* a, const u32* b){
    asm volatile("mma.sync.aligned.m16n8k16.row.col.f32.bf16.bf16.f32 "
        "{%0,%1,%2,%3}, {%4,%5,%6,%7}, {%8,%9}, {%0,%1,%2,%3};"
        : "+f"(c[0]),"+f"(c[1]),"+f"(c[2]),"+f"(c[3])
        : "r"(a[0]),"r"(a[1]),"r"(a[2]),"r"(a[3]), "r"(b[0]),"r"(b[1]));
}
__device__ __forceinline__ void cpa(void* s, const void* g){
    u32 a = (u32)__cvta_generic_to_shared(s);
    asm volatile("cp.async.cg.shared.global [%0],[%1],16;" :: "r"(a), "l"(g));
}
#define CP_COMMIT asm volatile("cp.async.commit_group;")
#define CP_WAIT0  asm volatile("cp.async.wait_group 0;")
#define CP_WAIT1  asm volatile("cp.async.wait_group 1;")
#define CP_WAIT2  asm volatile("cp.async.wait_group 2;")

__device__ __forceinline__ float qsum(float v){
    v += __shfl_xor_sync(0xffffffffu, v, 1);
    v += __shfl_xor_sync(0xffffffffu, v, 2);
    return v;
}
__device__ __forceinline__ float qmax(float v){
    v = fmaxf(v, __shfl_xor_sync(0xffffffffu, v, 1));
    v = fmaxf(v, __shfl_xor_sync(0xffffffffu, v, 2));
    return v;
}
__device__ __forceinline__ float qmin(float v){
    v = fminf(v, __shfl_xor_sync(0xffffffffu, v, 1));
    v = fminf(v, __shfl_xor_sync(0xffffffffu, v, 2));
    return v;
}
__device__ __forceinline__ float wsum(float v){
    #pragma unroll
    for (int o = 16; o > 0; o >>= 1) v += __shfl_xor_sync(0xffffffffu, v, o);
    return v;
}

// ---------------- elementwise kernels ----------------
__global__ void k_init(){
    int t = threadIdx.x;
    if (t < 8){ g_stat[2*t] = fenc(-INFINITY); g_stat[2*t+1] = fenc(INFINITY); }
    for (int i = t; i < BHN*DHD; i += blockDim.x) g_vcolsum[i] = 0.f;
    for (int i = t; i < MROWS;   i += blockDim.x) g_xqkvsum[i] = 0.f;
}

__global__ void k_minmax3(const float* __restrict__ pa, int na, int sa_,
                          const float* __restrict__ pb, int nb, int sb_,
                          const float* __restrict__ pc, int nc, int sc_){
    const float* p; int n, slot;
    if (blockIdx.y == 0){ p = pa; n = na; slot = sa_; }
    else if (blockIdx.y == 1){ p = pb; n = nb; slot = sb_; }
    else { p = pc; n = nc; slot = sc_; }
    float mx = -INFINITY, mn = INFINITY;
    int n4 = n >> 2;
    const float4* p4 = (const float4*)p;
    for (int i = blockIdx.x*blockDim.x + threadIdx.x; i < n4; i += gridDim.x*blockDim.x){
        float4 v = p4[i];
        mx = fmaxf(mx, fmaxf(fmaxf(v.x,v.y), fmaxf(v.z,v.w)));
        mn = fminf(mn, fminf(fminf(v.x,v.y), fminf(v.z,v.w)));
    }
    __shared__ float smx[256], smn[256];
    int t = threadIdx.x;
    smx[t] = mx; smn[t] = mn; __syncthreads();
    for (int o = 128; o > 0; o >>= 1){
        if (t < o){ smx[t] = fmaxf(smx[t], smx[t+o]); smn[t] = fminf(smn[t], smn[t+o]); }
        __syncthreads();
    }
    if (t == 0){
        atomicMax(&g_stat[2*slot],   fenc(smx[0]));
        atomicMin(&g_stat[2*slot+1], fenc(smn[0]));
    }
}

// ONE launch quantizing x, w_qkv, w_out (all rowlen 768). Warp-per-row.
__global__ void k_quantrow3(const float* __restrict__ x,
                            const float* __restrict__ w1,
                            const float* __restrict__ w2){
    int warp = threadIdx.x >> 5, lane = threadIdx.x & 31;
    int gr = blockIdx.x*8 + warp;
    const float* src; bf16* dst; float* rsum; int slot; int r;
    if (gr < MROWS){           src = x;  dst = g_xq;  rsum = g_rowsum_x;  slot = 0; r = gr; }
    else if (gr < MROWS+J3){   src = w1; dst = g_wq1; rsum = g_colsum_w1; slot = 1; r = gr - MROWS; }
    else {                     src = w2; dst = g_wq2; rsum = g_colsum_w2; slot = 7; r = gr - MROWS - J3; }
    float s, z, is; get_szi(slot, s, z, is);
    const float4* s4 = (const float4*)(src + (long long)r*DMODEL);
    uint2* d2 = (uint2*)(dst + (long long)r*DMODEL);
    float acc = 0.f;
    #pragma unroll
    for (int i = 0; i < 6; i++){
        float4 v = s4[i*32 + lane];
        float q0 = quantm(v.x, is, z), q1 = quantm(v.y, is, z);
        float q2 = quantm(v.z, is, z), q3 = quantm(v.w, is, z);
        acc += (q0+q1) + (q2+q3);
        uint2 o; o.x = packbf2(q0,q1); o.y = packbf2(q2,q3);
        d2[i*32 + lane] = o;
    }
    acc = wsum(acc);
    if (lane == 0) rsum[r] = acc;
}

// warp-per-token pack of quantized q/k/v; fused token sums + v colsum
__global__ void k_pack_qkv(){
    __shared__ float vsum[64];
    int bh = blockIdx.y;
    int b = bh / NH, h = bh - b*NH;
    int warp = threadIdx.x >> 5, lane = threadIdx.x & 31;
    int n = blockIdx.x*8 + warp;
    if (threadIdx.x < 64) vsum[threadIdx.x] = 0.f;
    __syncthreads();
    float sq, zq, iq, sk, zk, ik, sv, zv, iv;
    get_szi(2, sq, zq, iq); get_szi(3, sk, zk, ik); get_szi(4, sv, zv, iv);
    long long base = (long long)(b*SEQ + n)*J3 + h*DHD + 2*lane;
    float2 qv2 = *(const float2*)&g_xqkv[base];
    float2 kv2 = *(const float2*)&g_xqkv[base + DMODEL];
    float2 vv2 = *(const float2*)&g_xqkv[base + 2*DMODEL];
    float q0 = quantm(qv2.x, iq, zq), q1 = quantm(qv2.y, iq, zq);
    float k0 = quantm(kv2.x, ik, zk), k1 = quantm(kv2.y, ik, zk);
    float v0 = quantm(vv2.x, iv, zv), v1 = quantm(vv2.y, iv, zv);
    long long po = ((long long)bh*SEQ + n)*DHD/2 + lane;
    ((u32*)g_qb)[po] = packbf2(q0, q1);
    ((u32*)g_kb)[po] = packbf2(k0, k1);
    ((u32*)g_vb)[po] = packbf2(v0, v1);
    float qs = wsum(q0 + q1);
    float ks = wsum(k0 + k1);
    if (lane == 0){
        g_rowsumq[bh*SEQ + n] = qs;
        g_colsumk[bh*SEQ + n] = ks;
    }
    atomicAdd(&vsum[2*lane],   v0);
    atomicAdd(&vsum[2*lane+1], v1);
    __syncthreads();
    if (threadIdx.x < 64) atomicAdd(&g_vcolsum[bh*DHD + threadIdx.x], vsum[threadIdx.x]);
}

// ---------------- fused attention: stats pass, K-split z in {0,1} ----------------
// Each block handles 4 of 8 K-tiles; writes partial (m, S, mn) per row.
__global__ void __launch_bounds__(256) k_attn_stats(){
    extern __shared__ __align__(16) char smraw[];
    bf16* Qs  = (bf16*)smraw;
    bf16* Ks0 = (bf16*)(smraw + 18432);
    bf16* Ks1 = (bf16*)(smraw + 18432*2);
    float* csk0 = (float*)(smraw + 18432*3);
    float* csk1 = (float*)(smraw + 18432*3 + 512);

    int bh = blockIdx.y, qt = blockIdx.x, zz = blockIdx.z;
    int kt_lo = zz*4;
    int tid = threadIdx.x, warp = tid >> 5, lane = tid & 31;
    int l16 = lane & 15;
    int brow = (lane&7) + ((lane>>4)<<3);
    int bcol = ((lane>>3)&1)*8;

    float sq, zq, iq, sk, zk, ik;
    get_szi(2, sq, zq, iq); get_szi(3, sk, zk, ik);
    float s3 = (0.125f * sq) * sk;

    // prologue: Q + K(kt_lo) + csk in ONE commit group
    {
        #pragma unroll
        for (int it = 0; it < 4; it++){
            int idx = it*256 + tid;
            int r = idx >> 3, c8 = idx & 7;
            cpa(&Qs[r*72 + c8*8], &g_qb[((long long)bh*SEQ + qt*128 + r)*DHD + c8*8]);
        }
        #pragma unroll
        for (int it = 0; it < 4; it++){
            int idx = it*256 + tid;
            int r = idx >> 3, c8 = idx & 7;
            cpa(&Ks0[r*72 + c8*8], &g_kb[((long long)bh*SEQ + kt_lo*128 + r)*DHD + c8*8]);
        }
        if (tid < 32) cpa(&csk0[tid*4], &g_colsumk[bh*SEQ + kt_lo*128 + tid*4]);
        CP_COMMIT;
    }

    int r0 = warp*16 + (lane>>2), r1 = r0 + 8;
    float rsq0 = g_rowsumq[bh*SEQ + qt*128 + r0];
    float rsq1 = g_rowsumq[bh*SEQ + qt*128 + r1];

    float m0 = -INFINITY, m1 = -INFINITY;
    float n0 =  INFINITY, n1 =  INFINITY;
    float S0 = 0.f, S1 = 0.f;

    for (int t = 0; t < 4; t++){
        bf16*  Kc  = (t & 1) ? Ks1 : Ks0;
        float* ckc = (t & 1) ? csk1 : csk0;
        CP_WAIT0;            // chunk t arrived
        __syncthreads();     // and all reads of the other buffer (t-1) finished
        if (t < 3){
            bf16*  Kn  = (t & 1) ? Ks0 : Ks1;
            float* ckn = (t & 1) ? csk0 : csk1;
            int kt = kt_lo + t + 1;
            #pragma unroll
            for (int it = 0; it < 4; it++){
                int idx = it*256 + tid;
                int r = idx >> 3, c8 = idx & 7;
                cpa(&Kn[r*72 + c8*8], &g_kb[((long long)bh*SEQ + kt*128 + r)*DHD + c8*8]);
            }
            if (tid < 32) cpa(&ckn[tid*4], &g_colsumk[bh*SEQ + kt*128 + tid*4]);
            CP_COMMIT;
        }

        float acc[16][4];
        #pragma unroll
        for (int nt = 0; nt < 16; nt++){ acc[nt][0]=0.f; acc[nt][1]=0.f; acc[nt][2]=0.f; acc[nt][3]=0.f; }
        #pragma unroll
        for (int kk = 0; kk < 64; kk += 16){
            u32 af[4];
            ldsm4(af, &Qs[(warp*16 + l16)*72 + kk + (lane>>4)*8]);
            #pragma unroll
            for (int np = 0; np < 8; np++){
                u32 bq[4];
                ldsm4(bq, &Kc[(np*16 + brow)*72 + kk + bcol]);
                mma16816(acc[2*np],   af, bq);
                mma16816(acc[2*np+1], af, bq+2);
            }
        }

        int c = (lane&3)*2;
        #pragma unroll
        for (int nt = 0; nt < 16; nt++){
            int cg = nt*8 + c;
            float cz0 = ckc[cg]*zq, cz1 = ckc[cg+1]*zq;
            acc[nt][0] = (acc[nt][0] - cz0 - rsq0*zk)*s3;
            acc[nt][1] = (acc[nt][1] - cz1 - rsq0*zk)*s3;
            acc[nt][2] = (acc[nt][2] - cz0 - rsq1*zk)*s3;
            acc[nt][3] = (acc[nt][3] - cz1 - rsq1*zk)*s3;
        }
        float tx0=-INFINITY, tx1=-INFINITY, tn0=INFINITY, tn1=INFINITY;
        #pragma unroll
        for (int nt = 0; nt < 16; nt++){
            tx0 = fmaxf(tx0, fmaxf(acc[nt][0], acc[nt][1]));
            tx1 = fmaxf(tx1, fmaxf(acc[nt][2], acc[nt][3]));
            tn0 = fminf(tn0, fminf(acc[nt][0], acc[nt][1]));
            tn1 = fminf(tn1, fminf(acc[nt][2], acc[nt][3]));
        }
        tx0 = qmax(tx0); tx1 = qmax(tx1);
        tn0 = qmin(tn0); tn1 = qmin(tn1);
        float nm0 = fmaxf(m0, tx0), nm1 = fmaxf(m1, tx1);
        float se0 = 0.f, se1 = 0.f;
        #pragma unroll
        for (int nt = 0; nt < 16; nt++){
            se0 += __expf(acc[nt][0]-nm0) + __expf(acc[nt][1]-nm0);
            se1 += __expf(acc[nt][2]-nm1) + __expf(acc[nt][3]-nm1);
        }
        se0 = qsum(se0); se1 = qsum(se1);
        S0 = S0*__expf(m0-nm0) + se0;  m0 = nm0;  n0 = fminf(n0, tn0);
        S1 = S1*__expf(m1-nm1) + se1;  m1 = nm1;  n1 = fminf(n1, tn1);
    }

    if ((lane & 3) == 0){
        int ro0 = zz*BHN*SEQ + bh*SEQ + qt*128 + r0;
        int ro1 = zz*BHN*SEQ + bh*SEQ + qt*128 + r1;
        g_pm[ro0] = m0;  g_pS[ro0] = S0;  g_pn[ro0] = n0;
        g_pm[ro1] = m1;  g_pS[ro1] = S1;  g_pn[ro1] = n1;
    }
}

// combine partials -> g_rowm/g_rowS, slot-5 min/max atomics
__global__ void k_comb(){
    __shared__ float redx[256], redn[256];
    int i = blockIdx.x*256 + threadIdx.x;   // row index in [0, BHN*SEQ)
    float m0 = g_pm[i],            S0 = g_pS[i],            n0 = g_pn[i];
    float m1 = g_pm[BHN*SEQ + i],  S1 = g_pS[BHN*SEQ + i],  n1 = g_pn[BHN*SEQ + i];
    float m = fmaxf(m0, m1);
    float S = S0*__expf(m0 - m) + S1*__expf(m1 - m);
    float n = fminf(n0, n1);
    g_rowm[i] = m;
    g_rowS[i] = S;
    float iS = __fdiv_rn(1.0f, S);
    float ax = iS;
    float an = __expf(n - m)*iS;
    int t = threadIdx.x;
    redx[t] = ax; redn[t] = an; __syncthreads();
    for (int o = 128; o > 0; o >>= 1){
        if (t < o){ redx[t] = fmaxf(redx[t], redx[t+o]); redn[t] = fminf(redn[t], redn[t+o]); }
        __syncthreads();
    }
    if (t == 0){
        atomicMax(&g_stat[10], fenc(redx[0]));
        atomicMin(&g_stat[11], fenc(redn[0]));
    }
}

// ---------------- fused attention: recompute + quantize + AV (+out minmax) ----------------
__global__ void __launch_bounds__(256) k_attn_av(){
    extern __shared__ __align__(16) char smraw[];
    bf16* Qs  = (bf16*)smraw;
    bf16* Ks0 = (bf16*)(smraw + 18432);
    bf16* Ks1 = (bf16*)(smraw + 18432*2);
    bf16* Vs  = (bf16*)(smraw + 18432*3);
    float* csk0 = (float*)(smraw + 18432*4);
    float* csk1 = (float*)(smraw + 18432*4 + 512);
    float* vcs  = (float*)(smraw + 18432*4 + 1024);
    __shared__ float redx[256], redn[256];

    int bh = blockIdx.y, qt = blockIdx.x;
    int b = bh / NH, h = bh - b*NH;
    int tid = threadIdx.x, warp = tid >> 5, lane = tid & 31;
    int l16 = lane & 15;
    int brow = (lane&7) + ((lane>>4)<<3);
    int bcol = ((lane>>3)&1)*8;
    int vrow = (lane&7) + (((lane>>3)&1)<<3);
    int vsel = (lane>>4);

    float sq, zq, iq, sk, zk, ik, sv, zv, iv, sa, za, ia;
    get_szi(2, sq, zq, iq); get_szi(3, sk, zk, ik);
    get_szi(4, sv, zv, iv); get_szi(5, sa, za, ia);
    float s3 = (0.125f * sq) * sk;

    {
        #pragma unroll
        for (int it = 0; it < 4; it++){
            int idx = it*256 + tid;
            int r = idx >> 3, c8 = idx & 7;
            cpa(&Ks0[r*72 + c8*8], &g_kb[((long long)bh*SEQ + r)*DHD + c8*8]);
        }
        if (tid < 32) cpa(&csk0[tid*4], &g_colsumk[bh*SEQ + tid*4]);
        CP_COMMIT;
        #pragma unroll
        for (int it = 0; it < 4; it++){
            int idx = it*256 + tid;
            int r = idx >> 3, c8 = idx & 7;
            cpa(&Qs[r*72 + c8*8], &g_qb[((long long)bh*SEQ + qt*128 + r)*DHD + c8*8]);
        }
        if (tid < 16) cpa(&vcs[tid*4], &g_vcolsum[bh*DHD + tid*4]);
        CP_COMMIT;
    }

    int r0 = warp*16 + (lane>>2), r1 = r0 + 8;
    float rsq0 = g_rowsumq[bh*SEQ + qt*128 + r0];
    float rsq1 = g_rowsumq[bh*SEQ + qt*128 + r1];
    float m0 = g_rowm[bh*SEQ + qt*128 + r0], S0 = g_rowS[bh*SEQ + qt*128 + r0];
    float m1 = g_rowm[bh*SEQ + qt*128 + r1], S1 = g_rowS[bh*SEQ + qt*128 + r1];
    float coef0 = __fdiv_rn(1.0f, S0) * ia;
    float coef1 = __fdiv_rn(1.0f, S1) * ia;

    float oacc[8][4];
    #pragma unroll
    for (int nt = 0; nt < 8; nt++){ oacc[nt][0]=0.f; oacc[nt][1]=0.f; oacc[nt][2]=0.f; oacc[nt][3]=0.f; }
    float aqs0 = 0.f, aqs1 = 0.f;

    int st = 0;
    for (int kt = 0; kt < 8; kt++){
        bf16*  Kc  = st ? Ks1 : Ks0;
        float* ckc = st ? csk1 : csk0;
        if (kt < 7){
            bf16*  Kn  = st ? Ks0 : Ks1;
            float* ckn = st ? csk0 : csk1;
            #pragma unroll
            for (int it = 0; it < 4; it++){
                int idx = it*256 + tid;
                int r = idx >> 3, c8 = idx & 7;
                cpa(&Kn[r*72 + c8*8], &g_kb[((long long)bh*SEQ + (kt+1)*128 + r)*DHD + c8*8]);
            }
            if (tid < 32) cpa(&ckn[tid*4], &g_colsumk[bh*SEQ + (kt+1)*128 + tid*4]);
            CP_COMMIT;
        }
        #pragma unroll
        for (int it = 0; it < 4; it++){
            int idx = it*256 + tid;
            int r = idx >> 3, c8 = idx & 7;
            cpa(&Vs[r*72 + c8*8], &g_vb[((long long)bh*SEQ + kt*128 + r)*DHD + c8*8]);
        }
        CP_COMMIT;
        if (kt < 7) { CP_WAIT2; } else { CP_WAIT1; }
        __syncthreads();

        float acc[16][4];
        #pragma unroll
        for (int nt = 0; nt < 16; nt++){ acc[nt][0]=0.f; acc[nt][1]=0.f; acc[nt][2]=0.f; acc[nt][3]=0.f; }
        #pragma unroll
        for (int kk = 0; kk < 64; kk += 16){
            u32 af[4];
            ldsm4(af, &Qs[(warp*16 + l16)*72 + kk + (lane>>4)*8]);
            #pragma unroll
            for (int np = 0; np < 8; np++){
                u32 bq[4];
                ldsm4(bq, &Kc[(np*16 + brow)*72 + kk + bcol]);
                mma16816(acc[2*np],   af, bq);
                mma16816(acc[2*np+1], af, bq+2);
            }
        }

        int c = (lane&3)*2;
        #pragma unroll
        for (int nt = 0; nt < 16; nt++){
            int cg = nt*8 + c;
            float cz0 = ckc[cg]*zq, cz1 = ckc[cg+1]*zq;
            acc[nt][0] = (acc[nt][0] - cz0 - rsq0*zk)*s3;
            acc[nt][1] = (acc[nt][1] - cz1 - rsq0*zk)*s3;
            acc[nt][2] = (acc[nt][2] - cz0 - rsq1*zk)*s3;
            acc[nt][3] = (acc[nt][3] - cz1 - rsq1*zk)*s3;
        }

        if (kt < 7) { CP_WAIT1; } else { CP_WAIT0; }
        __syncthreads();

        #pragma unroll
        for (int j = 0; j < 8; j++){
            float q00 = rintf(fmaf(__expf(acc[2*j][0]   - m0), coef0, za));
            float q01 = rintf(fmaf(__expf(acc[2*j][1]   - m0), coef0, za));
            float q02 = rintf(fmaf(__expf(acc[2*j][2]   - m1), coef1, za));
            float q03 = rintf(fmaf(__expf(acc[2*j][3]   - m1), coef1, za));
            float q10 = rintf(fmaf(__expf(acc[2*j+1][0] - m0), coef0, za));
            float q11 = rintf(fmaf(__expf(acc[2*j+1][1] - m0), coef0, za));
            float q12 = rintf(fmaf(__expf(acc[2*j+1][2] - m1), coef1, za));
            float q13 = rintf(fmaf(__expf(acc[2*j+1][3] - m1), coef1, za));
            aqs0 += q00 + q01 + q10 + q11;
            aqs1 += q02 + q03 + q12 + q13;
            u32 pa[4];
            pa[0] = packbf2(q00, q01);
            pa[1] = packbf2(q02, q03);
            pa[2] = packbf2(q10, q11);
            pa[3] = packbf2(q12, q13);
            #pragma unroll
            for (int np = 0; np < 4; np++){
                u32 vf[4];
                ldsm4t(vf, &Vs[(16*j + vrow)*72 + (2*np + vsel)*8]);
                mma16816(oacc[2*np],   pa, vf);
                mma16816(oacc[2*np+1], pa, vf+2);
            }
        }
        __syncthreads();
        st ^= 1;
    }

    aqs0 = qsum(aqs0);
    aqs1 = qsum(aqs1);

    float mult  = sa * sv;
    float cterm = (za * zv) * (float)SEQ;
    int c = (lane&3)*2;
    long long ob0 = (long long)(b*SEQ + qt*128 + r0)*DMODEL + h*DHD;
    long long ob1 = (long long)(b*SEQ + qt*128 + r1)*DMODEL + h*DHD;
    float lmx = -INFINITY, lmn = INFINITY;
    #pragma unroll
    for (int nt = 0; nt < 8; nt++){
        int d0 = nt*8 + c;
        float w0 = vcs[d0]*za, w1 = vcs[d0+1]*za;
        float o0 = (oacc[nt][0] - w0 - aqs0*zv + cterm)*mult;
        float o1 = (oacc[nt][1] - w1 - aqs0*zv + cterm)*mult;
        float o2 = (oacc[nt][2] - w0 - aqs1*zv + cterm)*mult;
        float o3 = (oacc[nt][3] - w1 - aqs1*zv + cterm)*mult;
        g_outbuf[ob0 + d0]     = o0;
        g_outbuf[ob0 + d0 + 1] = o1;
        g_outbuf[ob1 + d0]     = o2;
        g_outbuf[ob1 + d0 + 1] = o3;
        lmx = fmaxf(lmx, fmaxf(fmaxf(o0,o1), fmaxf(o2,o3)));
        lmn = fminf(lmn, fminf(fminf(o0,o1), fminf(o2,o3)));
    }
    redx[tid] = lmx; redn[tid] = lmn; __syncthreads();
    for (int o = 128; o > 0; o >>= 1){
        if (tid < o){ redx[tid] = fmaxf(redx[tid], redx[tid+o]); redn[tid] = fminf(redn[tid], redn[tid+o]); }
        __syncthreads();
    }
    if (tid == 0){
        atomicMax(&g_stat[12], fenc(redx[0]));
        atomicMin(&g_stat[13], fenc(redn[0]));
    }
}

// ---------------- GEMM, BK=64, single barrier per chunk ----------------
template<int F1, int QA>
__global__ void __launch_bounds__(256) k_mma(
    const bf16* __restrict__ A, const float* __restrict__ Af, int lda,
    const bf16* __restrict__ Bm, int ldb,
    float* __restrict__ C, int ldc,
    int K,
    const float* __restrict__ colsumB,
    const float* __restrict__ rowsumA,
    int slotA, int slotB, float Kconst,
    const float* __restrict__ bias)
{
    const int BK = 64, PAD = 72;
    extern __shared__ __align__(16) char gsm[];
    bf16* As0 = (bf16*)gsm;
    bf16* As1 = (bf16*)(gsm + 128*PAD*2);
    bf16* Bs0 = (bf16*)(gsm + 128*PAD*4);
    bf16* Bs1 = (bf16*)(gsm + 128*PAD*6);
    float* redx = (float*)(gsm + 128*PAD*8);
    float* redn = redx + 256;

    int i0 = blockIdx.y * 128, j0 = blockIdx.x * 128;
    int tid = threadIdx.x, warp = tid >> 5, lane = tid & 31;
    int wm = warp >> 2, wn = warp & 3;
    int l16 = lane & 15;
    int brow = (lane&7) + ((lane>>4)<<3);
    int bcol = ((lane>>3)&1)*8;

    float sA, zA, iA, sB, zB, iB;
    get_szi(slotA, sA, zA, iA); get_szi(slotB, sB, zB, iB);

    float acc[4][4][4];
    #pragma unroll
    for (int a = 0; a < 4; a++)
        #pragma unroll
        for (int b = 0; b < 4; b++){
            acc[a][b][0]=0.f; acc[a][b][1]=0.f; acc[a][b][2]=0.f; acc[a][b][3]=0.f;
        }

    float4 areg[8];
    {
        if (QA){
            #pragma unroll
            for (int v = 0; v < 8; v++){
                int idx = v*256 + tid;
                int r = idx >> 4, c4 = idx & 15;
                areg[v] = *(const float4*)&Af[(long long)(i0 + r)*lda + c4*4];
            }
        } else {
            #pragma unroll
            for (int v = 0; v < 4; v++){
                int idx = v*256 + tid;
                int r = idx >> 3, c8 = idx & 7;
                cpa(&As0[r*PAD + c8*8], &A[(long long)(i0 + r)*lda + c8*8]);
            }
        }
        #pragma unroll
        for (int v = 0; v < 4; v++){
            int idx = v*256 + tid;
            int r = idx >> 3, c8 = idx & 7;
            cpa(&Bs0[r*PAD + c8*8], &Bm[(long long)(j0 + r)*ldb + c8*8]);
        }
        CP_COMMIT;
    }

    int st = 0;
    for (int k0 = 0; k0 < K; k0 += BK){
        bf16* Asc = st ? As1 : As0;
        bf16* Bsc = st ? Bs1 : Bs0;
        if (QA){
            #pragma unroll
            for (int v = 0; v < 8; v++){
                int idx = v*256 + tid;
                int r = idx >> 4, c4 = idx & 15;
                float q0 = quantm(areg[v].x, iA, zA), q1 = quantm(areg[v].y, iA, zA);
                float q2 = quantm(areg[v].z, iA, zA), q3 = quantm(areg[v].w, iA, zA);
                uint2 o; o.x = packbf2(q0,q1); o.y = packbf2(q2,q3);
                *(uint2*)&Asc[r*PAD + c4*4] = o;
            }
        }
        CP_WAIT0;
        __syncthreads();
        if (k0 + BK < K){
            bf16* Asn = st ? As0 : As1;
            bf16* Bsn = st ? Bs0 : Bs1;
            int kn = k0 + BK;
            if (QA){
                #pragma unroll
                for (int v = 0; v < 8; v++){
                    int idx = v*256 + tid;
                    int r = idx >> 4, c4 = idx & 15;
                    areg[v] = *(const float4*)&Af[(long long)(i0 + r)*lda + kn + c4*4];
                }
            } else {
                #pragma unroll
                for (int v = 0; v < 4; v++){
                    int idx = v*256 + tid;
                    int r = idx >> 3, c8 = idx & 7;
                    cpa(&Asn[r*PAD + c8*8], &A[(long long)(i0 + r)*lda + kn + c8*8]);
                }
            }
            #pragma unroll
            for (int v = 0; v < 4; v++){
                int idx = v*256 + tid;
                int r = idx >> 3, c8 = idx & 7;
                cpa(&Bsn[r*PAD + c8*8], &Bm[(long long)(j0 + r)*ldb + kn + c8*8]);
            }
            CP_COMMIT;
        }

        #pragma unroll
        for (int kk = 0; kk < BK; kk += 16){
            u32 af[4][4];
            #pragma unroll
            for (int mt = 0; mt < 4; mt++)
                ldsm4(af[mt], &Asc[(wm*64 + mt*16 + l16)*PAD + kk + (lane>>4)*8]);
            u32 bq[2][4];
            #pragma unroll
            for (int np = 0; np < 2; np++)
                ldsm4(bq[np], &Bsc[(wn*32 + np*16 + brow)*PAD + kk + bcol]);
            #pragma unroll
            for (int mt = 0; mt < 4; mt++){
                mma16816(acc[mt][0], af[mt], bq[0]);
                mma16816(acc[mt][1], af[mt], bq[0]+2);
                mma16816(acc[mt][2], af[mt], bq[1]);
                mma16816(acc[mt][3], af[mt], bq[1]+2);
            }
        }
        st ^= 1;
    }

    float mult  = sA * sB;
    float cterm = (zA * zB) * Kconst;

    float lmx = -INFINITY, lmn = INFINITY;

    #pragma unroll
    for (int mt = 0; mt < 4; mt++){
        int row0 = i0 + wm*64 + mt*16 + (lane>>2);
        float rs0 = rowsumA[row0], rs1 = rowsumA[row0+8];
        float p0 = 0.f, p8 = 0.f;
        #pragma unroll
        for (int nt = 0; nt < 4; nt++){
            int col0 = j0 + wn*32 + nt*8 + (lane&3)*2;
            float cs0 = colsumB[col0], cs1 = colsumB[col0+1];
            float b0 = bias ? bias[col0]   : 0.f;
            float b1 = bias ? bias[col0+1] : 0.f;
            float v0 = (acc[mt][nt][0] - cs0*zA - rs0*zB + cterm)*mult + b0;
            float v1 = (acc[mt][nt][1] - cs1*zA - rs0*zB + cterm)*mult + b1;
            float v2 = (acc[mt][nt][2] - cs0*zA - rs1*zB + cterm)*mult + b0;
            float v3 = (acc[mt][nt][3] - cs1*zA - rs1*zB + cterm)*mult + b1;
            C[(long long)row0*ldc + col0]       = v0;
            C[(long long)row0*ldc + col0 + 1]   = v1;
            C[(long long)(row0+8)*ldc + col0]   = v2;
            C[(long long)(row0+8)*ldc + col0+1] = v3;
            if (F1){
                p0 += v0 + v1; p8 += v2 + v3;
                lmx = fmaxf(lmx, fmaxf(fmaxf(v0,v1), fmaxf(v2,v3)));
                lmn = fminf(lmn, fminf(fminf(v0,v1), fminf(v2,v3)));
            }
        }
        if (F1){
            p0 = qsum(p0); p8 = qsum(p8);
            if ((lane & 3) == 0){
                atomicAdd(&g_xqkvsum[row0],   p0);
                atomicAdd(&g_xqkvsum[row0+8], p8);
            }
        }
    }

    if (F1){
        __syncthreads();
        redx[tid] = lmx; redn[tid] = lmn; __syncthreads();
        for (int o = 128; o > 0; o >>= 1){
            if (tid < o){ redx[tid] = fmaxf(redx[tid], redx[tid+o]); redn[tid] = fminf(redn[tid], redn[tid+o]); }
            __syncthreads();
        }
        if (tid == 0){
            int region = blockIdx.x / 6;
            atomicMax(&g_stat[2*(2+region)],   fenc(redx[0]));
            atomicMin(&g_stat[2*(2+region)+1], fenc(redn[0]));
        }
    }
}

// ---------------- launcher ----------------
#define GEMM_SMEM (128*72*2*4 + 2048)

extern "C" void kernel_launch(void* const* d_in, const int* in_sizes, int n_in,
                              void* d_out, int out_size){
    const float *x = 0, *wqkv = 0, *wout = 0, *bout = 0;
    for (int i = 0; i < n_in; i++){
        if      (in_sizes[i] == MROWS*DMODEL)  x    = (const float*)d_in[i];
        else if (in_sizes[i] == J3*DMODEL)     wqkv = (const float*)d_in[i];
        else if (in_sizes[i] == DMODEL*DMODEL) wout = (const float*)d_in[i];
        else if (in_sizes[i] == DMODEL)        bout = (const float*)d_in[i];
    }
    float* out = (float*)d_out;

    bf16 *p_xq, *p_wq1, *p_wq2;
    float *p_xqkv, *p_outbuf;
    float *p_rowsum_x, *p_colsum_w1, *p_colsum_w2, *p_xqkvsum;
    cudaGetSymbolAddress((void**)&p_xq,        g_xq);
    cudaGetSymbolAddress((void**)&p_wq1,       g_wq1);
    cudaGetSymbolAddress((void**)&p_wq2,       g_wq2);
    cudaGetSymbolAddress((void**)&p_xqkv,      g_xqkv);
    cudaGetSymbolAddress((void**)&p_outbuf,    g_outbuf);
    cudaGetSymbolAddress((void**)&p_rowsum_x,  g_rowsum_x);
    cudaGetSymbolAddress((void**)&p_colsum_w1, g_colsum_w1);
    cudaGetSymbolAddress((void**)&p_colsum_w2, g_colsum_w2);
    cudaGetSymbolAddress((void**)&p_xqkvsum,   g_xqkvsum);

    static int smem_set = 0;
    if (!smem_set){
        cudaFuncSetAttribute(k_attn_stats, cudaFuncAttributeMaxDynamicSharedMemorySize, 18432*3 + 2048);
        cudaFuncSetAttribute(k_attn_av,    cudaFuncAttributeMaxDynamicSharedMemorySize, 18432*4 + 2048);
        cudaFuncSetAttribute(k_mma<1,0>,   cudaFuncAttributeMaxDynamicSharedMemorySize, GEMM_SMEM);
        cudaFuncSetAttribute(k_mma<0,1>,   cudaFuncAttributeMaxDynamicSharedMemorySize, GEMM_SMEM);
        smem_set = 1;
    }

    k_init<<<1, 256>>>();
    k_minmax3<<<dim3(768, 3), 256>>>(x, MROWS*DMODEL, 0,
                                     wqkv, J3*DMODEL, 1,
                                     wout, DMODEL*DMODEL, 7);
    k_quantrow3<<<(MROWS+J3+DMODEL)/8, 256>>>(x, wqkv, wout);
    k_mma<1,0><<<dim3(J3/128, MROWS/128), 256, GEMM_SMEM>>>(
        p_xq, (const float*)0, DMODEL, p_wq1, DMODEL, p_xqkv, J3, DMODEL,
        p_colsum_w1, p_rowsum_x, 0, 1, (float)DMODEL, (const float*)0);
    k_pack_qkv<<<dim3(SEQ/8, BHN), 256>>>();
    k_attn_stats<<<dim3(8, BHN, 2), 256, 18432*3 + 2048>>>();
    k_comb<<<BHN*SEQ/256, 256>>>();
    k_attn_av<<<dim3(8, BHN), 256, 18432*4 + 2048>>>();
    k_mma<0,1><<<dim3(DMODEL/128, MROWS/128), 256, GEMM_SMEM>>>(
        (const bf16*)0, p_outbuf, DMODEL, p_wq2, DMODEL, out, DMODEL, DMODEL,
        p_colsum_w2, p_xqkvsum, 6, 7, (float)J3, bout);
}